// round 2
// baseline (speedup 1.0000x reference)
#include <cuda_runtime.h>
#include <cuda_bf16.h>
#include <math.h>

#define BATCH 4
#define SEQ   2048
#define DM    1024
#define NH    16
#define DH    64
#define DFF   4096
#define BS    (BATCH*SEQ)        // 8192 rows
#define EPSLN 1e-5f

// ---------------- scratch (device globals; no allocs allowed) ----------------
__device__ float g_n[(size_t)BS*DM];        // ln1 out, reused for ln2 out
__device__ float g_q[(size_t)BS*DM];
__device__ float g_k[(size_t)BS*DM];
__device__ float g_v[(size_t)BS*DM];
__device__ float g_attn[(size_t)BS*DM];     // concat attention output
__device__ float g_resid[(size_t)BS*DM];    // x + attn_out
__device__ float g_hidden[(size_t)BS*DFF];  // gelu(fc1)

// ---------------- layernorm: one block per row ----------------
__global__ __launch_bounds__(256)
void layernorm_k(const float* __restrict__ x, const float* __restrict__ gamma,
                 const float* __restrict__ beta, float* __restrict__ out) {
    int row = blockIdx.x;
    const float* xr = x + (size_t)row * DM;
    float* orow = out + (size_t)row * DM;
    int t = threadIdx.x;                  // 256 threads, 4 floats each
    float4 v = *(const float4*)(xr + t * 4);
    float s  = v.x + v.y + v.z + v.w;
    float ss = v.x*v.x + v.y*v.y + v.z*v.z + v.w*v.w;
    // warp reduce
    #pragma unroll
    for (int o = 16; o > 0; o >>= 1) {
        s  += __shfl_xor_sync(0xffffffffu, s,  o);
        ss += __shfl_xor_sync(0xffffffffu, ss, o);
    }
    __shared__ float rs[8], rss[8];
    int w = t >> 5, l = t & 31;
    if (l == 0) { rs[w] = s; rss[w] = ss; }
    __syncthreads();
    if (w == 0) {
        float a = (l < 8) ? rs[l]  : 0.f;
        float b = (l < 8) ? rss[l] : 0.f;
        #pragma unroll
        for (int o = 4; o > 0; o >>= 1) {
            a += __shfl_xor_sync(0xffffffffu, a, o);
            b += __shfl_xor_sync(0xffffffffu, b, o);
        }
        if (l == 0) { rs[0] = a; rss[0] = b; }
    }
    __syncthreads();
    float mean = rs[0] * (1.0f / DM);
    float var  = rss[0] * (1.0f / DM) - mean * mean;
    float rstd = rsqrtf(var + EPSLN);
    float4 gv = *(const float4*)(gamma + t * 4);
    float4 bv = *(const float4*)(beta  + t * 4);
    float4 o4;
    o4.x = gv.x * ((v.x - mean) * rstd) + bv.x;
    o4.y = gv.y * ((v.y - mean) * rstd) + bv.y;
    o4.z = gv.z * ((v.z - mean) * rstd) + bv.z;
    o4.w = gv.w * ((v.w - mean) * rstd) + bv.w;
    *(float4*)(orow + t * 4) = o4;
}

// ---------------- GEMM NT: C[M,N] = A[M,K] * W[N,K]^T (+epilogue) ----------------
// EPI: 0 = none, 1 = add residual R, 2 = gelu
#define BM 128
#define BN 128
#define BKT 16

__device__ __forceinline__ float gelu_f(float x) {
    float c = x * x * x;
    float t = tanhf(0.7978845608f * (x + 0.044715f * c));
    return 0.5f * x * (1.0f + t);
}

template<int EPI>
__global__ __launch_bounds__(256)
void gemm_nt(const float* __restrict__ A, const float* __restrict__ W,
             const float* __restrict__ R, float* __restrict__ C,
             int M, int N, int K) {
    __shared__ float As[BKT][BM];
    __shared__ float Bs[BKT][BN];
    int tid = threadIdx.x;
    int tx = tid & 15, ty = tid >> 4;
    const float* Ab = A + (size_t)blockIdx.y * BM * K;
    const float* Wb = W + (size_t)blockIdx.x * BN * K;
    float acc[8][8];
    #pragma unroll
    for (int i = 0; i < 8; i++)
        #pragma unroll
        for (int j = 0; j < 8; j++) acc[i][j] = 0.f;

    for (int k0 = 0; k0 < K; k0 += BKT) {
        #pragma unroll
        for (int i = 0; i < 2; i++) {
            int idx = tid + i * 256;          // 0..511 float4 slots
            int row = idx >> 2;
            int c   = (idx & 3) * 4;
            float4 va = *(const float4*)(Ab + (size_t)row * K + k0 + c);
            As[c + 0][row] = va.x; As[c + 1][row] = va.y;
            As[c + 2][row] = va.z; As[c + 3][row] = va.w;
            float4 vb = *(const float4*)(Wb + (size_t)row * K + k0 + c);
            Bs[c + 0][row] = vb.x; Bs[c + 1][row] = vb.y;
            Bs[c + 2][row] = vb.z; Bs[c + 3][row] = vb.w;
        }
        __syncthreads();
        #pragma unroll
        for (int k = 0; k < BKT; k++) {
            float4 a0 = *(const float4*)&As[k][ty * 8];
            float4 a1 = *(const float4*)&As[k][ty * 8 + 4];
            float4 b0 = *(const float4*)&Bs[k][tx * 8];
            float4 b1 = *(const float4*)&Bs[k][tx * 8 + 4];
            float a[8] = {a0.x,a0.y,a0.z,a0.w,a1.x,a1.y,a1.z,a1.w};
            float b[8] = {b0.x,b0.y,b0.z,b0.w,b1.x,b1.y,b1.z,b1.w};
            #pragma unroll
            for (int i = 0; i < 8; i++)
                #pragma unroll
                for (int j = 0; j < 8; j++)
                    acc[i][j] += a[i] * b[j];
        }
        __syncthreads();
    }
    // epilogue: two float4 stores per row
    #pragma unroll
    for (int i = 0; i < 8; i++) {
        size_t row = (size_t)blockIdx.y * BM + ty * 8 + i;
        size_t cbase = (size_t)blockIdx.x * BN + tx * 8;
        float out[8];
        #pragma unroll
        for (int j = 0; j < 8; j++) out[j] = acc[i][j];
        if (EPI == 1) {
            float4 r0 = *(const float4*)(R + row * N + cbase);
            float4 r1 = *(const float4*)(R + row * N + cbase + 4);
            out[0]+=r0.x; out[1]+=r0.y; out[2]+=r0.z; out[3]+=r0.w;
            out[4]+=r1.x; out[5]+=r1.y; out[6]+=r1.z; out[7]+=r1.w;
        }
        if (EPI == 2) {
            #pragma unroll
            for (int j = 0; j < 8; j++) out[j] = gelu_f(out[j]);
        }
        float4 o0 = make_float4(out[0], out[1], out[2], out[3]);
        float4 o1 = make_float4(out[4], out[5], out[6], out[7]);
        *(float4*)(C + row * N + cbase)     = o0;
        *(float4*)(C + row * N + cbase + 4) = o1;
    }
}

// ---------------- flash attention (fp32, causal) ----------------
// grid: (SEQ/128, BATCH*NH). 128 threads; thread t owns query row qt*128+t.
__global__ __launch_bounds__(128)
void flash_attn_k(const float* __restrict__ Q, const float* __restrict__ K,
                  const float* __restrict__ V, float* __restrict__ O) {
    int qt = blockIdx.x;
    int bh = blockIdx.y;
    int b = bh >> 4, h = bh & 15;
    int t = threadIdx.x;
    int srow = qt * 128 + t;
    __shared__ float ks[64][DH];
    __shared__ float vs[64][DH];

    float q[DH];
    const size_t qoff = ((size_t)(b * SEQ + srow) * NH + h) * DH;
    #pragma unroll
    for (int e4 = 0; e4 < DH / 4; e4++) {
        float4 v = *(const float4*)(Q + qoff + e4 * 4);
        q[e4*4+0] = v.x * 0.125f; q[e4*4+1] = v.y * 0.125f;
        q[e4*4+2] = v.z * 0.125f; q[e4*4+3] = v.w * 0.125f;
    }
    float acc[DH];
    #pragma unroll
    for (int e = 0; e < DH; e++) acc[e] = 0.f;
    float m = -1e30f, lsum = 0.f;

    int nkb = 2 * qt + 2;   // key blocks of 64 covering causal range
    for (int kb = 0; kb < nkb; kb++) {
        int base = kb * 64;
        #pragma unroll
        for (int i = 0; i < 8; i++) {
            int idx = t + i * 128;           // 1024 float4 slots per tile
            int row = idx >> 4;
            int c4  = (idx & 15) * 4;
            size_t goff = ((size_t)(b * SEQ + base + row) * NH + h) * DH + c4;
            *(float4*)&ks[row][c4] = *(const float4*)(K + goff);
            *(float4*)&vs[row][c4] = *(const float4*)(V + goff);
        }
        __syncthreads();
        #pragma unroll
        for (int c = 0; c < 64; c += 16) {
            float s[16];
            #pragma unroll
            for (int j = 0; j < 16; j++) {
                float d = 0.f;
                #pragma unroll
                for (int e4 = 0; e4 < DH / 4; e4++) {
                    float4 kv = *(const float4*)&ks[c + j][e4 * 4];
                    d += q[e4*4+0]*kv.x + q[e4*4+1]*kv.y
                       + q[e4*4+2]*kv.z + q[e4*4+3]*kv.w;
                }
                int jg = base + c + j;
                s[j] = (jg <= srow) ? d : -1e30f;
            }
            float cm = s[0];
            #pragma unroll
            for (int j = 1; j < 16; j++) cm = fmaxf(cm, s[j]);
            float mn  = fmaxf(m, cm);
            float fac = __expf(m - mn);
            lsum *= fac;
            #pragma unroll
            for (int e = 0; e < DH; e++) acc[e] *= fac;
            #pragma unroll
            for (int j = 0; j < 16; j++) {
                float p = __expf(s[j] - mn);
                lsum += p;
                #pragma unroll
                for (int e4 = 0; e4 < DH / 4; e4++) {
                    float4 vv = *(const float4*)&vs[c + j][e4 * 4];
                    acc[e4*4+0] += p * vv.x; acc[e4*4+1] += p * vv.y;
                    acc[e4*4+2] += p * vv.z; acc[e4*4+3] += p * vv.w;
                }
            }
            m = mn;
        }
        __syncthreads();
    }
    float rl = 1.0f / lsum;
    #pragma unroll
    for (int e4 = 0; e4 < DH / 4; e4++) {
        float4 o;
        o.x = acc[e4*4+0]*rl; o.y = acc[e4*4+1]*rl;
        o.z = acc[e4*4+2]*rl; o.w = acc[e4*4+3]*rl;
        *(float4*)(O + qoff + e4 * 4) = o;
    }
}

// ---------------- launch ----------------
extern "C" void kernel_launch(void* const* d_in, const int* in_sizes, int n_in,
                              void* d_out, int out_size) {
    const float* x      = (const float*)d_in[0];
    const float* gamma1 = (const float*)d_in[1];
    const float* beta1  = (const float*)d_in[2];
    const float* wq     = (const float*)d_in[3];
    const float* wk     = (const float*)d_in[4];
    const float* wv     = (const float*)d_in[5];
    const float* wo     = (const float*)d_in[6];
    const float* gamma2 = (const float*)d_in[7];
    const float* beta2  = (const float*)d_in[8];
    const float* fc1    = (const float*)d_in[9];
    const float* fc2    = (const float*)d_in[10];
    float* out = (float*)d_out;

    float *n_, *q_, *k_, *v_, *attn_, *resid_, *hid_;
    cudaGetSymbolAddress((void**)&n_,     g_n);
    cudaGetSymbolAddress((void**)&q_,     g_q);
    cudaGetSymbolAddress((void**)&k_,     g_k);
    cudaGetSymbolAddress((void**)&v_,     g_v);
    cudaGetSymbolAddress((void**)&attn_,  g_attn);
    cudaGetSymbolAddress((void**)&resid_, g_resid);
    cudaGetSymbolAddress((void**)&hid_,   g_hidden);

    dim3 gProj(DM / BN, BS / BM);      // (8, 64)
    dim3 gFF1(DFF / BN, BS / BM);      // (32, 64)
    dim3 gFF2(DM / BN, BS / BM);       // (8, 64)
    dim3 gAttn(SEQ / 128, BATCH * NH); // (16, 64)

    // 1. LN1
    layernorm_k<<<BS, 256>>>(x, gamma1, beta1, n_);
    // 2-4. QKV projections
    gemm_nt<0><<<gProj, 256>>>(n_, wq, nullptr, q_, BS, DM, DM);
    gemm_nt<0><<<gProj, 256>>>(n_, wk, nullptr, k_, BS, DM, DM);
    gemm_nt<0><<<gProj, 256>>>(n_, wv, nullptr, v_, BS, DM, DM);
    // 5. attention
    flash_attn_k<<<gAttn, 128>>>(q_, k_, v_, attn_);
    // 6. output projection + residual (x)
    gemm_nt<1><<<gProj, 256>>>(attn_, wo, x, resid_, BS, DM, DM);
    // 7. LN2 (reuse n_)
    layernorm_k<<<BS, 256>>>(resid_, gamma2, beta2, n_);
    // 8. FC1 + GELU
    gemm_nt<2><<<gFF1, 256>>>(n_, fc1, nullptr, hid_, BS, DFF, DM);
    // 9. FC2 + residual -> d_out
    gemm_nt<1><<<gFF2, 256>>>(hid_, fc2, resid_, out, BS, DM, DFF);
}

// round 4
// speedup vs baseline: 1.4178x; 1.4178x over previous
#include <cuda_runtime.h>
#include <cuda_bf16.h>
#include <math.h>
#include <stdint.h>

#define BATCH 4
#define SEQ   2048
#define DM    1024
#define NH    16
#define DH    64
#define DFF   4096
#define BS    (BATCH*SEQ)
#define EPSLN 1e-5f

// ---------------- scratch ----------------
__device__ float g_n[(size_t)BS*DM];
__device__ float g_q[(size_t)BS*DM];
__device__ float g_k[(size_t)BS*DM];
__device__ float g_v[(size_t)BS*DM];
__device__ float g_attn[(size_t)BS*DM];
__device__ float g_resid[(size_t)BS*DM];
__device__ float g_hidden[(size_t)BS*DFF];

// ---------------- helpers ----------------
__device__ __forceinline__ uint32_t smem_u32(const void* p) {
    uint32_t a;
    asm("{ .reg .u64 t; cvta.to.shared.u64 t, %1; cvt.u32.u64 %0, t; }" : "=r"(a) : "l"(p));
    return a;
}

// swizzle for 64-byte rows (32 bf16/row): XOR bits[4:5] with bits[7:8]
__device__ __forceinline__ uint32_t swz(uint32_t off) {
    return off ^ ((off >> 3) & 0x30);
}

__device__ __forceinline__ void ldsm_x4(uint32_t addr, uint32_t& r0, uint32_t& r1,
                                        uint32_t& r2, uint32_t& r3) {
    asm volatile("ldmatrix.sync.aligned.m8n8.x4.shared.b16 {%0,%1,%2,%3}, [%4];"
                 : "=r"(r0), "=r"(r1), "=r"(r2), "=r"(r3) : "r"(addr));
}

__device__ __forceinline__ void mma_bf16(float* d, uint32_t a0, uint32_t a1,
                                         uint32_t a2, uint32_t a3,
                                         uint32_t b0, uint32_t b1) {
    asm volatile("mma.sync.aligned.m16n8k16.row.col.f32.bf16.bf16.f32 "
                 "{%0,%1,%2,%3}, {%4,%5,%6,%7}, {%8,%9}, {%0,%1,%2,%3};"
                 : "+f"(d[0]), "+f"(d[1]), "+f"(d[2]), "+f"(d[3])
                 : "r"(a0), "r"(a1), "r"(a2), "r"(a3), "r"(b0), "r"(b1));
}

__device__ __forceinline__ float gelu_f(float x) {
    float c = x * x * x;
    float t = tanhf(0.7978845608f * (x + 0.044715f * c));
    return 0.5f * x * (1.0f + t);
}

// pack 4 floats -> hi bf16x2 pair + lo bf16x2 pair
__device__ __forceinline__ void split4(float4 v, uint32_t& h01, uint32_t& h23,
                                       uint32_t& l01, uint32_t& l23) {
    __nv_bfloat16 h0 = __float2bfloat16(v.x), h1 = __float2bfloat16(v.y);
    __nv_bfloat16 h2 = __float2bfloat16(v.z), h3 = __float2bfloat16(v.w);
    __nv_bfloat16 l0 = __float2bfloat16(v.x - __bfloat162float(h0));
    __nv_bfloat16 l1 = __float2bfloat16(v.y - __bfloat162float(h1));
    __nv_bfloat16 l2 = __float2bfloat16(v.z - __bfloat162float(h2));
    __nv_bfloat16 l3 = __float2bfloat16(v.w - __bfloat162float(h3));
    h01 = ((uint32_t)__bfloat16_as_ushort(h1) << 16) | __bfloat16_as_ushort(h0);
    h23 = ((uint32_t)__bfloat16_as_ushort(h3) << 16) | __bfloat16_as_ushort(h2);
    l01 = ((uint32_t)__bfloat16_as_ushort(l1) << 16) | __bfloat16_as_ushort(l0);
    l23 = ((uint32_t)__bfloat16_as_ushort(l3) << 16) | __bfloat16_as_ushort(l2);
}

// ---------------- layernorm ----------------
__global__ __launch_bounds__(256)
void layernorm_k(const float* __restrict__ x, const float* __restrict__ gamma,
                 const float* __restrict__ beta, float* __restrict__ out) {
    int row = blockIdx.x;
    const float* xr = x + (size_t)row * DM;
    float* orow = out + (size_t)row * DM;
    int t = threadIdx.x;
    float4 v = *(const float4*)(xr + t * 4);
    float s  = v.x + v.y + v.z + v.w;
    float ss = v.x*v.x + v.y*v.y + v.z*v.z + v.w*v.w;
    #pragma unroll
    for (int o = 16; o > 0; o >>= 1) {
        s  += __shfl_xor_sync(0xffffffffu, s,  o);
        ss += __shfl_xor_sync(0xffffffffu, ss, o);
    }
    __shared__ float rs[8], rss[8];
    int w = t >> 5, l = t & 31;
    if (l == 0) { rs[w] = s; rss[w] = ss; }
    __syncthreads();
    if (w == 0) {
        float a = (l < 8) ? rs[l]  : 0.f;
        float b = (l < 8) ? rss[l] : 0.f;
        #pragma unroll
        for (int o = 4; o > 0; o >>= 1) {
            a += __shfl_xor_sync(0xffffffffu, a, o);
            b += __shfl_xor_sync(0xffffffffu, b, o);
        }
        if (l == 0) { rs[0] = a; rss[0] = b; }
    }
    __syncthreads();
    float mean = rs[0] * (1.0f / DM);
    float var  = rss[0] * (1.0f / DM) - mean * mean;
    float rstd = rsqrtf(var + EPSLN);
    float4 gv = *(const float4*)(gamma + t * 4);
    float4 bv = *(const float4*)(beta  + t * 4);
    float4 o4;
    o4.x = gv.x * ((v.x - mean) * rstd) + bv.x;
    o4.y = gv.y * ((v.y - mean) * rstd) + bv.y;
    o4.z = gv.z * ((v.z - mean) * rstd) + bv.z;
    o4.w = gv.w * ((v.w - mean) * rstd) + bv.w;
    *(float4*)(orow + t * 4) = o4;
}

// ---------------- mma.sync bf16-split GEMM NT ----------------
// C[M,N] = A[M,K] @ W[N,K]^T, fp32 in/out. 128x128x32 CTA tile, 8 warps,
// 64x32 warp tile. 3 passes: AhBh + AhBl + AlBh. EPI: 0 none, 1 +R, 2 gelu.
template<int EPI>
__global__ __launch_bounds__(256)
void gemm_tc(const float* __restrict__ A, const float* __restrict__ W,
             const float* __restrict__ R, float* __restrict__ C,
             int M, int N, int K) {
    __shared__ __align__(1024) __nv_bfloat16 AHs[128*32];
    __shared__ __align__(1024) __nv_bfloat16 ALs[128*32];
    __shared__ __align__(1024) __nv_bfloat16 BHs[128*32];
    __shared__ __align__(1024) __nv_bfloat16 BLs[128*32];
    uint32_t ah = smem_u32(AHs), al = smem_u32(ALs);
    uint32_t bh = smem_u32(BHs), bl = smem_u32(BLs);

    int tid = threadIdx.x, wid = tid >> 5, lane = tid & 31;
    int wm = wid >> 2, wn = wid & 3;           // warp tile: rows wm*64, cols wn*32

    const float* Ab = A + (size_t)blockIdx.y * 128 * K;
    const float* Wb = W + (size_t)blockIdx.x * 128 * K;

    // thread's two 16B segments per matrix: seg s -> row s>>2, kseg s&3
    int s0 = tid, s1 = tid + 256;
    int r0s = s0 >> 2, k0s = s0 & 3;
    int r1s = s1 >> 2, k1s = s1 & 3;
    uint32_t sw0 = swz(r0s * 64 + k0s * 16);
    uint32_t sw1 = swz(r1s * 64 + k1s * 16);

    float4 pa[4], pb[4];
    #define LOAD_CHUNK(kb) do { \
        pa[0] = *(const float4*)(Ab + (size_t)r0s * K + (kb) + k0s * 8); \
        pa[1] = *(const float4*)(Ab + (size_t)r0s * K + (kb) + k0s * 8 + 4); \
        pa[2] = *(const float4*)(Ab + (size_t)r1s * K + (kb) + k1s * 8); \
        pa[3] = *(const float4*)(Ab + (size_t)r1s * K + (kb) + k1s * 8 + 4); \
        pb[0] = *(const float4*)(Wb + (size_t)r0s * K + (kb) + k0s * 8); \
        pb[1] = *(const float4*)(Wb + (size_t)r0s * K + (kb) + k0s * 8 + 4); \
        pb[2] = *(const float4*)(Wb + (size_t)r1s * K + (kb) + k1s * 8); \
        pb[3] = *(const float4*)(Wb + (size_t)r1s * K + (kb) + k1s * 8 + 4); \
    } while (0)

    #define STORE_CHUNK() do { \
        uint32_t h0,h1,l0,l1,h2,h3,l2,l3; \
        split4(pa[0], h0, h1, l0, l1); split4(pa[1], h2, h3, l2, l3); \
        asm volatile("st.shared.v4.b32 [%0], {%1,%2,%3,%4};" :: "r"(ah+sw0), "r"(h0),"r"(h1),"r"(h2),"r"(h3)); \
        asm volatile("st.shared.v4.b32 [%0], {%1,%2,%3,%4};" :: "r"(al+sw0), "r"(l0),"r"(l1),"r"(l2),"r"(l3)); \
        split4(pa[2], h0, h1, l0, l1); split4(pa[3], h2, h3, l2, l3); \
        asm volatile("st.shared.v4.b32 [%0], {%1,%2,%3,%4};" :: "r"(ah+sw1), "r"(h0),"r"(h1),"r"(h2),"r"(h3)); \
        asm volatile("st.shared.v4.b32 [%0], {%1,%2,%3,%4};" :: "r"(al+sw1), "r"(l0),"r"(l1),"r"(l2),"r"(l3)); \
        split4(pb[0], h0, h1, l0, l1); split4(pb[1], h2, h3, l2, l3); \
        asm volatile("st.shared.v4.b32 [%0], {%1,%2,%3,%4};" :: "r"(bh+sw0), "r"(h0),"r"(h1),"r"(h2),"r"(h3)); \
        asm volatile("st.shared.v4.b32 [%0], {%1,%2,%3,%4};" :: "r"(bl+sw0), "r"(l0),"r"(l1),"r"(l2),"r"(l3)); \
        split4(pb[2], h0, h1, l0, l1); split4(pb[3], h2, h3, l2, l3); \
        asm volatile("st.shared.v4.b32 [%0], {%1,%2,%3,%4};" :: "r"(bh+sw1), "r"(h0),"r"(h1),"r"(h2),"r"(h3)); \
        asm volatile("st.shared.v4.b32 [%0], {%1,%2,%3,%4};" :: "r"(bl+sw1), "r"(l0),"r"(l1),"r"(l2),"r"(l3)); \
    } while (0)

    float acc[4][4][4];
    #pragma unroll
    for (int i = 0; i < 4; i++)
        #pragma unroll
        for (int j = 0; j < 4; j++)
            #pragma unroll
            for (int e = 0; e < 4; e++) acc[i][j][e] = 0.f;

    int g = lane >> 3, rg = lane & 7;          // ldmatrix group / row-in-group
    int nch = K >> 5;

    LOAD_CHUNK(0);
    for (int ch = 0; ch < nch; ch++) {
        __syncthreads();
        STORE_CHUNK();
        __syncthreads();
        if (ch + 1 < nch) LOAD_CHUNK((ch + 1) << 5);

        #pragma unroll
        for (int ks = 0; ks < 2; ks++) {
            // B frags: pairs of n-frags via x4, hi and lo
            uint32_t bhr[2][4], blr[2][4];
            #pragma unroll
            for (int p = 0; p < 2; p++) {
                int nrow = wn * 32 + p * 16 + (g & 1) * 8 + rg;
                int kseg = ks * 2 + (g >> 1);
                uint32_t off = swz(nrow * 64 + kseg * 16);
                ldsm_x4(bh + off, bhr[p][0], bhr[p][1], bhr[p][2], bhr[p][3]);
                ldsm_x4(bl + off, blr[p][0], blr[p][1], blr[p][2], blr[p][3]);
            }
            #pragma unroll
            for (int mf = 0; mf < 4; mf++) {
                int arow = wm * 64 + mf * 16 + (g & 1) * 8 + rg;
                int kseg = ks * 2 + (g >> 1);
                uint32_t off = swz(arow * 64 + kseg * 16);
                uint32_t a0,a1,a2,a3, x0,x1,x2,x3;
                ldsm_x4(ah + off, a0, a1, a2, a3);
                ldsm_x4(al + off, x0, x1, x2, x3);
                #pragma unroll
                for (int nf = 0; nf < 4; nf++) {
                    int p = nf >> 1, q = nf & 1;   // q: which n-frag in the pair
                    uint32_t bb0 = bhr[p][q], bb1 = bhr[p][q + 2];
                    uint32_t cb0 = blr[p][q], cb1 = blr[p][q + 2];
                    mma_bf16(acc[mf][nf], a0, a1, a2, a3, bb0, bb1);
                    mma_bf16(acc[mf][nf], a0, a1, a2, a3, cb0, cb1);
                    mma_bf16(acc[mf][nf], x0, x1, x2, x3, bb0, bb1);
                }
            }
        }
    }

    // epilogue: frag (mf,nf): rows wm*64+mf*16+lane/4 (+8), cols wn*32+nf*8+2*(lane%4)
    #pragma unroll
    for (int mf = 0; mf < 4; mf++) {
        #pragma unroll
        for (int h = 0; h < 2; h++) {
            size_t row = (size_t)blockIdx.y * 128 + wm * 64 + mf * 16 + (lane >> 2) + h * 8;
            #pragma unroll
            for (int nf = 0; nf < 4; nf++) {
                size_t col = (size_t)blockIdx.x * 128 + wn * 32 + nf * 8 + (lane & 3) * 2;
                float o0 = acc[mf][nf][h * 2 + 0];
                float o1 = acc[mf][nf][h * 2 + 1];
                if (EPI == 1) {
                    float2 r2 = *(const float2*)(R + row * N + col);
                    o0 += r2.x; o1 += r2.y;
                }
                if (EPI == 2) { o0 = gelu_f(o0); o1 = gelu_f(o1); }
                *(float2*)(C + row * N + col) = make_float2(o0, o1);
            }
        }
    }
}

// ---------------- flash attention (fp32, causal) ----------------
__global__ __launch_bounds__(128)
void flash_attn_k(const float* __restrict__ Q, const float* __restrict__ K,
                  const float* __restrict__ V, float* __restrict__ O) {
    int qt = blockIdx.x;
    int bh = blockIdx.y;
    int b = bh >> 4, h = bh & 15;
    int t = threadIdx.x;
    int srow = qt * 128 + t;
    __shared__ float ks[64][DH];
    __shared__ float vs[64][DH];

    float q[DH];
    const size_t qoff = ((size_t)(b * SEQ + srow) * NH + h) * DH;
    #pragma unroll
    for (int e4 = 0; e4 < DH / 4; e4++) {
        float4 v = *(const float4*)(Q + qoff + e4 * 4);
        q[e4*4+0] = v.x * 0.125f; q[e4*4+1] = v.y * 0.125f;
        q[e4*4+2] = v.z * 0.125f; q[e4*4+3] = v.w * 0.125f;
    }
    float acc[DH];
    #pragma unroll
    for (int e = 0; e < DH; e++) acc[e] = 0.f;
    float m = -1e30f, lsum = 0.f;

    int nkb = 2 * qt + 2;
    for (int kb = 0; kb < nkb; kb++) {
        int base = kb * 64;
        #pragma unroll
        for (int i = 0; i < 8; i++) {
            int idx = t + i * 128;
            int row = idx >> 4;
            int c4  = (idx & 15) * 4;
            size_t goff = ((size_t)(b * SEQ + base + row) * NH + h) * DH + c4;
            *(float4*)&ks[row][c4] = *(const float4*)(K + goff);
            *(float4*)&vs[row][c4] = *(const float4*)(V + goff);
        }
        __syncthreads();
        #pragma unroll
        for (int c = 0; c < 64; c += 16) {
            float s[16];
            #pragma unroll
            for (int j = 0; j < 16; j++) {
                float d = 0.f;
                #pragma unroll
                for (int e4 = 0; e4 < DH / 4; e4++) {
                    float4 kv = *(const float4*)&ks[c + j][e4 * 4];
                    d += q[e4*4+0]*kv.x + q[e4*4+1]*kv.y
                       + q[e4*4+2]*kv.z + q[e4*4+3]*kv.w;
                }
                int jg = base + c + j;
                s[j] = (jg <= srow) ? d : -1e30f;
            }
            float cm = s[0];
            #pragma unroll
            for (int j = 1; j < 16; j++) cm = fmaxf(cm, s[j]);
            float mn  = fmaxf(m, cm);
            float fac = __expf(m - mn);
            lsum *= fac;
            #pragma unroll
            for (int e = 0; e < DH; e++) acc[e] *= fac;
            #pragma unroll
            for (int j = 0; j < 16; j++) {
                float p = __expf(s[j] - mn);
                lsum += p;
                #pragma unroll
                for (int e4 = 0; e4 < DH / 4; e4++) {
                    float4 vv = *(const float4*)&vs[c + j][e4 * 4];
                    acc[e4*4+0] += p * vv.x; acc[e4*4+1] += p * vv.y;
                    acc[e4*4+2] += p * vv.z; acc[e4*4+3] += p * vv.w;
                }
            }
            m = mn;
        }
        __syncthreads();
    }
    float rl = 1.0f / lsum;
    #pragma unroll
    for (int e4 = 0; e4 < DH / 4; e4++) {
        float4 o;
        o.x = acc[e4*4+0]*rl; o.y = acc[e4*4+1]*rl;
        o.z = acc[e4*4+2]*rl; o.w = acc[e4*4+3]*rl;
        *(float4*)(O + qoff + e4 * 4) = o;
    }
}

// ---------------- launch ----------------
extern "C" void kernel_launch(void* const* d_in, const int* in_sizes, int n_in,
                              void* d_out, int out_size) {
    const float* x      = (const float*)d_in[0];
    const float* gamma1 = (const float*)d_in[1];
    const float* beta1  = (const float*)d_in[2];
    const float* wq     = (const float*)d_in[3];
    const float* wk     = (const float*)d_in[4];
    const float* wv     = (const float*)d_in[5];
    const float* wo     = (const float*)d_in[6];
    const float* gamma2 = (const float*)d_in[7];
    const float* beta2  = (const float*)d_in[8];
    const float* fc1    = (const float*)d_in[9];
    const float* fc2    = (const float*)d_in[10];
    float* out = (float*)d_out;

    float *n_, *q_, *k_, *v_, *attn_, *resid_, *hid_;
    cudaGetSymbolAddress((void**)&n_,     g_n);
    cudaGetSymbolAddress((void**)&q_,     g_q);
    cudaGetSymbolAddress((void**)&k_,     g_k);
    cudaGetSymbolAddress((void**)&v_,     g_v);
    cudaGetSymbolAddress((void**)&attn_,  g_attn);
    cudaGetSymbolAddress((void**)&resid_, g_resid);
    cudaGetSymbolAddress((void**)&hid_,   g_hidden);

    dim3 gProj(DM / 128, BS / 128);      // (8, 64)
    dim3 gFF1(DFF / 128, BS / 128);      // (32, 64)
    dim3 gFF2(DM / 128, BS / 128);       // (8, 64)
    dim3 gAttn(SEQ / 128, BATCH * NH);   // (16, 64)

    layernorm_k<<<BS, 256>>>(x, gamma1, beta1, n_);
    gemm_tc<0><<<gProj, 256>>>(n_, wq, nullptr, q_, BS, DM, DM);
    gemm_tc<0><<<gProj, 256>>>(n_, wk, nullptr, k_, BS, DM, DM);
    gemm_tc<0><<<gProj, 256>>>(n_, wv, nullptr, v_, BS, DM, DM);
    flash_attn_k<<<gAttn, 128>>>(q_, k_, v_, attn_);
    gemm_tc<1><<<gProj, 256>>>(attn_, wo, x, resid_, BS, DM, DM);
    layernorm_k<<<BS, 256>>>(resid_, gamma2, beta2, n_);
    gemm_tc<2><<<gFF1, 256>>>(n_, fc1, nullptr, hid_, BS, DFF, DM);
    gemm_tc<1><<<gFF2, 256>>>(hid_, fc2, resid_, out, BS, DM, DFF);
}

// round 5
// speedup vs baseline: 2.4356x; 1.7178x over previous
#include <cuda_runtime.h>
#include <cuda_bf16.h>
#include <math.h>
#include <stdint.h>

#define BATCH 4
#define SEQ   2048
#define DM    1024
#define NH    16
#define DH    64
#define DFF   4096
#define BS    (BATCH*SEQ)
#define EPSLN 1e-5f

typedef unsigned long long u64t;

// ---------------- scratch ----------------
__device__ float g_q[(size_t)BS*DM];
__device__ float g_k[(size_t)BS*DM];
__device__ float g_v[(size_t)BS*DM];
__device__ float g_resid[(size_t)BS*DM];
__device__ __nv_bfloat16 g_nh[(size_t)BS*DM],  g_nl[(size_t)BS*DM];
__device__ __nv_bfloat16 g_ah[(size_t)BS*DM],  g_al[(size_t)BS*DM];
__device__ __nv_bfloat16 g_hh[(size_t)BS*DFF], g_hl[(size_t)BS*DFF];
// weights hi/lo: wq@0, wk@1M, wv@2M, wo@3M, fc1@4M, fc2@8M  (1M = DM*DM)
#define WOFF_Q  ((size_t)0)
#define WOFF_K  ((size_t)DM*DM)
#define WOFF_V  ((size_t)2*DM*DM)
#define WOFF_O  ((size_t)3*DM*DM)
#define WOFF_F1 ((size_t)4*DM*DM)
#define WOFF_F2 ((size_t)(4*DM*DM) + (size_t)DFF*DM)
__device__ __nv_bfloat16 g_wh[(size_t)4*DM*DM + 2*(size_t)DFF*DM];
__device__ __nv_bfloat16 g_wl[(size_t)4*DM*DM + 2*(size_t)DFF*DM];

// ---------------- helpers ----------------
__device__ __forceinline__ uint32_t smem_u32(const void* p) {
    uint32_t a;
    asm("{ .reg .u64 t; cvta.to.shared.u64 t, %1; cvt.u32.u64 %0, t; }" : "=r"(a) : "l"(p));
    return a;
}
__device__ __forceinline__ uint32_t swz(uint32_t off) {   // 64B rows
    return off ^ ((off >> 3) & 0x30);
}
__device__ __forceinline__ void ldsm_x4(uint32_t addr, uint32_t& r0, uint32_t& r1,
                                        uint32_t& r2, uint32_t& r3) {
    asm volatile("ldmatrix.sync.aligned.m8n8.x4.shared.b16 {%0,%1,%2,%3}, [%4];"
                 : "=r"(r0), "=r"(r1), "=r"(r2), "=r"(r3) : "r"(addr));
}
__device__ __forceinline__ void mma_bf16(float* d, uint32_t a0, uint32_t a1,
                                         uint32_t a2, uint32_t a3,
                                         uint32_t b0, uint32_t b1) {
    asm volatile("mma.sync.aligned.m16n8k16.row.col.f32.bf16.bf16.f32 "
                 "{%0,%1,%2,%3}, {%4,%5,%6,%7}, {%8,%9}, {%0,%1,%2,%3};"
                 : "+f"(d[0]), "+f"(d[1]), "+f"(d[2]), "+f"(d[3])
                 : "r"(a0), "r"(a1), "r"(a2), "r"(a3), "r"(b0), "r"(b1));
}
#define CPA(dst, src) asm volatile("cp.async.cg.shared.global [%0], [%1], 16;" :: "r"(dst), "l"(src))

__device__ __forceinline__ float gelu_f(float x) {
    float c = x * x * x;
    float t = tanhf(0.7978845608f * (x + 0.044715f * c));
    return 0.5f * x * (1.0f + t);
}
__device__ __forceinline__ void split4(float4 v, uint32_t& h01, uint32_t& h23,
                                       uint32_t& l01, uint32_t& l23) {
    __nv_bfloat16 h0 = __float2bfloat16(v.x), h1 = __float2bfloat16(v.y);
    __nv_bfloat16 h2 = __float2bfloat16(v.z), h3 = __float2bfloat16(v.w);
    __nv_bfloat16 l0 = __float2bfloat16(v.x - __bfloat162float(h0));
    __nv_bfloat16 l1 = __float2bfloat16(v.y - __bfloat162float(h1));
    __nv_bfloat16 l2 = __float2bfloat16(v.z - __bfloat162float(h2));
    __nv_bfloat16 l3 = __float2bfloat16(v.w - __bfloat162float(h3));
    h01 = ((uint32_t)__bfloat16_as_ushort(h1) << 16) | __bfloat16_as_ushort(h0);
    h23 = ((uint32_t)__bfloat16_as_ushort(h3) << 16) | __bfloat16_as_ushort(h2);
    l01 = ((uint32_t)__bfloat16_as_ushort(l1) << 16) | __bfloat16_as_ushort(l0);
    l23 = ((uint32_t)__bfloat16_as_ushort(l3) << 16) | __bfloat16_as_ushort(l2);
}
__device__ __forceinline__ void split2(float x, float y, uint32_t& h, uint32_t& l) {
    __nv_bfloat16 h0 = __float2bfloat16(x), h1 = __float2bfloat16(y);
    __nv_bfloat16 l0 = __float2bfloat16(x - __bfloat162float(h0));
    __nv_bfloat16 l1 = __float2bfloat16(y - __bfloat162float(h1));
    h = ((uint32_t)__bfloat16_as_ushort(h1) << 16) | __bfloat16_as_ushort(h0);
    l = ((uint32_t)__bfloat16_as_ushort(l1) << 16) | __bfloat16_as_ushort(l0);
}

// f32x2 packed math
__device__ __forceinline__ u64t pack2(float lo, float hi) {
    u64t r; asm("mov.b64 %0, {%1,%2};" : "=l"(r) : "f"(lo), "f"(hi)); return r;
}
__device__ __forceinline__ void unpack2(u64t v, float& lo, float& hi) {
    asm("mov.b64 {%0,%1}, %2;" : "=f"(lo), "=f"(hi) : "l"(v));
}
__device__ __forceinline__ u64t fma2(u64t a, u64t b, u64t c) {
    u64t d; asm("fma.rn.f32x2 %0, %1, %2, %3;" : "=l"(d) : "l"(a), "l"(b), "l"(c)); return d;
}
__device__ __forceinline__ u64t mul2(u64t a, u64t b) {
    u64t d; asm("mul.rn.f32x2 %0, %1, %2;" : "=l"(d) : "l"(a), "l"(b)); return d;
}
__device__ __forceinline__ void lds_v2u64(uint32_t addr, u64t& a, u64t& b) {
    asm volatile("ld.shared.v2.b64 {%0,%1}, [%2];" : "=l"(a), "=l"(b) : "r"(addr));
}

// ---------------- weight convert: f32 -> hi/lo bf16 ----------------
__global__ __launch_bounds__(256)
void conv_hl(const float* __restrict__ s, __nv_bfloat16* __restrict__ h,
             __nv_bfloat16* __restrict__ l, int n4) {
    int i = blockIdx.x * 256 + threadIdx.x;
    if (i >= n4) return;
    float4 v = *(const float4*)(s + (size_t)i * 4);
    uint32_t h01, h23, l01, l23;
    split4(v, h01, h23, l01, l23);
    *(uint2*)(h + (size_t)i * 4) = make_uint2(h01, h23);
    *(uint2*)(l + (size_t)i * 4) = make_uint2(l01, l23);
}

// ---------------- layernorm: writes hi/lo bf16 ----------------
__global__ __launch_bounds__(256)
void layernorm_k(const float* __restrict__ x, const float* __restrict__ gamma,
                 const float* __restrict__ beta,
                 __nv_bfloat16* __restrict__ oh, __nv_bfloat16* __restrict__ ol) {
    int row = blockIdx.x;
    const float* xr = x + (size_t)row * DM;
    int t = threadIdx.x;
    float4 v = *(const float4*)(xr + t * 4);
    float s  = v.x + v.y + v.z + v.w;
    float ss = v.x*v.x + v.y*v.y + v.z*v.z + v.w*v.w;
    #pragma unroll
    for (int o = 16; o > 0; o >>= 1) {
        s  += __shfl_xor_sync(0xffffffffu, s,  o);
        ss += __shfl_xor_sync(0xffffffffu, ss, o);
    }
    __shared__ float rs[8], rss[8];
    int w = t >> 5, l = t & 31;
    if (l == 0) { rs[w] = s; rss[w] = ss; }
    __syncthreads();
    if (w == 0) {
        float a = (l < 8) ? rs[l]  : 0.f;
        float b = (l < 8) ? rss[l] : 0.f;
        #pragma unroll
        for (int o = 4; o > 0; o >>= 1) {
            a += __shfl_xor_sync(0xffffffffu, a, o);
            b += __shfl_xor_sync(0xffffffffu, b, o);
        }
        if (l == 0) { rs[0] = a; rss[0] = b; }
    }
    __syncthreads();
    float mean = rs[0] * (1.0f / DM);
    float var  = rss[0] * (1.0f / DM) - mean * mean;
    float rstd = rsqrtf(var + EPSLN);
    float4 gv = *(const float4*)(gamma + t * 4);
    float4 bv = *(const float4*)(beta  + t * 4);
    float4 o4;
    o4.x = gv.x * ((v.x - mean) * rstd) + bv.x;
    o4.y = gv.y * ((v.y - mean) * rstd) + bv.y;
    o4.z = gv.z * ((v.z - mean) * rstd) + bv.z;
    o4.w = gv.w * ((v.w - mean) * rstd) + bv.w;
    uint32_t h01, h23, l01, l23;
    split4(o4, h01, h23, l01, l23);
    *(uint2*)(oh + (size_t)row * DM + t * 4) = make_uint2(h01, h23);
    *(uint2*)(ol + (size_t)row * DM + t * 4) = make_uint2(l01, l23);
}

// ---------------- bf16-split GEMM NT with cp.async pipeline ----------------
// C = A @ W^T. A,W given as hi/lo bf16 [rows, K]. 128x128x32 tile, 8 warps.
// EPI: 0 none, 1 +R, 2 gelu.  OUT: 0 f32 -> Cf, 2 hi/lo bf16 -> Ch/Cl.
#define GSM (65536 + 1024)

template<int EPI, int OUT>
__global__ __launch_bounds__(256)
void gemm_tc(const __nv_bfloat16* __restrict__ Ah_, const __nv_bfloat16* __restrict__ Al_,
             const __nv_bfloat16* __restrict__ Wh_, const __nv_bfloat16* __restrict__ Wl_,
             const float* __restrict__ R, float* __restrict__ Cf,
             __nv_bfloat16* __restrict__ Ch, __nv_bfloat16* __restrict__ Cl,
             int M, int N, int K) {
    extern __shared__ char dsm[];
    uint32_t sb = (smem_u32(dsm) + 1023) & ~1023u;   // stage s at sb + s*32768

    int tid = threadIdx.x, wid = tid >> 5, lane = tid & 31;
    int wm = wid >> 2, wn = wid & 3;

    const char* Abh = (const char*)(Ah_ + (size_t)blockIdx.y * 128 * K);
    const char* Abl = (const char*)(Al_ + (size_t)blockIdx.y * 128 * K);
    const char* Wbh = (const char*)(Wh_ + (size_t)blockIdx.x * 128 * K);
    const char* Wbl = (const char*)(Wl_ + (size_t)blockIdx.x * 128 * K);

    int r0 = tid >> 2, gg = tid & 3;            // rows r0 and r0+64, granule gg
    uint32_t so0 = swz(r0 * 64 + gg * 16);
    uint32_t so1 = swz((r0 + 64) * 64 + gg * 16);
    size_t gb0 = (size_t)r0 * K * 2 + gg * 16;          // byte offsets (bf16)
    size_t gb1 = (size_t)(r0 + 64) * K * 2 + gg * 16;

    #define ISSUE(kb, st) do { \
        uint32_t s_ = sb + (st) * 32768; \
        size_t kbb = (size_t)(kb) * 2; \
        CPA(s_ + so0,         Abh + gb0 + kbb); \
        CPA(s_ + so1,         Abh + gb1 + kbb); \
        CPA(s_ + 8192  + so0, Abl + gb0 + kbb); \
        CPA(s_ + 8192  + so1, Abl + gb1 + kbb); \
        CPA(s_ + 16384 + so0, Wbh + gb0 + kbb); \
        CPA(s_ + 16384 + so1, Wbh + gb1 + kbb); \
        CPA(s_ + 24576 + so0, Wbl + gb0 + kbb); \
        CPA(s_ + 24576 + so1, Wbl + gb1 + kbb); \
    } while (0)

    float acc[4][4][4];
    #pragma unroll
    for (int i = 0; i < 4; i++)
        #pragma unroll
        for (int j = 0; j < 4; j++)
            #pragma unroll
            for (int e = 0; e < 4; e++) acc[i][j][e] = 0.f;

    int g = lane >> 3, rg = lane & 7;
    int nch = K >> 5;

    ISSUE(0, 0);
    asm volatile("cp.async.commit_group;");

    for (int ch = 0; ch < nch; ch++) {
        if (ch + 1 < nch) {
            ISSUE((ch + 1) << 5, (ch + 1) & 1);
            asm volatile("cp.async.commit_group;");
            asm volatile("cp.async.wait_group 1;" ::: "memory");
        } else {
            asm volatile("cp.async.wait_group 0;" ::: "memory");
        }
        __syncthreads();
        uint32_t ah = sb + (ch & 1) * 32768;
        uint32_t al = ah + 8192, bh = ah + 16384, bl = ah + 24576;

        #pragma unroll
        for (int ks = 0; ks < 2; ks++) {
            int kseg = ks * 2 + (g >> 1);
            uint32_t bhr[2][4], blr[2][4];
            #pragma unroll
            for (int p = 0; p < 2; p++) {
                int nrow = wn * 32 + p * 16 + (g & 1) * 8 + rg;
                uint32_t off = swz(nrow * 64 + kseg * 16);
                ldsm_x4(bh + off, bhr[p][0], bhr[p][1], bhr[p][2], bhr[p][3]);
                ldsm_x4(bl + off, blr[p][0], blr[p][1], blr[p][2], blr[p][3]);
            }
            #pragma unroll
            for (int mf = 0; mf < 4; mf++) {
                int arow = wm * 64 + mf * 16 + (g & 1) * 8 + rg;
                uint32_t off = swz(arow * 64 + kseg * 16);
                uint32_t a0,a1,a2,a3, x0,x1,x2,x3;
                ldsm_x4(ah + off, a0, a1, a2, a3);
                ldsm_x4(al + off, x0, x1, x2, x3);
                #pragma unroll
                for (int nf = 0; nf < 4; nf++) {
                    int p = nf >> 1, q = nf & 1;
                    uint32_t bb0 = bhr[p][q], bb1 = bhr[p][q + 2];
                    uint32_t cb0 = blr[p][q], cb1 = blr[p][q + 2];
                    mma_bf16(acc[mf][nf], a0, a1, a2, a3, bb0, bb1);
                    mma_bf16(acc[mf][nf], a0, a1, a2, a3, cb0, cb1);
                    mma_bf16(acc[mf][nf], x0, x1, x2, x3, bb0, bb1);
                }
            }
        }
        __syncthreads();
    }

    #pragma unroll
    for (int mf = 0; mf < 4; mf++) {
        #pragma unroll
        for (int h = 0; h < 2; h++) {
            size_t row = (size_t)blockIdx.y * 128 + wm * 64 + mf * 16 + (lane >> 2) + h * 8;
            #pragma unroll
            for (int nf = 0; nf < 4; nf++) {
                size_t col = (size_t)blockIdx.x * 128 + wn * 32 + nf * 8 + (lane & 3) * 2;
                float o0 = acc[mf][nf][h * 2 + 0];
                float o1 = acc[mf][nf][h * 2 + 1];
                if (EPI == 1) {
                    float2 r2 = *(const float2*)(R + row * N + col);
                    o0 += r2.x; o1 += r2.y;
                }
                if (EPI == 2) { o0 = gelu_f(o0); o1 = gelu_f(o1); }
                if (OUT == 0) {
                    *(float2*)(Cf + row * N + col) = make_float2(o0, o1);
                } else {
                    uint32_t hh, ll;
                    split2(o0, o1, hh, ll);
                    *(uint32_t*)(Ch + row * N + col) = hh;
                    *(uint32_t*)(Cl + row * N + col) = ll;
                }
            }
        }
    }
}

// ---------------- flash attention (f32x2 packed, causal) ----------------
// writes hi/lo bf16 for the wo GEMM
__global__ __launch_bounds__(128)
void flash_attn_k(const float* __restrict__ Q, const float* __restrict__ Kg,
                  const float* __restrict__ Vg,
                  __nv_bfloat16* __restrict__ Oh, __nv_bfloat16* __restrict__ Ol) {
    int qt = blockIdx.x;
    int bh = blockIdx.y;
    int b = bh >> 4, h = bh & 15;
    int t = threadIdx.x;
    int srow = qt * 128 + t;
    __shared__ float ks[64][DH];
    __shared__ float vs[64][DH];
    uint32_t ksb = smem_u32(ks), vsb = smem_u32(vs);

    const size_t qoff = ((size_t)(b * SEQ + srow) * NH + h) * DH;
    u64t q2[32];
    #pragma unroll
    for (int i = 0; i < 16; i++) {
        float4 v = *(const float4*)(Q + qoff + i * 4);
        q2[i*2]   = pack2(v.x * 0.125f, v.y * 0.125f);
        q2[i*2+1] = pack2(v.z * 0.125f, v.w * 0.125f);
    }
    u64t acc2[32];
    #pragma unroll
    for (int i = 0; i < 32; i++) acc2[i] = 0ull;
    float m = -1e30f, lsum = 0.f;

    int nkb = 2 * qt + 2;
    for (int kb = 0; kb < nkb; kb++) {
        int base = kb * 64;
        #pragma unroll
        for (int i = 0; i < 8; i++) {
            int idx = t + i * 128;
            int row = idx >> 4;
            int c4  = (idx & 15) * 4;
            size_t goff = ((size_t)(b * SEQ + base + row) * NH + h) * DH + c4;
            *(float4*)&ks[row][c4] = *(const float4*)(Kg + goff);
            *(float4*)&vs[row][c4] = *(const float4*)(Vg + goff);
        }
        __syncthreads();
        #pragma unroll
        for (int c = 0; c < 64; c += 16) {
            float s[16];
            #pragma unroll
            for (int j = 0; j < 16; j++) {
                u64t d2 = 0ull;
                uint32_t ra = ksb + (c + j) * 256;
                #pragma unroll
                for (int i = 0; i < 16; i++) {
                    u64t k0, k1;
                    lds_v2u64(ra + i * 16, k0, k1);
                    d2 = fma2(q2[i*2], k0, d2);
                    d2 = fma2(q2[i*2+1], k1, d2);
                }
                float lo, hi; unpack2(d2, lo, hi);
                float d = lo + hi;
                s[j] = (base + c + j <= srow) ? d : -1e30f;
            }
            float cm = s[0];
            #pragma unroll
            for (int j = 1; j < 16; j++) cm = fmaxf(cm, s[j]);
            float mn  = fmaxf(m, cm);
            float fac = __expf(m - mn);
            lsum *= fac;
            u64t f2 = pack2(fac, fac);
            #pragma unroll
            for (int i = 0; i < 32; i++) acc2[i] = mul2(acc2[i], f2);
            #pragma unroll
            for (int j = 0; j < 16; j++) {
                float p = __expf(s[j] - mn);
                lsum += p;
                u64t p2 = pack2(p, p);
                uint32_t rv = vsb + (c + j) * 256;
                #pragma unroll
                for (int i = 0; i < 16; i++) {
                    u64t v0, v1;
                    lds_v2u64(rv + i * 16, v0, v1);
                    acc2[i*2]   = fma2(p2, v0, acc2[i*2]);
                    acc2[i*2+1] = fma2(p2, v1, acc2[i*2+1]);
                }
            }
            m = mn;
        }
        __syncthreads();
    }
    float rl = 1.0f / lsum;
    #pragma unroll
    for (int i = 0; i < 32; i++) {
        float lo, hi; unpack2(acc2[i], lo, hi);
        lo *= rl; hi *= rl;
        uint32_t hh, ll;
        split2(lo, hi, hh, ll);
        *(uint32_t*)(Oh + qoff + i * 2) = hh;
        *(uint32_t*)(Ol + qoff + i * 2) = ll;
    }
}

// ---------------- launch ----------------
extern "C" void kernel_launch(void* const* d_in, const int* in_sizes, int n_in,
                              void* d_out, int out_size) {
    const float* x      = (const float*)d_in[0];
    const float* gamma1 = (const float*)d_in[1];
    const float* beta1  = (const float*)d_in[2];
    const float* wq     = (const float*)d_in[3];
    const float* wk     = (const float*)d_in[4];
    const float* wv     = (const float*)d_in[5];
    const float* wo     = (const float*)d_in[6];
    const float* gamma2 = (const float*)d_in[7];
    const float* beta2  = (const float*)d_in[8];
    const float* fc1    = (const float*)d_in[9];
    const float* fc2    = (const float*)d_in[10];
    float* out = (float*)d_out;

    float *q_, *k_, *v_, *resid_;
    __nv_bfloat16 *nh_, *nl_, *ah_, *al_, *hh_, *hl_, *wh_, *wl_;
    cudaGetSymbolAddress((void**)&q_,    g_q);
    cudaGetSymbolAddress((void**)&k_,    g_k);
    cudaGetSymbolAddress((void**)&v_,    g_v);
    cudaGetSymbolAddress((void**)&resid_,g_resid);
    cudaGetSymbolAddress((void**)&nh_,   g_nh);
    cudaGetSymbolAddress((void**)&nl_,   g_nl);
    cudaGetSymbolAddress((void**)&ah_,   g_ah);
    cudaGetSymbolAddress((void**)&al_,   g_al);
    cudaGetSymbolAddress((void**)&hh_,   g_hh);
    cudaGetSymbolAddress((void**)&hl_,   g_hl);
    cudaGetSymbolAddress((void**)&wh_,   g_wh);
    cudaGetSymbolAddress((void**)&wl_,   g_wl);

    cudaFuncSetAttribute(gemm_tc<0,0>, cudaFuncAttributeMaxDynamicSharedMemorySize, GSM);
    cudaFuncSetAttribute(gemm_tc<1,0>, cudaFuncAttributeMaxDynamicSharedMemorySize, GSM);
    cudaFuncSetAttribute(gemm_tc<2,2>, cudaFuncAttributeMaxDynamicSharedMemorySize, GSM);

    // weight conversion (graph-capturable, deterministic)
    const int nQ = DM * DM / 4, nF = DFF * DM / 4;
    conv_hl<<<(nQ + 255) / 256, 256>>>(wq,  wh_ + WOFF_Q,  wl_ + WOFF_Q,  nQ);
    conv_hl<<<(nQ + 255) / 256, 256>>>(wk,  wh_ + WOFF_K,  wl_ + WOFF_K,  nQ);
    conv_hl<<<(nQ + 255) / 256, 256>>>(wv,  wh_ + WOFF_V,  wl_ + WOFF_V,  nQ);
    conv_hl<<<(nQ + 255) / 256, 256>>>(wo,  wh_ + WOFF_O,  wl_ + WOFF_O,  nQ);
    conv_hl<<<(nF + 255) / 256, 256>>>(fc1, wh_ + WOFF_F1, wl_ + WOFF_F1, nF);
    conv_hl<<<(nF + 255) / 256, 256>>>(fc2, wh_ + WOFF_F2, wl_ + WOFF_F2, nF);

    dim3 gProj(DM / 128, BS / 128);      // (8, 64)
    dim3 gFF1(DFF / 128, BS / 128);      // (32, 64)
    dim3 gFF2(DM / 128, BS / 128);       // (8, 64)
    dim3 gAttn(SEQ / 128, BATCH * NH);   // (16, 64)

    layernorm_k<<<BS, 256>>>(x, gamma1, beta1, nh_, nl_);
    gemm_tc<0,0><<<gProj, 256, GSM>>>(nh_, nl_, wh_ + WOFF_Q, wl_ + WOFF_Q,
                                      nullptr, q_, nullptr, nullptr, BS, DM, DM);
    gemm_tc<0,0><<<gProj, 256, GSM>>>(nh_, nl_, wh_ + WOFF_K, wl_ + WOFF_K,
                                      nullptr, k_, nullptr, nullptr, BS, DM, DM);
    gemm_tc<0,0><<<gProj, 256, GSM>>>(nh_, nl_, wh_ + WOFF_V, wl_ + WOFF_V,
                                      nullptr, v_, nullptr, nullptr, BS, DM, DM);
    flash_attn_k<<<gAttn, 128>>>(q_, k_, v_, ah_, al_);
    gemm_tc<1,0><<<gProj, 256, GSM>>>(ah_, al_, wh_ + WOFF_O, wl_ + WOFF_O,
                                      x, resid_, nullptr, nullptr, BS, DM, DM);
    layernorm_k<<<BS, 256>>>(resid_, gamma2, beta2, nh_, nl_);
    gemm_tc<2,2><<<gFF1, 256, GSM>>>(nh_, nl_, wh_ + WOFF_F1, wl_ + WOFF_F1,
                                     nullptr, nullptr, hh_, hl_, BS, DFF, DM);
    gemm_tc<1,0><<<gFF2, 256, GSM>>>(hh_, hl_, wh_ + WOFF_F2, wl_ + WOFF_F2,
                                     resid_, out, nullptr, nullptr, BS, DM, DFF);
}

// round 6
// speedup vs baseline: 3.7496x; 1.5395x over previous
#include <cuda_runtime.h>
#include <cuda_bf16.h>
#include <math.h>
#include <stdint.h>

#define BATCH 4
#define SEQ   2048
#define DM    1024
#define NH    16
#define DH    64
#define DFF   4096
#define BS    (BATCH*SEQ)
#define EPSLN 1e-5f
#define CEXP  0.1803368801f   // log2(e)/8

// ---------------- scratch ----------------
__device__ float g_resid[(size_t)BS*DM];
__device__ __nv_bfloat16 g_nh[(size_t)BS*DM],  g_nl[(size_t)BS*DM];
__device__ __nv_bfloat16 g_qh[(size_t)BS*DM],  g_ql[(size_t)BS*DM];
__device__ __nv_bfloat16 g_kh[(size_t)BS*DM],  g_kl[(size_t)BS*DM];
__device__ __nv_bfloat16 g_vh[(size_t)BS*DM],  g_vl[(size_t)BS*DM];
__device__ __nv_bfloat16 g_ah[(size_t)BS*DM],  g_al[(size_t)BS*DM];
__device__ __nv_bfloat16 g_hh[(size_t)BS*DFF], g_hl[(size_t)BS*DFF];
#define WOFF_Q  ((size_t)0)
#define WOFF_K  ((size_t)DM*DM)
#define WOFF_V  ((size_t)2*DM*DM)
#define WOFF_O  ((size_t)3*DM*DM)
#define WOFF_F1 ((size_t)4*DM*DM)
#define WOFF_F2 ((size_t)(4*DM*DM) + (size_t)DFF*DM)
__device__ __nv_bfloat16 g_wh[(size_t)4*DM*DM + 2*(size_t)DFF*DM];
__device__ __nv_bfloat16 g_wl[(size_t)4*DM*DM + 2*(size_t)DFF*DM];

// ---------------- helpers ----------------
__device__ __forceinline__ uint32_t smem_u32(const void* p) {
    uint32_t a;
    asm("{ .reg .u64 t; cvta.to.shared.u64 t, %1; cvt.u32.u64 %0, t; }" : "=r"(a) : "l"(p));
    return a;
}
__device__ __forceinline__ uint32_t swz(uint32_t off)    { return off ^ ((off >> 3) & 0x30); }
__device__ __forceinline__ uint32_t swz128(uint32_t off) { return off ^ ((off >> 3) & 0x70); }

__device__ __forceinline__ void ldsm_x4(uint32_t addr, uint32_t& r0, uint32_t& r1,
                                        uint32_t& r2, uint32_t& r3) {
    asm volatile("ldmatrix.sync.aligned.m8n8.x4.shared.b16 {%0,%1,%2,%3}, [%4];"
                 : "=r"(r0), "=r"(r1), "=r"(r2), "=r"(r3) : "r"(addr));
}
__device__ __forceinline__ void ldsm_x4t(uint32_t addr, uint32_t* r) {
    asm volatile("ldmatrix.sync.aligned.m8n8.x4.trans.shared.b16 {%0,%1,%2,%3}, [%4];"
                 : "=r"(r[0]), "=r"(r[1]), "=r"(r[2]), "=r"(r[3]) : "r"(addr));
}
__device__ __forceinline__ void mma_bf16(float* d, uint32_t a0, uint32_t a1,
                                         uint32_t a2, uint32_t a3,
                                         uint32_t b0, uint32_t b1) {
    asm volatile("mma.sync.aligned.m16n8k16.row.col.f32.bf16.bf16.f32 "
                 "{%0,%1,%2,%3}, {%4,%5,%6,%7}, {%8,%9}, {%0,%1,%2,%3};"
                 : "+f"(d[0]), "+f"(d[1]), "+f"(d[2]), "+f"(d[3])
                 : "r"(a0), "r"(a1), "r"(a2), "r"(a3), "r"(b0), "r"(b1));
}
#define CPA(dst, src) asm volatile("cp.async.cg.shared.global [%0], [%1], 16;" :: "r"(dst), "l"(src))

__device__ __forceinline__ float gelu_f(float x) {
    float c = x * x * x;
    float t = tanhf(0.7978845608f * (x + 0.044715f * c));
    return 0.5f * x * (1.0f + t);
}
__device__ __forceinline__ void split4(float4 v, uint32_t& h01, uint32_t& h23,
                                       uint32_t& l01, uint32_t& l23) {
    __nv_bfloat16 h0 = __float2bfloat16(v.x), h1 = __float2bfloat16(v.y);
    __nv_bfloat16 h2 = __float2bfloat16(v.z), h3 = __float2bfloat16(v.w);
    __nv_bfloat16 l0 = __float2bfloat16(v.x - __bfloat162float(h0));
    __nv_bfloat16 l1 = __float2bfloat16(v.y - __bfloat162float(h1));
    __nv_bfloat16 l2 = __float2bfloat16(v.z - __bfloat162float(h2));
    __nv_bfloat16 l3 = __float2bfloat16(v.w - __bfloat162float(h3));
    h01 = ((uint32_t)__bfloat16_as_ushort(h1) << 16) | __bfloat16_as_ushort(h0);
    h23 = ((uint32_t)__bfloat16_as_ushort(h3) << 16) | __bfloat16_as_ushort(h2);
    l01 = ((uint32_t)__bfloat16_as_ushort(l1) << 16) | __bfloat16_as_ushort(l0);
    l23 = ((uint32_t)__bfloat16_as_ushort(l3) << 16) | __bfloat16_as_ushort(l2);
}
__device__ __forceinline__ void split2(float x, float y, uint32_t& h, uint32_t& l) {
    __nv_bfloat16 h0 = __float2bfloat16(x), h1 = __float2bfloat16(y);
    __nv_bfloat16 l0 = __float2bfloat16(x - __bfloat162float(h0));
    __nv_bfloat16 l1 = __float2bfloat16(y - __bfloat162float(h1));
    h = ((uint32_t)__bfloat16_as_ushort(h1) << 16) | __bfloat16_as_ushort(h0);
    l = ((uint32_t)__bfloat16_as_ushort(l1) << 16) | __bfloat16_as_ushort(l0);
}

// fast 2^x on the FMA pipe (x <= 0, clamped at -60; rel err < 1e-6)
__device__ __forceinline__ float exp2p(float x) {
    x = fmaxf(x, -60.0f);
    float y = x + 12582912.0f;                 // round-to-nearest int (magic)
    int   n = __float_as_int(y) - 0x4B400000;
    float f = x - (y - 12582912.0f);           // f in [-0.5, 0.5]
    float p =            1.3333558e-3f;
    p = fmaf(p, f, 9.6181291e-3f);
    p = fmaf(p, f, 5.5504109e-2f);
    p = fmaf(p, f, 2.4022651e-1f);
    p = fmaf(p, f, 6.9314718e-1f);
    p = fmaf(p, f, 1.0f);
    return __uint_as_float(__float_as_uint(p) + ((uint32_t)n << 23));
}

// ---------------- weight convert ----------------
__global__ __launch_bounds__(256)
void conv_hl(const float* __restrict__ s, __nv_bfloat16* __restrict__ h,
             __nv_bfloat16* __restrict__ l, int n4) {
    int i = blockIdx.x * 256 + threadIdx.x;
    if (i >= n4) return;
    float4 v = *(const float4*)(s + (size_t)i * 4);
    uint32_t h01, h23, l01, l23;
    split4(v, h01, h23, l01, l23);
    *(uint2*)(h + (size_t)i * 4) = make_uint2(h01, h23);
    *(uint2*)(l + (size_t)i * 4) = make_uint2(l01, l23);
}

// ---------------- layernorm -> hi/lo bf16 ----------------
__global__ __launch_bounds__(256)
void layernorm_k(const float* __restrict__ x, const float* __restrict__ gamma,
                 const float* __restrict__ beta,
                 __nv_bfloat16* __restrict__ oh, __nv_bfloat16* __restrict__ ol) {
    int row = blockIdx.x;
    const float* xr = x + (size_t)row * DM;
    int t = threadIdx.x;
    float4 v = *(const float4*)(xr + t * 4);
    float s  = v.x + v.y + v.z + v.w;
    float ss = v.x*v.x + v.y*v.y + v.z*v.z + v.w*v.w;
    #pragma unroll
    for (int o = 16; o > 0; o >>= 1) {
        s  += __shfl_xor_sync(0xffffffffu, s,  o);
        ss += __shfl_xor_sync(0xffffffffu, ss, o);
    }
    __shared__ float rs[8], rss[8];
    int w = t >> 5, l = t & 31;
    if (l == 0) { rs[w] = s; rss[w] = ss; }
    __syncthreads();
    if (w == 0) {
        float a = (l < 8) ? rs[l]  : 0.f;
        float b = (l < 8) ? rss[l] : 0.f;
        #pragma unroll
        for (int o = 4; o > 0; o >>= 1) {
            a += __shfl_xor_sync(0xffffffffu, a, o);
            b += __shfl_xor_sync(0xffffffffu, b, o);
        }
        if (l == 0) { rs[0] = a; rss[0] = b; }
    }
    __syncthreads();
    float mean = rs[0] * (1.0f / DM);
    float var  = rss[0] * (1.0f / DM) - mean * mean;
    float rstd = rsqrtf(var + EPSLN);
    float4 gv = *(const float4*)(gamma + t * 4);
    float4 bv = *(const float4*)(beta  + t * 4);
    float4 o4;
    o4.x = gv.x * ((v.x - mean) * rstd) + bv.x;
    o4.y = gv.y * ((v.y - mean) * rstd) + bv.y;
    o4.z = gv.z * ((v.z - mean) * rstd) + bv.z;
    o4.w = gv.w * ((v.w - mean) * rstd) + bv.w;
    uint32_t h01, h23, l01, l23;
    split4(o4, h01, h23, l01, l23);
    *(uint2*)(oh + (size_t)row * DM + t * 4) = make_uint2(h01, h23);
    *(uint2*)(ol + (size_t)row * DM + t * 4) = make_uint2(l01, l23);
}

// ---------------- bf16-split GEMM NT (cp.async pipelined) ----------------
#define GSM (65536 + 1024)

template<int EPI, int OUT>
__global__ __launch_bounds__(256)
void gemm_tc(const __nv_bfloat16* __restrict__ Ah_, const __nv_bfloat16* __restrict__ Al_,
             const __nv_bfloat16* __restrict__ Wh_, const __nv_bfloat16* __restrict__ Wl_,
             const float* __restrict__ R, float* __restrict__ Cf,
             __nv_bfloat16* __restrict__ Ch, __nv_bfloat16* __restrict__ Cl,
             int M, int N, int K) {
    extern __shared__ char dsm[];
    uint32_t sb = (smem_u32(dsm) + 1023) & ~1023u;

    int tid = threadIdx.x, wid = tid >> 5, lane = tid & 31;
    int wm = wid >> 2, wn = wid & 3;

    const char* Abh = (const char*)(Ah_ + (size_t)blockIdx.y * 128 * K);
    const char* Abl = (const char*)(Al_ + (size_t)blockIdx.y * 128 * K);
    const char* Wbh = (const char*)(Wh_ + (size_t)blockIdx.x * 128 * K);
    const char* Wbl = (const char*)(Wl_ + (size_t)blockIdx.x * 128 * K);

    int r0 = tid >> 2, gg = tid & 3;
    uint32_t so0 = swz(r0 * 64 + gg * 16);
    uint32_t so1 = swz((r0 + 64) * 64 + gg * 16);
    size_t gb0 = (size_t)r0 * K * 2 + gg * 16;
    size_t gb1 = (size_t)(r0 + 64) * K * 2 + gg * 16;

    #define G_ISSUE(kb, st) do { \
        uint32_t s_ = sb + (st) * 32768; \
        size_t kbb = (size_t)(kb) * 2; \
        CPA(s_ + so0,         Abh + gb0 + kbb); \
        CPA(s_ + so1,         Abh + gb1 + kbb); \
        CPA(s_ + 8192  + so0, Abl + gb0 + kbb); \
        CPA(s_ + 8192  + so1, Abl + gb1 + kbb); \
        CPA(s_ + 16384 + so0, Wbh + gb0 + kbb); \
        CPA(s_ + 16384 + so1, Wbh + gb1 + kbb); \
        CPA(s_ + 24576 + so0, Wbl + gb0 + kbb); \
        CPA(s_ + 24576 + so1, Wbl + gb1 + kbb); \
    } while (0)

    float acc[4][4][4];
    #pragma unroll
    for (int i = 0; i < 4; i++)
        #pragma unroll
        for (int j = 0; j < 4; j++)
            #pragma unroll
            for (int e = 0; e < 4; e++) acc[i][j][e] = 0.f;

    int g = lane >> 3, rg = lane & 7;
    int nch = K >> 5;

    G_ISSUE(0, 0);
    asm volatile("cp.async.commit_group;");

    for (int ch = 0; ch < nch; ch++) {
        if (ch + 1 < nch) {
            G_ISSUE((ch + 1) << 5, (ch + 1) & 1);
            asm volatile("cp.async.commit_group;");
            asm volatile("cp.async.wait_group 1;" ::: "memory");
        } else {
            asm volatile("cp.async.wait_group 0;" ::: "memory");
        }
        __syncthreads();
        uint32_t ah = sb + (ch & 1) * 32768;
        uint32_t al = ah + 8192, bh = ah + 16384, bl = ah + 24576;

        #pragma unroll
        for (int ks = 0; ks < 2; ks++) {
            int kseg = ks * 2 + (g >> 1);
            uint32_t bhr[2][4], blr[2][4];
            #pragma unroll
            for (int p = 0; p < 2; p++) {
                int nrow = wn * 32 + p * 16 + (g & 1) * 8 + rg;
                uint32_t off = swz(nrow * 64 + kseg * 16);
                ldsm_x4(bh + off, bhr[p][0], bhr[p][1], bhr[p][2], bhr[p][3]);
                ldsm_x4(bl + off, blr[p][0], blr[p][1], blr[p][2], blr[p][3]);
            }
            #pragma unroll
            for (int mf = 0; mf < 4; mf++) {
                int arow = wm * 64 + mf * 16 + (g & 1) * 8 + rg;
                uint32_t off = swz(arow * 64 + kseg * 16);
                uint32_t a0,a1,a2,a3, x0,x1,x2,x3;
                ldsm_x4(ah + off, a0, a1, a2, a3);
                ldsm_x4(al + off, x0, x1, x2, x3);
                #pragma unroll
                for (int nf = 0; nf < 4; nf++) {
                    int p = nf >> 1, q = nf & 1;
                    uint32_t bb0 = bhr[p][q], bb1 = bhr[p][q + 2];
                    uint32_t cb0 = blr[p][q], cb1 = blr[p][q + 2];
                    mma_bf16(acc[mf][nf], a0, a1, a2, a3, bb0, bb1);
                    mma_bf16(acc[mf][nf], a0, a1, a2, a3, cb0, cb1);
                    mma_bf16(acc[mf][nf], x0, x1, x2, x3, bb0, bb1);
                }
            }
        }
        __syncthreads();
    }

    #pragma unroll
    for (int mf = 0; mf < 4; mf++) {
        #pragma unroll
        for (int h = 0; h < 2; h++) {
            size_t row = (size_t)blockIdx.y * 128 + wm * 64 + mf * 16 + (lane >> 2) + h * 8;
            #pragma unroll
            for (int nf = 0; nf < 4; nf++) {
                size_t col = (size_t)blockIdx.x * 128 + wn * 32 + nf * 8 + (lane & 3) * 2;
                float o0 = acc[mf][nf][h * 2 + 0];
                float o1 = acc[mf][nf][h * 2 + 1];
                if (EPI == 1) {
                    float2 r2 = *(const float2*)(R + row * N + col);
                    o0 += r2.x; o1 += r2.y;
                }
                if (EPI == 2) { o0 = gelu_f(o0); o1 = gelu_f(o1); }
                if (OUT == 0) {
                    *(float2*)(Cf + row * N + col) = make_float2(o0, o1);
                } else {
                    uint32_t hh, ll;
                    split2(o0, o1, hh, ll);
                    *(uint32_t*)(Ch + row * N + col) = hh;
                    *(uint32_t*)(Cl + row * N + col) = ll;
                }
            }
        }
    }
}

// ---------------- tensor-core flash attention (causal) ----------------
// grid (SEQ/64, B*H), 128 threads. 64 q-rows per CTA; 64-key tiles.
// 3-pass split QK^T and PV; fp32 softmax with FMA-pipe exp2.
#define ASM (16384 + 65536 + 1024)

__global__ __launch_bounds__(128)
void flash_attn_tc(const __nv_bfloat16* __restrict__ Qh, const __nv_bfloat16* __restrict__ Ql,
                   const __nv_bfloat16* __restrict__ Kh, const __nv_bfloat16* __restrict__ Kl,
                   const __nv_bfloat16* __restrict__ Vh, const __nv_bfloat16* __restrict__ Vl,
                   __nv_bfloat16* __restrict__ Oh, __nv_bfloat16* __restrict__ Ol) {
    extern __shared__ char dsm[];
    uint32_t sb = (smem_u32(dsm) + 1023) & ~1023u;
    uint32_t sQh = sb, sQl = sb + 8192;

    int qt = gridDim.x - 1 - blockIdx.x;           // long tiles first
    int bh = blockIdx.y;
    int b = bh >> 4, h = bh & 15;
    int tid = threadIdx.x, w = tid >> 5, lane = tid & 31;
    int g = lane >> 3, rg = lane & 7;
    int qstart = qt * 64;

    const char* Khc = (const char*)Kh;  const char* Klc = (const char*)Kl;
    const char* Vhc = (const char*)Vh;  const char* Vlc = (const char*)Vl;

    // issue Q (hi/lo)
    size_t qg = ((size_t)(b * SEQ + qstart)) * DM + h * 64;
    #pragma unroll
    for (int i = 0; i < 4; i++) {
        int seg = tid + i * 128;
        int row = seg >> 3, cs = seg & 7;
        uint32_t so = swz128(row * 128 + cs * 16);
        size_t gb = (qg + (size_t)row * DM + cs * 8) * 2;
        CPA(sQh + so, (const char*)Qh + gb);
        CPA(sQl + so, (const char*)Ql + gb);
    }

    #define AKV_ISSUE(kbase, st) do { \
        uint32_t s_ = sb + 16384 + (st) * 32768; \
        size_t g0 = ((size_t)(b * SEQ + (kbase))) * DM + h * 64; \
        _Pragma("unroll") \
        for (int i_ = 0; i_ < 4; i_++) { \
            int seg_ = tid + i_ * 128; \
            int row_ = seg_ >> 3, cs_ = seg_ & 7; \
            uint32_t so_ = swz128(row_ * 128 + cs_ * 16); \
            size_t gb_ = (g0 + (size_t)row_ * DM + cs_ * 8) * 2; \
            CPA(s_ + so_,          Khc + gb_); \
            CPA(s_ + 8192  + so_,  Klc + gb_); \
            CPA(s_ + 16384 + so_,  Vhc + gb_); \
            CPA(s_ + 24576 + so_,  Vlc + gb_); \
        } \
    } while (0)

    AKV_ISSUE(0, 0);
    asm volatile("cp.async.commit_group;");

    float s[8][4], o[8][4];
    uint32_t qfh[4][4], qfl[4][4];
    #pragma unroll
    for (int nf = 0; nf < 8; nf++)
        #pragma unroll
        for (int e = 0; e < 4; e++) o[nf][e] = 0.f;
    float m0 = -1e30f, m1 = -1e30f, l0 = 0.f, l1 = 0.f;

    for (int kb = 0; kb <= qt; kb++) {
        if (kb < qt) {
            AKV_ISSUE((kb + 1) * 64, (kb + 1) & 1);
            asm volatile("cp.async.commit_group;");
            asm volatile("cp.async.wait_group 1;" ::: "memory");
        } else {
            asm volatile("cp.async.wait_group 0;" ::: "memory");
        }
        __syncthreads();

        if (kb == 0) {        // Q fragments once
            #pragma unroll
            for (int kseg = 0; kseg < 4; kseg++) {
                int arow = w * 16 + (g & 1) * 8 + rg;
                uint32_t off = swz128(arow * 128 + kseg * 32 + (g >> 1) * 16);
                ldsm_x4(sQh + off, qfh[kseg][0], qfh[kseg][1], qfh[kseg][2], qfh[kseg][3]);
                ldsm_x4(sQl + off, qfl[kseg][0], qfl[kseg][1], qfl[kseg][2], qfl[kseg][3]);
            }
        }

        uint32_t kB = sb + 16384 + (kb & 1) * 32768;
        uint32_t sKh = kB, sKl = kB + 8192, sVh = kB + 16384, sVl = kB + 24576;

        // ---- S = Q K^T (3-pass split) ----
        #pragma unroll
        for (int nf = 0; nf < 8; nf++)
            #pragma unroll
            for (int e = 0; e < 4; e++) s[nf][e] = 0.f;
        #pragma unroll
        for (int kseg = 0; kseg < 4; kseg++) {
            uint32_t kh[4][4], kl[4][4];
            int kcol = kseg * 32 + (g >> 1) * 16;
            #pragma unroll
            for (int p = 0; p < 4; p++) {
                int nrow = p * 16 + (g & 1) * 8 + rg;
                uint32_t off = swz128(nrow * 128 + kcol);
                ldsm_x4(sKh + off, kh[p][0], kh[p][1], kh[p][2], kh[p][3]);
                ldsm_x4(sKl + off, kl[p][0], kl[p][1], kl[p][2], kl[p][3]);
            }
            #pragma unroll
            for (int p = 0; p < 4; p++)
                #pragma unroll
                for (int q = 0; q < 2; q++) {
                    int nf = 2 * p + q;
                    mma_bf16(s[nf], qfh[kseg][0], qfh[kseg][1], qfh[kseg][2], qfh[kseg][3],
                             kh[p][q], kh[p][q + 2]);
                    mma_bf16(s[nf], qfh[kseg][0], qfh[kseg][1], qfh[kseg][2], qfh[kseg][3],
                             kl[p][q], kl[p][q + 2]);
                    mma_bf16(s[nf], qfl[kseg][0], qfl[kseg][1], qfl[kseg][2], qfl[kseg][3],
                             kh[p][q], kh[p][q + 2]);
                }
        }

        // ---- causal mask (diagonal tile only) ----
        if (kb == qt) {
            int r0 = w * 16 + (lane >> 2);          // within-tile row
            int c0 = (lane & 3) * 2;
            #pragma unroll
            for (int nf = 0; nf < 8; nf++) {
                int c = c0 + nf * 8;
                if (c     > r0)     s[nf][0] = -1e30f;
                if (c + 1 > r0)     s[nf][1] = -1e30f;
                if (c     > r0 + 8) s[nf][2] = -1e30f;
                if (c + 1 > r0 + 8) s[nf][3] = -1e30f;
            }
        }

        // ---- online softmax ----
        float mr0 = -1e30f, mr1 = -1e30f;
        #pragma unroll
        for (int nf = 0; nf < 8; nf++) {
            mr0 = fmaxf(mr0, fmaxf(s[nf][0], s[nf][1]));
            mr1 = fmaxf(mr1, fmaxf(s[nf][2], s[nf][3]));
        }
        mr0 = fmaxf(mr0, __shfl_xor_sync(0xffffffffu, mr0, 1));
        mr0 = fmaxf(mr0, __shfl_xor_sync(0xffffffffu, mr0, 2));
        mr1 = fmaxf(mr1, __shfl_xor_sync(0xffffffffu, mr1, 1));
        mr1 = fmaxf(mr1, __shfl_xor_sync(0xffffffffu, mr1, 2));
        float mn0 = fmaxf(m0, mr0), mn1 = fmaxf(m1, mr1);
        float f0 = exp2p((m0 - mn0) * CEXP);
        float f1 = exp2p((m1 - mn1) * CEXP);
        l0 *= f0; l1 *= f1;
        #pragma unroll
        for (int nf = 0; nf < 8; nf++) {
            o[nf][0] *= f0; o[nf][1] *= f0; o[nf][2] *= f1; o[nf][3] *= f1;
        }
        m0 = mn0; m1 = mn1;
        #pragma unroll
        for (int nf = 0; nf < 8; nf++) {
            s[nf][0] = exp2p((s[nf][0] - m0) * CEXP);
            s[nf][1] = exp2p((s[nf][1] - m0) * CEXP);
            s[nf][2] = exp2p((s[nf][2] - m1) * CEXP);
            s[nf][3] = exp2p((s[nf][3] - m1) * CEXP);
            l0 += s[nf][0] + s[nf][1];
            l1 += s[nf][2] + s[nf][3];
        }

        // ---- O += P V (3-pass split, P from registers) ----
        #pragma unroll
        for (int kk = 0; kk < 4; kk++) {
            uint32_t ah0, ah1, ah2, ah3, al0, al1, al2, al3;
            split2(s[2*kk][0],   s[2*kk][1],   ah0, al0);
            split2(s[2*kk][2],   s[2*kk][3],   ah1, al1);
            split2(s[2*kk+1][0], s[2*kk+1][1], ah2, al2);
            split2(s[2*kk+1][2], s[2*kk+1][3], ah3, al3);
            int vrow = kk * 16 + (g >> 1) * 8 + rg;
            #pragma unroll
            for (int ep = 0; ep < 4; ep++) {
                int ecol = ep * 16 + (g & 1) * 8;
                uint32_t off = swz128(vrow * 128 + ecol * 2);
                uint32_t vh[4], vl[4];
                ldsm_x4t(sVh + off, vh);
                ldsm_x4t(sVl + off, vl);
                mma_bf16(o[2*ep],   ah0, ah1, ah2, ah3, vh[0], vh[2]);
                mma_bf16(o[2*ep+1], ah0, ah1, ah2, ah3, vh[1], vh[3]);
                mma_bf16(o[2*ep],   al0, al1, al2, al3, vh[0], vh[2]);
                mma_bf16(o[2*ep+1], al0, al1, al2, al3, vh[1], vh[3]);
                mma_bf16(o[2*ep],   ah0, ah1, ah2, ah3, vl[0], vl[2]);
                mma_bf16(o[2*ep+1], ah0, ah1, ah2, ah3, vl[1], vl[3]);
            }
        }
        __syncthreads();
    }

    // ---- finalize ----
    l0 += __shfl_xor_sync(0xffffffffu, l0, 1);
    l0 += __shfl_xor_sync(0xffffffffu, l0, 2);
    l1 += __shfl_xor_sync(0xffffffffu, l1, 1);
    l1 += __shfl_xor_sync(0xffffffffu, l1, 2);
    float rl0 = 1.0f / l0, rl1 = 1.0f / l1;
    int row0 = qstart + w * 16 + (lane >> 2);
    size_t ob0 = ((size_t)(b * SEQ + row0)) * DM + h * 64;
    size_t ob1 = ob0 + (size_t)8 * DM;
    #pragma unroll
    for (int nf = 0; nf < 8; nf++) {
        int e = nf * 8 + (lane & 3) * 2;
        uint32_t hh, ll;
        split2(o[nf][0] * rl0, o[nf][1] * rl0, hh, ll);
        *(uint32_t*)(Oh + ob0 + e) = hh;
        *(uint32_t*)(Ol + ob0 + e) = ll;
        split2(o[nf][2] * rl1, o[nf][3] * rl1, hh, ll);
        *(uint32_t*)(Oh + ob1 + e) = hh;
        *(uint32_t*)(Ol + ob1 + e) = ll;
    }
}

// ---------------- launch ----------------
extern "C" void kernel_launch(void* const* d_in, const int* in_sizes, int n_in,
                              void* d_out, int out_size) {
    const float* x      = (const float*)d_in[0];
    const float* gamma1 = (const float*)d_in[1];
    const float* beta1  = (const float*)d_in[2];
    const float* wq     = (const float*)d_in[3];
    const float* wk     = (const float*)d_in[4];
    const float* wv     = (const float*)d_in[5];
    const float* wo     = (const float*)d_in[6];
    const float* gamma2 = (const float*)d_in[7];
    const float* beta2  = (const float*)d_in[8];
    const float* fc1    = (const float*)d_in[9];
    const float* fc2    = (const float*)d_in[10];
    float* out = (float*)d_out;

    float *resid_;
    __nv_bfloat16 *nh_, *nl_, *qh_, *ql_, *kh_, *kl_, *vh_, *vl_, *ah_, *al_, *hh_, *hl_, *wh_, *wl_;
    cudaGetSymbolAddress((void**)&resid_, g_resid);
    cudaGetSymbolAddress((void**)&nh_, g_nh);  cudaGetSymbolAddress((void**)&nl_, g_nl);
    cudaGetSymbolAddress((void**)&qh_, g_qh);  cudaGetSymbolAddress((void**)&ql_, g_ql);
    cudaGetSymbolAddress((void**)&kh_, g_kh);  cudaGetSymbolAddress((void**)&kl_, g_kl);
    cudaGetSymbolAddress((void**)&vh_, g_vh);  cudaGetSymbolAddress((void**)&vl_, g_vl);
    cudaGetSymbolAddress((void**)&ah_, g_ah);  cudaGetSymbolAddress((void**)&al_, g_al);
    cudaGetSymbolAddress((void**)&hh_, g_hh);  cudaGetSymbolAddress((void**)&hl_, g_hl);
    cudaGetSymbolAddress((void**)&wh_, g_wh);  cudaGetSymbolAddress((void**)&wl_, g_wl);

    cudaFuncSetAttribute(gemm_tc<0,2>, cudaFuncAttributeMaxDynamicSharedMemorySize, GSM);
    cudaFuncSetAttribute(gemm_tc<1,0>, cudaFuncAttributeMaxDynamicSharedMemorySize, GSM);
    cudaFuncSetAttribute(gemm_tc<2,2>, cudaFuncAttributeMaxDynamicSharedMemorySize, GSM);
    cudaFuncSetAttribute(flash_attn_tc, cudaFuncAttributeMaxDynamicSharedMemorySize, ASM);

    const int nQ = DM * DM / 4, nF = DFF * DM / 4;
    conv_hl<<<(nQ + 255) / 256, 256>>>(wq,  wh_ + WOFF_Q,  wl_ + WOFF_Q,  nQ);
    conv_hl<<<(nQ + 255) / 256, 256>>>(wk,  wh_ + WOFF_K,  wl_ + WOFF_K,  nQ);
    conv_hl<<<(nQ + 255) / 256, 256>>>(wv,  wh_ + WOFF_V,  wl_ + WOFF_V,  nQ);
    conv_hl<<<(nQ + 255) / 256, 256>>>(wo,  wh_ + WOFF_O,  wl_ + WOFF_O,  nQ);
    conv_hl<<<(nF + 255) / 256, 256>>>(fc1, wh_ + WOFF_F1, wl_ + WOFF_F1, nF);
    conv_hl<<<(nF + 255) / 256, 256>>>(fc2, wh_ + WOFF_F2, wl_ + WOFF_F2, nF);

    dim3 gProj(DM / 128, BS / 128);
    dim3 gFF1(DFF / 128, BS / 128);
    dim3 gFF2(DM / 128, BS / 128);
    dim3 gAttn(SEQ / 64, BATCH * NH);

    layernorm_k<<<BS, 256>>>(x, gamma1, beta1, nh_, nl_);
    gemm_tc<0,2><<<gProj, 256, GSM>>>(nh_, nl_, wh_ + WOFF_Q, wl_ + WOFF_Q,
                                      nullptr, nullptr, qh_, ql_, BS, DM, DM);
    gemm_tc<0,2><<<gProj, 256, GSM>>>(nh_, nl_, wh_ + WOFF_K, wl_ + WOFF_K,
                                      nullptr, nullptr, kh_, kl_, BS, DM, DM);
    gemm_tc<0,2><<<gProj, 256, GSM>>>(nh_, nl_, wh_ + WOFF_V, wl_ + WOFF_V,
                                      nullptr, nullptr, vh_, vl_, BS, DM, DM);
    flash_attn_tc<<<gAttn, 128, ASM>>>(qh_, ql_, kh_, kl_, vh_, vl_, ah_, al_);
    gemm_tc<1,0><<<gProj, 256, GSM>>>(ah_, al_, wh_ + WOFF_O, wl_ + WOFF_O,
                                      x, resid_, nullptr, nullptr, BS, DM, DM);
    layernorm_k<<<BS, 256>>>(resid_, gamma2, beta2, nh_, nl_);
    gemm_tc<2,2><<<gFF1, 256, GSM>>>(nh_, nl_, wh_ + WOFF_F1, wl_ + WOFF_F1,
                                     nullptr, nullptr, hh_, hl_, BS, DFF, DM);
    gemm_tc<1,0><<<gFF2, 256, GSM>>>(hh_, hl_, wh_ + WOFF_F2, wl_ + WOFF_F2,
                                     resid_, out, nullptr, nullptr, BS, DM, DFF);
}

// round 7
// speedup vs baseline: 3.7942x; 1.0119x over previous
#include <cuda_runtime.h>
#include <cuda_bf16.h>
#include <math.h>
#include <stdint.h>

#define BATCH 4
#define SEQ   2048
#define DM    1024
#define NH    16
#define DH    64
#define DFF   4096
#define BS    (BATCH*SEQ)
#define QKVS  3072
#define EPSLN 1e-5f
#define CEXP  0.1803368801f   // log2(e)/8

// ---------------- scratch ----------------
__device__ float g_resid[(size_t)BS*DM];
__device__ __nv_bfloat16 g_nh[(size_t)BS*DM],   g_nl[(size_t)BS*DM];
__device__ __nv_bfloat16 g_qkvh[(size_t)BS*QKVS], g_qkvl[(size_t)BS*QKVS];
__device__ __nv_bfloat16 g_ah[(size_t)BS*DM],   g_al[(size_t)BS*DM];
__device__ __nv_bfloat16 g_hh[(size_t)BS*DFF],  g_hl[(size_t)BS*DFF];
#define WOFF_Q  ((size_t)0)
#define WOFF_K  ((size_t)DM*DM)
#define WOFF_V  ((size_t)2*DM*DM)
#define WOFF_O  ((size_t)3*DM*DM)
#define WOFF_F1 ((size_t)4*DM*DM)
#define WOFF_F2 ((size_t)(4*DM*DM) + (size_t)DFF*DM)
__device__ __nv_bfloat16 g_wh[(size_t)4*DM*DM + 2*(size_t)DFF*DM];
__device__ __nv_bfloat16 g_wl[(size_t)4*DM*DM + 2*(size_t)DFF*DM];

// ---------------- helpers ----------------
__device__ __forceinline__ uint32_t smem_u32(const void* p) {
    uint32_t a;
    asm("{ .reg .u64 t; cvta.to.shared.u64 t, %1; cvt.u32.u64 %0, t; }" : "=r"(a) : "l"(p));
    return a;
}
__device__ __forceinline__ uint32_t swz(uint32_t off)    { return off ^ ((off >> 3) & 0x30); }
__device__ __forceinline__ uint32_t swz128(uint32_t off) { return off ^ ((off >> 3) & 0x70); }

__device__ __forceinline__ void ldsm_x4(uint32_t addr, uint32_t& r0, uint32_t& r1,
                                        uint32_t& r2, uint32_t& r3) {
    asm volatile("ldmatrix.sync.aligned.m8n8.x4.shared.b16 {%0,%1,%2,%3}, [%4];"
                 : "=r"(r0), "=r"(r1), "=r"(r2), "=r"(r3) : "r"(addr));
}
__device__ __forceinline__ void ldsm_x4t(uint32_t addr, uint32_t* r) {
    asm volatile("ldmatrix.sync.aligned.m8n8.x4.trans.shared.b16 {%0,%1,%2,%3}, [%4];"
                 : "=r"(r[0]), "=r"(r[1]), "=r"(r[2]), "=r"(r[3]) : "r"(addr));
}
__device__ __forceinline__ void mma_bf16(float* d, uint32_t a0, uint32_t a1,
                                         uint32_t a2, uint32_t a3,
                                         uint32_t b0, uint32_t b1) {
    asm volatile("mma.sync.aligned.m16n8k16.row.col.f32.bf16.bf16.f32 "
                 "{%0,%1,%2,%3}, {%4,%5,%6,%7}, {%8,%9}, {%0,%1,%2,%3};"
                 : "+f"(d[0]), "+f"(d[1]), "+f"(d[2]), "+f"(d[3])
                 : "r"(a0), "r"(a1), "r"(a2), "r"(a3), "r"(b0), "r"(b1));
}
#define CPA(dst, src) asm volatile("cp.async.cg.shared.global [%0], [%1], 16;" :: "r"(dst), "l"(src))

__device__ __forceinline__ float gelu_f(float x) {
    float c = x * x * x;
    float t = tanhf(0.7978845608f * (x + 0.044715f * c));
    return 0.5f * x * (1.0f + t);
}
__device__ __forceinline__ void split4(float4 v, uint32_t& h01, uint32_t& h23,
                                       uint32_t& l01, uint32_t& l23) {
    __nv_bfloat16 h0 = __float2bfloat16(v.x), h1 = __float2bfloat16(v.y);
    __nv_bfloat16 h2 = __float2bfloat16(v.z), h3 = __float2bfloat16(v.w);
    __nv_bfloat16 l0 = __float2bfloat16(v.x - __bfloat162float(h0));
    __nv_bfloat16 l1 = __float2bfloat16(v.y - __bfloat162float(h1));
    __nv_bfloat16 l2 = __float2bfloat16(v.z - __bfloat162float(h2));
    __nv_bfloat16 l3 = __float2bfloat16(v.w - __bfloat162float(h3));
    h01 = ((uint32_t)__bfloat16_as_ushort(h1) << 16) | __bfloat16_as_ushort(h0);
    h23 = ((uint32_t)__bfloat16_as_ushort(h3) << 16) | __bfloat16_as_ushort(h2);
    l01 = ((uint32_t)__bfloat16_as_ushort(l1) << 16) | __bfloat16_as_ushort(l0);
    l23 = ((uint32_t)__bfloat16_as_ushort(l3) << 16) | __bfloat16_as_ushort(l2);
}
__device__ __forceinline__ void split2(float x, float y, uint32_t& h, uint32_t& l) {
    __nv_bfloat16 h0 = __float2bfloat16(x), h1 = __float2bfloat16(y);
    __nv_bfloat16 l0 = __float2bfloat16(x - __bfloat162float(h0));
    __nv_bfloat16 l1 = __float2bfloat16(y - __bfloat162float(h1));
    h = ((uint32_t)__bfloat16_as_ushort(h1) << 16) | __bfloat16_as_ushort(h0);
    l = ((uint32_t)__bfloat16_as_ushort(l1) << 16) | __bfloat16_as_ushort(l0);
}
__device__ __forceinline__ float exp2p(float x) {
    x = fmaxf(x, -60.0f);
    float y = x + 12582912.0f;
    int   n = __float_as_int(y) - 0x4B400000;
    float f = x - (y - 12582912.0f);
    float p =            1.3333558e-3f;
    p = fmaf(p, f, 9.6181291e-3f);
    p = fmaf(p, f, 5.5504109e-2f);
    p = fmaf(p, f, 2.4022651e-1f);
    p = fmaf(p, f, 6.9314718e-1f);
    p = fmaf(p, f, 1.0f);
    return __uint_as_float(__float_as_uint(p) + ((uint32_t)n << 23));
}

// ---------------- weight convert ----------------
__global__ __launch_bounds__(256)
void conv_hl(const float* __restrict__ s, __nv_bfloat16* __restrict__ h,
             __nv_bfloat16* __restrict__ l, int n4) {
    int i = blockIdx.x * 256 + threadIdx.x;
    if (i >= n4) return;
    float4 v = *(const float4*)(s + (size_t)i * 4);
    uint32_t h01, h23, l01, l23;
    split4(v, h01, h23, l01, l23);
    *(uint2*)(h + (size_t)i * 4) = make_uint2(h01, h23);
    *(uint2*)(l + (size_t)i * 4) = make_uint2(l01, l23);
}

// ---------------- layernorm -> hi/lo bf16 ----------------
__global__ __launch_bounds__(256)
void layernorm_k(const float* __restrict__ x, const float* __restrict__ gamma,
                 const float* __restrict__ beta,
                 __nv_bfloat16* __restrict__ oh, __nv_bfloat16* __restrict__ ol) {
    int row = blockIdx.x;
    const float* xr = x + (size_t)row * DM;
    int t = threadIdx.x;
    float4 v = *(const float4*)(xr + t * 4);
    float s  = v.x + v.y + v.z + v.w;
    float ss = v.x*v.x + v.y*v.y + v.z*v.z + v.w*v.w;
    #pragma unroll
    for (int o = 16; o > 0; o >>= 1) {
        s  += __shfl_xor_sync(0xffffffffu, s,  o);
        ss += __shfl_xor_sync(0xffffffffu, ss, o);
    }
    __shared__ float rs[8], rss[8];
    int w = t >> 5, l = t & 31;
    if (l == 0) { rs[w] = s; rss[w] = ss; }
    __syncthreads();
    if (w == 0) {
        float a = (l < 8) ? rs[l]  : 0.f;
        float b = (l < 8) ? rss[l] : 0.f;
        #pragma unroll
        for (int o = 4; o > 0; o >>= 1) {
            a += __shfl_xor_sync(0xffffffffu, a, o);
            b += __shfl_xor_sync(0xffffffffu, b, o);
        }
        if (l == 0) { rs[0] = a; rss[0] = b; }
    }
    __syncthreads();
    float mean = rs[0] * (1.0f / DM);
    float var  = rss[0] * (1.0f / DM) - mean * mean;
    float rstd = rsqrtf(var + EPSLN);
    float4 gv = *(const float4*)(gamma + t * 4);
    float4 bv = *(const float4*)(beta  + t * 4);
    float4 o4;
    o4.x = gv.x * ((v.x - mean) * rstd) + bv.x;
    o4.y = gv.y * ((v.y - mean) * rstd) + bv.y;
    o4.z = gv.z * ((v.z - mean) * rstd) + bv.z;
    o4.w = gv.w * ((v.w - mean) * rstd) + bv.w;
    uint32_t h01, h23, l01, l23;
    split4(o4, h01, h23, l01, l23);
    *(uint2*)(oh + (size_t)row * DM + t * 4) = make_uint2(h01, h23);
    *(uint2*)(ol + (size_t)row * DM + t * 4) = make_uint2(l01, l23);
}

// ---------------- bf16-split GEMM NT (3-stage cp.async, 1 sync/chunk) ----------------
#define GSM (3*32768 + 1024)

template<int EPI, int OUT>
__global__ __launch_bounds__(256)
void gemm_tc(const __nv_bfloat16* __restrict__ Ah_, const __nv_bfloat16* __restrict__ Al_,
             const __nv_bfloat16* __restrict__ Wh_, const __nv_bfloat16* __restrict__ Wl_,
             const float* __restrict__ R, float* __restrict__ Cf,
             __nv_bfloat16* __restrict__ Ch, __nv_bfloat16* __restrict__ Cl,
             int M, int N, int K) {
    extern __shared__ char dsm[];
    uint32_t sb = (smem_u32(dsm) + 1023) & ~1023u;

    int tid = threadIdx.x, wid = tid >> 5, lane = tid & 31;
    int wm = wid >> 2, wn = wid & 3;

    const char* Abh = (const char*)(Ah_ + (size_t)blockIdx.y * 128 * K);
    const char* Abl = (const char*)(Al_ + (size_t)blockIdx.y * 128 * K);
    const char* Wbh = (const char*)(Wh_ + (size_t)blockIdx.x * 128 * K);
    const char* Wbl = (const char*)(Wl_ + (size_t)blockIdx.x * 128 * K);

    int r0 = tid >> 2, gg = tid & 3;
    uint32_t so0 = swz(r0 * 64 + gg * 16);
    uint32_t so1 = swz((r0 + 64) * 64 + gg * 16);
    size_t gb0 = (size_t)r0 * K * 2 + gg * 16;
    size_t gb1 = (size_t)(r0 + 64) * K * 2 + gg * 16;

    #define G_ISSUE(kb, st) do { \
        uint32_t s_ = sb + (st) * 32768; \
        size_t kbb = (size_t)(kb) * 2; \
        CPA(s_ + so0,         Abh + gb0 + kbb); \
        CPA(s_ + so1,         Abh + gb1 + kbb); \
        CPA(s_ + 8192  + so0, Abl + gb0 + kbb); \
        CPA(s_ + 8192  + so1, Abl + gb1 + kbb); \
        CPA(s_ + 16384 + so0, Wbh + gb0 + kbb); \
        CPA(s_ + 16384 + so1, Wbh + gb1 + kbb); \
        CPA(s_ + 24576 + so0, Wbl + gb0 + kbb); \
        CPA(s_ + 24576 + so1, Wbl + gb1 + kbb); \
    } while (0)

    float acc[4][4][4];
    #pragma unroll
    for (int i = 0; i < 4; i++)
        #pragma unroll
        for (int j = 0; j < 4; j++)
            #pragma unroll
            for (int e = 0; e < 4; e++) acc[i][j][e] = 0.f;

    int g = lane >> 3, rg = lane & 7;
    int nch = K >> 5;

    G_ISSUE(0, 0);
    asm volatile("cp.async.commit_group;");
    G_ISSUE(32, 1);
    asm volatile("cp.async.commit_group;");

    int st_c = 0, st_i = 2;
    for (int ch = 0; ch < nch; ch++) {
        if (ch + 1 < nch) asm volatile("cp.async.wait_group 1;" ::: "memory");
        else              asm volatile("cp.async.wait_group 0;" ::: "memory");
        __syncthreads();
        if (ch + 2 < nch) {
            G_ISSUE((ch + 2) << 5, st_i);
            asm volatile("cp.async.commit_group;");
            st_i = (st_i == 2) ? 0 : st_i + 1;
        }
        uint32_t ah = sb + st_c * 32768;
        st_c = (st_c == 2) ? 0 : st_c + 1;
        uint32_t al = ah + 8192, bh = ah + 16384, bl = ah + 24576;

        #pragma unroll
        for (int ks = 0; ks < 2; ks++) {
            int kseg = ks * 2 + (g >> 1);
            uint32_t bhr[2][4], blr[2][4];
            #pragma unroll
            for (int p = 0; p < 2; p++) {
                int nrow = wn * 32 + p * 16 + (g & 1) * 8 + rg;
                uint32_t off = swz(nrow * 64 + kseg * 16);
                ldsm_x4(bh + off, bhr[p][0], bhr[p][1], bhr[p][2], bhr[p][3]);
                ldsm_x4(bl + off, blr[p][0], blr[p][1], blr[p][2], blr[p][3]);
            }
            #pragma unroll
            for (int mf = 0; mf < 4; mf++) {
                int arow = wm * 64 + mf * 16 + (g & 1) * 8 + rg;
                uint32_t off = swz(arow * 64 + kseg * 16);
                uint32_t a0,a1,a2,a3, x0,x1,x2,x3;
                ldsm_x4(ah + off, a0, a1, a2, a3);
                ldsm_x4(al + off, x0, x1, x2, x3);
                #pragma unroll
                for (int nf = 0; nf < 4; nf++) {
                    int p = nf >> 1, q = nf & 1;
                    uint32_t bb0 = bhr[p][q], bb1 = bhr[p][q + 2];
                    uint32_t cb0 = blr[p][q], cb1 = blr[p][q + 2];
                    mma_bf16(acc[mf][nf], a0, a1, a2, a3, bb0, bb1);
                    mma_bf16(acc[mf][nf], a0, a1, a2, a3, cb0, cb1);
                    mma_bf16(acc[mf][nf], x0, x1, x2, x3, bb0, bb1);
                }
            }
        }
    }

    #pragma unroll
    for (int mf = 0; mf < 4; mf++) {
        #pragma unroll
        for (int h = 0; h < 2; h++) {
            size_t row = (size_t)blockIdx.y * 128 + wm * 64 + mf * 16 + (lane >> 2) + h * 8;
            #pragma unroll
            for (int nf = 0; nf < 4; nf++) {
                size_t col = (size_t)blockIdx.x * 128 + wn * 32 + nf * 8 + (lane & 3) * 2;
                float o0 = acc[mf][nf][h * 2 + 0];
                float o1 = acc[mf][nf][h * 2 + 1];
                if (EPI == 1) {
                    float2 r2 = *(const float2*)(R + row * N + col);
                    o0 += r2.x; o1 += r2.y;
                }
                if (EPI == 2) { o0 = gelu_f(o0); o1 = gelu_f(o1); }
                if (OUT == 0) {
                    *(float2*)(Cf + row * N + col) = make_float2(o0, o1);
                } else {
                    uint32_t hh, ll;
                    split2(o0, o1, hh, ll);
                    *(uint32_t*)(Ch + row * N + col) = hh;
                    *(uint32_t*)(Cl + row * N + col) = ll;
                }
            }
        }
    }
}

// ---------------- tensor-core flash attention (3-stage KV, causal) ----------------
// Q/K/V packed in qkv buffers [BS, 3072]: q@0, k@1024, v@2048 (+h*64).
#define ASM (16384 + 3*32768 + 1024)

__global__ __launch_bounds__(128)
void flash_attn_tc(const __nv_bfloat16* __restrict__ QKVh,
                   const __nv_bfloat16* __restrict__ QKVl,
                   __nv_bfloat16* __restrict__ Oh, __nv_bfloat16* __restrict__ Ol) {
    extern __shared__ char dsm[];
    uint32_t sb = (smem_u32(dsm) + 1023) & ~1023u;
    uint32_t sQh = sb, sQl = sb + 8192;

    int qt = gridDim.x - 1 - blockIdx.x;
    int bh = blockIdx.y;
    int b = bh >> 4, h = bh & 15;
    int tid = threadIdx.x, w = tid >> 5, lane = tid & 31;
    int g = lane >> 3, rg = lane & 7;
    int qstart = qt * 64;

    const char* Qhc = (const char*)QKVh;  const char* Qlc = (const char*)QKVl;

    // issue Q (hi/lo) — folded into first commit group
    size_t qg = ((size_t)(b * SEQ + qstart)) * QKVS + h * 64;
    #pragma unroll
    for (int i = 0; i < 4; i++) {
        int seg = tid + i * 128;
        int row = seg >> 3, cs = seg & 7;
        uint32_t so = swz128(row * 128 + cs * 16);
        size_t gb = (qg + (size_t)row * QKVS + cs * 8) * 2;
        CPA(sQh + so, Qhc + gb);
        CPA(sQl + so, Qlc + gb);
    }

    #define AKV_ISSUE(kbase, st) do { \
        uint32_t s_ = sb + 16384 + (st) * 32768; \
        size_t g0 = ((size_t)(b * SEQ + (kbase))) * QKVS + 1024 + h * 64; \
        _Pragma("unroll") \
        for (int i_ = 0; i_ < 4; i_++) { \
            int seg_ = tid + i_ * 128; \
            int row_ = seg_ >> 3, cs_ = seg_ & 7; \
            uint32_t so_ = swz128(row_ * 128 + cs_ * 16); \
            size_t gb_ = (g0 + (size_t)row_ * QKVS + cs_ * 8) * 2; \
            CPA(s_ + so_,          Qhc + gb_); \
            CPA(s_ + 8192  + so_,  Qlc + gb_); \
            CPA(s_ + 16384 + so_,  Qhc + gb_ + 2048); \
            CPA(s_ + 24576 + so_,  Qlc + gb_ + 2048); \
        } \
    } while (0)

    AKV_ISSUE(0, 0);
    asm volatile("cp.async.commit_group;");
    if (qt >= 1) {
        AKV_ISSUE(64, 1);
        asm volatile("cp.async.commit_group;");
    }

    float s[8][4], o[8][4];
    uint32_t qfh[4][4], qfl[4][4];
    #pragma unroll
    for (int nf = 0; nf < 8; nf++)
        #pragma unroll
        for (int e = 0; e < 4; e++) o[nf][e] = 0.f;
    float m0 = -1e30f, m1 = -1e30f, l0 = 0.f, l1 = 0.f;

    int st_c = 0, st_i = 2;
    for (int kb = 0; kb <= qt; kb++) {
        if (kb < qt) asm volatile("cp.async.wait_group 1;" ::: "memory");
        else         asm volatile("cp.async.wait_group 0;" ::: "memory");
        __syncthreads();
        if (kb + 2 <= qt) {
            AKV_ISSUE((kb + 2) * 64, st_i);
            asm volatile("cp.async.commit_group;");
            st_i = (st_i == 2) ? 0 : st_i + 1;
        }

        if (kb == 0) {
            #pragma unroll
            for (int kseg = 0; kseg < 4; kseg++) {
                int arow = w * 16 + (g & 1) * 8 + rg;
                uint32_t off = swz128(arow * 128 + kseg * 32 + (g >> 1) * 16);
                ldsm_x4(sQh + off, qfh[kseg][0], qfh[kseg][1], qfh[kseg][2], qfh[kseg][3]);
                ldsm_x4(sQl + off, qfl[kseg][0], qfl[kseg][1], qfl[kseg][2], qfl[kseg][3]);
            }
        }

        uint32_t kB = sb + 16384 + st_c * 32768;
        st_c = (st_c == 2) ? 0 : st_c + 1;
        uint32_t sKh = kB, sKl = kB + 8192, sVh = kB + 16384, sVl = kB + 24576;

        // ---- S = Q K^T ----
        #pragma unroll
        for (int nf = 0; nf < 8; nf++)
            #pragma unroll
            for (int e = 0; e < 4; e++) s[nf][e] = 0.f;
        #pragma unroll
        for (int kseg = 0; kseg < 4; kseg++) {
            uint32_t kh[4][4], kl[4][4];
            int kcol = kseg * 32 + (g >> 1) * 16;
            #pragma unroll
            for (int p = 0; p < 4; p++) {
                int nrow = p * 16 + (g & 1) * 8 + rg;
                uint32_t off = swz128(nrow * 128 + kcol);
                ldsm_x4(sKh + off, kh[p][0], kh[p][1], kh[p][2], kh[p][3]);
                ldsm_x4(sKl + off, kl[p][0], kl[p][1], kl[p][2], kl[p][3]);
            }
            #pragma unroll
            for (int p = 0; p < 4; p++)
                #pragma unroll
                for (int q = 0; q < 2; q++) {
                    int nf = 2 * p + q;
                    mma_bf16(s[nf], qfh[kseg][0], qfh[kseg][1], qfh[kseg][2], qfh[kseg][3],
                             kh[p][q], kh[p][q + 2]);
                    mma_bf16(s[nf], qfh[kseg][0], qfh[kseg][1], qfh[kseg][2], qfh[kseg][3],
                             kl[p][q], kl[p][q + 2]);
                    mma_bf16(s[nf], qfl[kseg][0], qfl[kseg][1], qfl[kseg][2], qfl[kseg][3],
                             kh[p][q], kh[p][q + 2]);
                }
        }

        if (kb == qt) {
            int r0 = w * 16 + (lane >> 2);
            int c0 = (lane & 3) * 2;
            #pragma unroll
            for (int nf = 0; nf < 8; nf++) {
                int c = c0 + nf * 8;
                if (c     > r0)     s[nf][0] = -1e30f;
                if (c + 1 > r0)     s[nf][1] = -1e30f;
                if (c     > r0 + 8) s[nf][2] = -1e30f;
                if (c + 1 > r0 + 8) s[nf][3] = -1e30f;
            }
        }

        // ---- online softmax ----
        float mr0 = -1e30f, mr1 = -1e30f;
        #pragma unroll
        for (int nf = 0; nf < 8; nf++) {
            mr0 = fmaxf(mr0, fmaxf(s[nf][0], s[nf][1]));
            mr1 = fmaxf(mr1, fmaxf(s[nf][2], s[nf][3]));
        }
        mr0 = fmaxf(mr0, __shfl_xor_sync(0xffffffffu, mr0, 1));
        mr0 = fmaxf(mr0, __shfl_xor_sync(0xffffffffu, mr0, 2));
        mr1 = fmaxf(mr1, __shfl_xor_sync(0xffffffffu, mr1, 1));
        mr1 = fmaxf(mr1, __shfl_xor_sync(0xffffffffu, mr1, 2));
        float mn0 = fmaxf(m0, mr0), mn1 = fmaxf(m1, mr1);
        float f0 = exp2p((m0 - mn0) * CEXP);
        float f1 = exp2p((m1 - mn1) * CEXP);
        l0 *= f0; l1 *= f1;
        #pragma unroll
        for (int nf = 0; nf < 8; nf++) {
            o[nf][0] *= f0; o[nf][1] *= f0; o[nf][2] *= f1; o[nf][3] *= f1;
        }
        m0 = mn0; m1 = mn1;
        #pragma unroll
        for (int nf = 0; nf < 8; nf++) {
            s[nf][0] = exp2p((s[nf][0] - m0) * CEXP);
            s[nf][1] = exp2p((s[nf][1] - m0) * CEXP);
            s[nf][2] = exp2p((s[nf][2] - m1) * CEXP);
            s[nf][3] = exp2p((s[nf][3] - m1) * CEXP);
            l0 += s[nf][0] + s[nf][1];
            l1 += s[nf][2] + s[nf][3];
        }

        // ---- O += P V ----
        #pragma unroll
        for (int kk = 0; kk < 4; kk++) {
            uint32_t ah0, ah1, ah2, ah3, al0, al1, al2, al3;
            split2(s[2*kk][0],   s[2*kk][1],   ah0, al0);
            split2(s[2*kk][2],   s[2*kk][3],   ah1, al1);
            split2(s[2*kk+1][0], s[2*kk+1][1], ah2, al2);
            split2(s[2*kk+1][2], s[2*kk+1][3], ah3, al3);
            int vrow = kk * 16 + (g >> 1) * 8 + rg;
            #pragma unroll
            for (int ep = 0; ep < 4; ep++) {
                int ecol = ep * 16 + (g & 1) * 8;
                uint32_t off = swz128(vrow * 128 + ecol * 2);
                uint32_t vh[4], vl[4];
                ldsm_x4t(sVh + off, vh);
                ldsm_x4t(sVl + off, vl);
                mma_bf16(o[2*ep],   ah0, ah1, ah2, ah3, vh[0], vh[2]);
                mma_bf16(o[2*ep+1], ah0, ah1, ah2, ah3, vh[1], vh[3]);
                mma_bf16(o[2*ep],   al0, al1, al2, al3, vh[0], vh[2]);
                mma_bf16(o[2*ep+1], al0, al1, al2, al3, vh[1], vh[3]);
                mma_bf16(o[2*ep],   ah0, ah1, ah2, ah3, vl[0], vl[2]);
                mma_bf16(o[2*ep+1], ah0, ah1, ah2, ah3, vl[1], vl[3]);
            }
        }
    }

    // ---- finalize ----
    l0 += __shfl_xor_sync(0xffffffffu, l0, 1);
    l0 += __shfl_xor_sync(0xffffffffu, l0, 2);
    l1 += __shfl_xor_sync(0xffffffffu, l1, 1);
    l1 += __shfl_xor_sync(0xffffffffu, l1, 2);
    float rl0 = 1.0f / l0, rl1 = 1.0f / l1;
    int row0 = qstart + w * 16 + (lane >> 2);
    size_t ob0 = ((size_t)(b * SEQ + row0)) * DM + h * 64;
    size_t ob1 = ob0 + (size_t)8 * DM;
    #pragma unroll
    for (int nf = 0; nf < 8; nf++) {
        int e = nf * 8 + (lane & 3) * 2;
        uint32_t hh, ll;
        split2(o[nf][0] * rl0, o[nf][1] * rl0, hh, ll);
        *(uint32_t*)(Oh + ob0 + e) = hh;
        *(uint32_t*)(Ol + ob0 + e) = ll;
        split2(o[nf][2] * rl1, o[nf][3] * rl1, hh, ll);
        *(uint32_t*)(Oh + ob1 + e) = hh;
        *(uint32_t*)(Ol + ob1 + e) = ll;
    }
}

// ---------------- launch ----------------
extern "C" void kernel_launch(void* const* d_in, const int* in_sizes, int n_in,
                              void* d_out, int out_size) {
    const float* x      = (const float*)d_in[0];
    const float* gamma1 = (const float*)d_in[1];
    const float* beta1  = (const float*)d_in[2];
    const float* wq     = (const float*)d_in[3];
    const float* wk     = (const float*)d_in[4];
    const float* wv     = (const float*)d_in[5];
    const float* wo     = (const float*)d_in[6];
    const float* gamma2 = (const float*)d_in[7];
    const float* beta2  = (const float*)d_in[8];
    const float* fc1    = (const float*)d_in[9];
    const float* fc2    = (const float*)d_in[10];
    float* out = (float*)d_out;

    float *resid_;
    __nv_bfloat16 *nh_, *nl_, *qkvh_, *qkvl_, *ah_, *al_, *hh_, *hl_, *wh_, *wl_;
    cudaGetSymbolAddress((void**)&resid_, g_resid);
    cudaGetSymbolAddress((void**)&nh_, g_nh);     cudaGetSymbolAddress((void**)&nl_, g_nl);
    cudaGetSymbolAddress((void**)&qkvh_, g_qkvh); cudaGetSymbolAddress((void**)&qkvl_, g_qkvl);
    cudaGetSymbolAddress((void**)&ah_, g_ah);     cudaGetSymbolAddress((void**)&al_, g_al);
    cudaGetSymbolAddress((void**)&hh_, g_hh);     cudaGetSymbolAddress((void**)&hl_, g_hl);
    cudaGetSymbolAddress((void**)&wh_, g_wh);     cudaGetSymbolAddress((void**)&wl_, g_wl);

    cudaFuncSetAttribute(gemm_tc<0,2>, cudaFuncAttributeMaxDynamicSharedMemorySize, GSM);
    cudaFuncSetAttribute(gemm_tc<1,0>, cudaFuncAttributeMaxDynamicSharedMemorySize, GSM);
    cudaFuncSetAttribute(gemm_tc<2,2>, cudaFuncAttributeMaxDynamicSharedMemorySize, GSM);
    cudaFuncSetAttribute(flash_attn_tc, cudaFuncAttributeMaxDynamicSharedMemorySize, ASM);

    const int nQ = DM * DM / 4, nF = DFF * DM / 4;
    conv_hl<<<(nQ + 255) / 256, 256>>>(wq,  wh_ + WOFF_Q,  wl_ + WOFF_Q,  nQ);
    conv_hl<<<(nQ + 255) / 256, 256>>>(wk,  wh_ + WOFF_K,  wl_ + WOFF_K,  nQ);
    conv_hl<<<(nQ + 255) / 256, 256>>>(wv,  wh_ + WOFF_V,  wl_ + WOFF_V,  nQ);
    conv_hl<<<(nQ + 255) / 256, 256>>>(wo,  wh_ + WOFF_O,  wl_ + WOFF_O,  nQ);
    conv_hl<<<(nF + 255) / 256, 256>>>(fc1, wh_ + WOFF_F1, wl_ + WOFF_F1, nF);
    conv_hl<<<(nF + 255) / 256, 256>>>(fc2, wh_ + WOFF_F2, wl_ + WOFF_F2, nF);

    dim3 gQKV(QKVS / 128, BS / 128);     // (24, 64)
    dim3 gProj(DM / 128, BS / 128);      // (8, 64)
    dim3 gFF1(DFF / 128, BS / 128);      // (32, 64)
    dim3 gFF2(DM / 128, BS / 128);       // (8, 64)
    dim3 gAttn(SEQ / 64, BATCH * NH);    // (32, 64)

    layernorm_k<<<BS, 256>>>(x, gamma1, beta1, nh_, nl_);
    gemm_tc<0,2><<<gQKV, 256, GSM>>>(nh_, nl_, wh_ + WOFF_Q, wl_ + WOFF_Q,
                                     nullptr, nullptr, qkvh_, qkvl_, BS, QKVS, DM);
    flash_attn_tc<<<gAttn, 128, ASM>>>(qkvh_, qkvl_, ah_, al_);
    gemm_tc<1,0><<<gProj, 256, GSM>>>(ah_, al_, wh_ + WOFF_O, wl_ + WOFF_O,
                                      x, resid_, nullptr, nullptr, BS, DM, DM);
    layernorm_k<<<BS, 256>>>(resid_, gamma2, beta2, nh_, nl_);
    gemm_tc<2,2><<<gFF1, 256, GSM>>>(nh_, nl_, wh_ + WOFF_F1, wl_ + WOFF_F1,
                                     nullptr, nullptr, hh_, hl_, BS, DFF, DM);
    gemm_tc<1,0><<<gFF2, 256, GSM>>>(hh_, hl_, wh_ + WOFF_F2, wl_ + WOFF_F2,
                                     resid_, out, nullptr, nullptr, BS, DM, DFF);
}

// round 8
// speedup vs baseline: 3.8610x; 1.0176x over previous
#include <cuda_runtime.h>
#include <cuda_bf16.h>
#include <math.h>
#include <stdint.h>

#define BATCH 4
#define SEQ   2048
#define DM    1024
#define NH    16
#define DH    64
#define DFF   4096
#define BS    (BATCH*SEQ)
#define QKVS  3072
#define EPSLN 1e-5f
#define CEXP  0.1803368801f   // log2(e)/8

// ---------------- scratch ----------------
__device__ float g_resid[(size_t)BS*DM];
__device__ __nv_bfloat16 g_nh[(size_t)BS*DM],   g_nl[(size_t)BS*DM];
__device__ __nv_bfloat16 g_qkvh[(size_t)BS*QKVS], g_qkvl[(size_t)BS*QKVS];
__device__ __nv_bfloat16 g_ah[(size_t)BS*DM],   g_al[(size_t)BS*DM];
__device__ __nv_bfloat16 g_hh[(size_t)BS*DFF],  g_hl[(size_t)BS*DFF];
#define WOFF_Q  ((size_t)0)
#define WOFF_K  ((size_t)DM*DM)
#define WOFF_V  ((size_t)2*DM*DM)
#define WOFF_O  ((size_t)3*DM*DM)
#define WOFF_F1 ((size_t)4*DM*DM)
#define WOFF_F2 ((size_t)(4*DM*DM) + (size_t)DFF*DM)
__device__ __nv_bfloat16 g_wh[(size_t)4*DM*DM + 2*(size_t)DFF*DM];
__device__ __nv_bfloat16 g_wl[(size_t)4*DM*DM + 2*(size_t)DFF*DM];

// ---------------- helpers ----------------
__device__ __forceinline__ uint32_t smem_u32(const void* p) {
    uint32_t a;
    asm("{ .reg .u64 t; cvta.to.shared.u64 t, %1; cvt.u32.u64 %0, t; }" : "=r"(a) : "l"(p));
    return a;
}
__device__ __forceinline__ uint32_t swz(uint32_t off)    { return off ^ ((off >> 3) & 0x30); }
__device__ __forceinline__ uint32_t swz128(uint32_t off) { return off ^ ((off >> 3) & 0x70); }

__device__ __forceinline__ void ldsm_x4(uint32_t addr, uint32_t& r0, uint32_t& r1,
                                        uint32_t& r2, uint32_t& r3) {
    asm volatile("ldmatrix.sync.aligned.m8n8.x4.shared.b16 {%0,%1,%2,%3}, [%4];"
                 : "=r"(r0), "=r"(r1), "=r"(r2), "=r"(r3) : "r"(addr));
}
__device__ __forceinline__ void ldsm_x4t(uint32_t addr, uint32_t* r) {
    asm volatile("ldmatrix.sync.aligned.m8n8.x4.trans.shared.b16 {%0,%1,%2,%3}, [%4];"
                 : "=r"(r[0]), "=r"(r[1]), "=r"(r[2]), "=r"(r[3]) : "r"(addr));
}
__device__ __forceinline__ void mma_bf16(float* d, uint32_t a0, uint32_t a1,
                                         uint32_t a2, uint32_t a3,
                                         uint32_t b0, uint32_t b1) {
    asm volatile("mma.sync.aligned.m16n8k16.row.col.f32.bf16.bf16.f32 "
                 "{%0,%1,%2,%3}, {%4,%5,%6,%7}, {%8,%9}, {%0,%1,%2,%3};"
                 : "+f"(d[0]), "+f"(d[1]), "+f"(d[2]), "+f"(d[3])
                 : "r"(a0), "r"(a1), "r"(a2), "r"(a3), "r"(b0), "r"(b1));
}
#define CPA(dst, src) asm volatile("cp.async.cg.shared.global [%0], [%1], 16;" :: "r"(dst), "l"(src))

__device__ __forceinline__ float gelu_f(float x) {
    float c = x * x * x;
    float t = tanhf(0.7978845608f * (x + 0.044715f * c));
    return 0.5f * x * (1.0f + t);
}
__device__ __forceinline__ void split4(float4 v, uint32_t& h01, uint32_t& h23,
                                       uint32_t& l01, uint32_t& l23) {
    __nv_bfloat16 h0 = __float2bfloat16(v.x), h1 = __float2bfloat16(v.y);
    __nv_bfloat16 h2 = __float2bfloat16(v.z), h3 = __float2bfloat16(v.w);
    __nv_bfloat16 l0 = __float2bfloat16(v.x - __bfloat162float(h0));
    __nv_bfloat16 l1 = __float2bfloat16(v.y - __bfloat162float(h1));
    __nv_bfloat16 l2 = __float2bfloat16(v.z - __bfloat162float(h2));
    __nv_bfloat16 l3 = __float2bfloat16(v.w - __bfloat162float(h3));
    h01 = ((uint32_t)__bfloat16_as_ushort(h1) << 16) | __bfloat16_as_ushort(h0);
    h23 = ((uint32_t)__bfloat16_as_ushort(h3) << 16) | __bfloat16_as_ushort(h2);
    l01 = ((uint32_t)__bfloat16_as_ushort(l1) << 16) | __bfloat16_as_ushort(l0);
    l23 = ((uint32_t)__bfloat16_as_ushort(l3) << 16) | __bfloat16_as_ushort(l2);
}
__device__ __forceinline__ void split2(float x, float y, uint32_t& h, uint32_t& l) {
    __nv_bfloat16 h0 = __float2bfloat16(x), h1 = __float2bfloat16(y);
    __nv_bfloat16 l0 = __float2bfloat16(x - __bfloat162float(h0));
    __nv_bfloat16 l1 = __float2bfloat16(y - __bfloat162float(h1));
    h = ((uint32_t)__bfloat16_as_ushort(h1) << 16) | __bfloat16_as_ushort(h0);
    l = ((uint32_t)__bfloat16_as_ushort(l1) << 16) | __bfloat16_as_ushort(l0);
}
__device__ __forceinline__ float exp2p(float x) {
    x = fmaxf(x, -60.0f);
    float y = x + 12582912.0f;
    int   n = __float_as_int(y) - 0x4B400000;
    float f = x - (y - 12582912.0f);
    float p =            1.3333558e-3f;
    p = fmaf(p, f, 9.6181291e-3f);
    p = fmaf(p, f, 5.5504109e-2f);
    p = fmaf(p, f, 2.4022651e-1f);
    p = fmaf(p, f, 6.9314718e-1f);
    p = fmaf(p, f, 1.0f);
    return __uint_as_float(__float_as_uint(p) + ((uint32_t)n << 23));
}

// ---------------- weight convert ----------------
__global__ __launch_bounds__(256)
void conv_hl(const float* __restrict__ s, __nv_bfloat16* __restrict__ h,
             __nv_bfloat16* __restrict__ l, int n4) {
    int i = blockIdx.x * 256 + threadIdx.x;
    if (i >= n4) return;
    float4 v = *(const float4*)(s + (size_t)i * 4);
    uint32_t h01, h23, l01, l23;
    split4(v, h01, h23, l01, l23);
    *(uint2*)(h + (size_t)i * 4) = make_uint2(h01, h23);
    *(uint2*)(l + (size_t)i * 4) = make_uint2(l01, l23);
}

// ---------------- layernorm -> hi/lo bf16 ----------------
__global__ __launch_bounds__(256)
void layernorm_k(const float* __restrict__ x, const float* __restrict__ gamma,
                 const float* __restrict__ beta,
                 __nv_bfloat16* __restrict__ oh, __nv_bfloat16* __restrict__ ol) {
    int row = blockIdx.x;
    const float* xr = x + (size_t)row * DM;
    int t = threadIdx.x;
    float4 v = *(const float4*)(xr + t * 4);
    float s  = v.x + v.y + v.z + v.w;
    float ss = v.x*v.x + v.y*v.y + v.z*v.z + v.w*v.w;
    #pragma unroll
    for (int o = 16; o > 0; o >>= 1) {
        s  += __shfl_xor_sync(0xffffffffu, s,  o);
        ss += __shfl_xor_sync(0xffffffffu, ss, o);
    }
    __shared__ float rs[8], rss[8];
    int w = t >> 5, l = t & 31;
    if (l == 0) { rs[w] = s; rss[w] = ss; }
    __syncthreads();
    if (w == 0) {
        float a = (l < 8) ? rs[l]  : 0.f;
        float b = (l < 8) ? rss[l] : 0.f;
        #pragma unroll
        for (int o = 4; o > 0; o >>= 1) {
            a += __shfl_xor_sync(0xffffffffu, a, o);
            b += __shfl_xor_sync(0xffffffffu, b, o);
        }
        if (l == 0) { rs[0] = a; rss[0] = b; }
    }
    __syncthreads();
    float mean = rs[0] * (1.0f / DM);
    float var  = rss[0] * (1.0f / DM) - mean * mean;
    float rstd = rsqrtf(var + EPSLN);
    float4 gv = *(const float4*)(gamma + t * 4);
    float4 bv = *(const float4*)(beta  + t * 4);
    float4 o4;
    o4.x = gv.x * ((v.x - mean) * rstd) + bv.x;
    o4.y = gv.y * ((v.y - mean) * rstd) + bv.y;
    o4.z = gv.z * ((v.z - mean) * rstd) + bv.z;
    o4.w = gv.w * ((v.w - mean) * rstd) + bv.w;
    uint32_t h01, h23, l01, l23;
    split4(o4, h01, h23, l01, l23);
    *(uint2*)(oh + (size_t)row * DM + t * 4) = make_uint2(h01, h23);
    *(uint2*)(ol + (size_t)row * DM + t * 4) = make_uint2(l01, l23);
}

// ---------------- bf16-split GEMM NT (3-stage cp.async, 2 CTAs/SM) ----------------
#define GSM (3*32768 + 1024)

template<int EPI, int OUT>
__global__ __launch_bounds__(256, 2)
void gemm_tc(const __nv_bfloat16* __restrict__ Ah_, const __nv_bfloat16* __restrict__ Al_,
             const __nv_bfloat16* __restrict__ Wh_, const __nv_bfloat16* __restrict__ Wl_,
             const float* __restrict__ R, float* __restrict__ Cf,
             __nv_bfloat16* __restrict__ Ch, __nv_bfloat16* __restrict__ Cl,
             int M, int N, int K) {
    extern __shared__ char dsm[];
    uint32_t sb = (smem_u32(dsm) + 1023) & ~1023u;

    int tid = threadIdx.x, wid = tid >> 5, lane = tid & 31;
    int wm = wid >> 2, wn = wid & 3;

    const char* Abh = (const char*)(Ah_ + (size_t)blockIdx.y * 128 * K);
    const char* Abl = (const char*)(Al_ + (size_t)blockIdx.y * 128 * K);
    const char* Wbh = (const char*)(Wh_ + (size_t)blockIdx.x * 128 * K);
    const char* Wbl = (const char*)(Wl_ + (size_t)blockIdx.x * 128 * K);

    int r0 = tid >> 2, gg = tid & 3;
    uint32_t so0 = swz(r0 * 64 + gg * 16);
    uint32_t so1 = swz((r0 + 64) * 64 + gg * 16);
    size_t gb0 = (size_t)r0 * K * 2 + gg * 16;
    size_t gb1 = (size_t)(r0 + 64) * K * 2 + gg * 16;

    #define G_ISSUE(kb, st) do { \
        uint32_t s_ = sb + (st) * 32768; \
        size_t kbb = (size_t)(kb) * 2; \
        CPA(s_ + so0,         Abh + gb0 + kbb); \
        CPA(s_ + so1,         Abh + gb1 + kbb); \
        CPA(s_ + 8192  + so0, Abl + gb0 + kbb); \
        CPA(s_ + 8192  + so1, Abl + gb1 + kbb); \
        CPA(s_ + 16384 + so0, Wbh + gb0 + kbb); \
        CPA(s_ + 16384 + so1, Wbh + gb1 + kbb); \
        CPA(s_ + 24576 + so0, Wbl + gb0 + kbb); \
        CPA(s_ + 24576 + so1, Wbl + gb1 + kbb); \
    } while (0)

    float acc[4][4][4];
    #pragma unroll
    for (int i = 0; i < 4; i++)
        #pragma unroll
        for (int j = 0; j < 4; j++)
            #pragma unroll
            for (int e = 0; e < 4; e++) acc[i][j][e] = 0.f;

    int g = lane >> 3, rg = lane & 7;
    int nch = K >> 5;

    G_ISSUE(0, 0);
    asm volatile("cp.async.commit_group;");
    G_ISSUE(32, 1);
    asm volatile("cp.async.commit_group;");

    int st_c = 0, st_i = 2;
    for (int ch = 0; ch < nch; ch++) {
        if (ch + 1 < nch) asm volatile("cp.async.wait_group 1;" ::: "memory");
        else              asm volatile("cp.async.wait_group 0;" ::: "memory");
        __syncthreads();
        if (ch + 2 < nch) {
            G_ISSUE((ch + 2) << 5, st_i);
            asm volatile("cp.async.commit_group;");
            st_i = (st_i == 2) ? 0 : st_i + 1;
        }
        uint32_t ah = sb + st_c * 32768;
        st_c = (st_c == 2) ? 0 : st_c + 1;
        uint32_t al = ah + 8192, bh = ah + 16384, bl = ah + 24576;

        #pragma unroll
        for (int ks = 0; ks < 2; ks++) {
            int kseg = ks * 2 + (g >> 1);
            uint32_t bhr[2][4], blr[2][4];
            #pragma unroll
            for (int p = 0; p < 2; p++) {
                int nrow = wn * 32 + p * 16 + (g & 1) * 8 + rg;
                uint32_t off = swz(nrow * 64 + kseg * 16);
                ldsm_x4(bh + off, bhr[p][0], bhr[p][1], bhr[p][2], bhr[p][3]);
                ldsm_x4(bl + off, blr[p][0], blr[p][1], blr[p][2], blr[p][3]);
            }
            #pragma unroll
            for (int mf = 0; mf < 4; mf++) {
                int arow = wm * 64 + mf * 16 + (g & 1) * 8 + rg;
                uint32_t off = swz(arow * 64 + kseg * 16);
                uint32_t a0,a1,a2,a3, x0,x1,x2,x3;
                ldsm_x4(ah + off, a0, a1, a2, a3);
                ldsm_x4(al + off, x0, x1, x2, x3);
                #pragma unroll
                for (int nf = 0; nf < 4; nf++) {
                    int p = nf >> 1, q = nf & 1;
                    uint32_t bb0 = bhr[p][q], bb1 = bhr[p][q + 2];
                    uint32_t cb0 = blr[p][q], cb1 = blr[p][q + 2];
                    mma_bf16(acc[mf][nf], a0, a1, a2, a3, bb0, bb1);
                    mma_bf16(acc[mf][nf], a0, a1, a2, a3, cb0, cb1);
                    mma_bf16(acc[mf][nf], x0, x1, x2, x3, bb0, bb1);
                }
            }
        }
    }

    #pragma unroll
    for (int mf = 0; mf < 4; mf++) {
        #pragma unroll
        for (int h = 0; h < 2; h++) {
            size_t row = (size_t)blockIdx.y * 128 + wm * 64 + mf * 16 + (lane >> 2) + h * 8;
            #pragma unroll
            for (int nf = 0; nf < 4; nf++) {
                size_t col = (size_t)blockIdx.x * 128 + wn * 32 + nf * 8 + (lane & 3) * 2;
                float o0 = acc[mf][nf][h * 2 + 0];
                float o1 = acc[mf][nf][h * 2 + 1];
                if (EPI == 1) {
                    float2 r2 = *(const float2*)(R + row * N + col);
                    o0 += r2.x; o1 += r2.y;
                }
                if (EPI == 2) { o0 = gelu_f(o0); o1 = gelu_f(o1); }
                if (OUT == 0) {
                    *(float2*)(Cf + row * N + col) = make_float2(o0, o1);
                } else {
                    uint32_t hh, ll;
                    split2(o0, o1, hh, ll);
                    *(uint32_t*)(Ch + row * N + col) = hh;
                    *(uint32_t*)(Cl + row * N + col) = ll;
                }
            }
        }
    }
}

// ---------------- tensor-core flash attention (3-stage KV, causal) ----------------
#define ASM (16384 + 3*32768 + 1024)

__global__ __launch_bounds__(128)
void flash_attn_tc(const __nv_bfloat16* __restrict__ QKVh,
                   const __nv_bfloat16* __restrict__ QKVl,
                   __nv_bfloat16* __restrict__ Oh, __nv_bfloat16* __restrict__ Ol) {
    extern __shared__ char dsm[];
    uint32_t sb = (smem_u32(dsm) + 1023) & ~1023u;
    uint32_t sQh = sb, sQl = sb + 8192;

    int qt = gridDim.x - 1 - blockIdx.x;
    int bh = blockIdx.y;
    int b = bh >> 4, h = bh & 15;
    int tid = threadIdx.x, w = tid >> 5, lane = tid & 31;
    int g = lane >> 3, rg = lane & 7;
    int qstart = qt * 64;

    const char* Qhc = (const char*)QKVh;  const char* Qlc = (const char*)QKVl;

    size_t qg = ((size_t)(b * SEQ + qstart)) * QKVS + h * 64;
    #pragma unroll
    for (int i = 0; i < 4; i++) {
        int seg = tid + i * 128;
        int row = seg >> 3, cs = seg & 7;
        uint32_t so = swz128(row * 128 + cs * 16);
        size_t gb = (qg + (size_t)row * QKVS + cs * 8) * 2;
        CPA(sQh + so, Qhc + gb);
        CPA(sQl + so, Qlc + gb);
    }

    #define AKV_ISSUE(kbase, st) do { \
        uint32_t s_ = sb + 16384 + (st) * 32768; \
        size_t g0 = ((size_t)(b * SEQ + (kbase))) * QKVS + 1024 + h * 64; \
        _Pragma("unroll") \
        for (int i_ = 0; i_ < 4; i_++) { \
            int seg_ = tid + i_ * 128; \
            int row_ = seg_ >> 3, cs_ = seg_ & 7; \
            uint32_t so_ = swz128(row_ * 128 + cs_ * 16); \
            size_t gb_ = (g0 + (size_t)row_ * QKVS + cs_ * 8) * 2; \
            CPA(s_ + so_,          Qhc + gb_); \
            CPA(s_ + 8192  + so_,  Qlc + gb_); \
            CPA(s_ + 16384 + so_,  Qhc + gb_ + 2048); \
            CPA(s_ + 24576 + so_,  Qlc + gb_ + 2048); \
        } \
    } while (0)

    AKV_ISSUE(0, 0);
    asm volatile("cp.async.commit_group;");
    if (qt >= 1) {
        AKV_ISSUE(64, 1);
        asm volatile("cp.async.commit_group;");
    }

    float s[8][4], o[8][4];
    uint32_t qfh[4][4], qfl[4][4];
    #pragma unroll
    for (int nf = 0; nf < 8; nf++)
        #pragma unroll
        for (int e = 0; e < 4; e++) o[nf][e] = 0.f;
    float m0 = -1e30f, m1 = -1e30f, l0 = 0.f, l1 = 0.f;

    int st_c = 0, st_i = 2;
    for (int kb = 0; kb <= qt; kb++) {
        if (kb < qt) asm volatile("cp.async.wait_group 1;" ::: "memory");
        else         asm volatile("cp.async.wait_group 0;" ::: "memory");
        __syncthreads();
        if (kb + 2 <= qt) {
            AKV_ISSUE((kb + 2) * 64, st_i);
            asm volatile("cp.async.commit_group;");
            st_i = (st_i == 2) ? 0 : st_i + 1;
        }

        if (kb == 0) {
            #pragma unroll
            for (int kseg = 0; kseg < 4; kseg++) {
                int arow = w * 16 + (g & 1) * 8 + rg;
                uint32_t off = swz128(arow * 128 + kseg * 32 + (g >> 1) * 16);
                ldsm_x4(sQh + off, qfh[kseg][0], qfh[kseg][1], qfh[kseg][2], qfh[kseg][3]);
                ldsm_x4(sQl + off, qfl[kseg][0], qfl[kseg][1], qfl[kseg][2], qfl[kseg][3]);
            }
        }

        uint32_t kB = sb + 16384 + st_c * 32768;
        st_c = (st_c == 2) ? 0 : st_c + 1;
        uint32_t sKh = kB, sKl = kB + 8192, sVh = kB + 16384, sVl = kB + 24576;

        #pragma unroll
        for (int nf = 0; nf < 8; nf++)
            #pragma unroll
            for (int e = 0; e < 4; e++) s[nf][e] = 0.f;
        #pragma unroll
        for (int kseg = 0; kseg < 4; kseg++) {
            uint32_t kh[4][4], kl[4][4];
            int kcol = kseg * 32 + (g >> 1) * 16;
            #pragma unroll
            for (int p = 0; p < 4; p++) {
                int nrow = p * 16 + (g & 1) * 8 + rg;
                uint32_t off = swz128(nrow * 128 + kcol);
                ldsm_x4(sKh + off, kh[p][0], kh[p][1], kh[p][2], kh[p][3]);
                ldsm_x4(sKl + off, kl[p][0], kl[p][1], kl[p][2], kl[p][3]);
            }
            #pragma unroll
            for (int p = 0; p < 4; p++)
                #pragma unroll
                for (int q = 0; q < 2; q++) {
                    int nf = 2 * p + q;
                    mma_bf16(s[nf], qfh[kseg][0], qfh[kseg][1], qfh[kseg][2], qfh[kseg][3],
                             kh[p][q], kh[p][q + 2]);
                    mma_bf16(s[nf], qfh[kseg][0], qfh[kseg][1], qfh[kseg][2], qfh[kseg][3],
                             kl[p][q], kl[p][q + 2]);
                    mma_bf16(s[nf], qfl[kseg][0], qfl[kseg][1], qfl[kseg][2], qfl[kseg][3],
                             kh[p][q], kh[p][q + 2]);
                }
        }

        if (kb == qt) {
            int r0 = w * 16 + (lane >> 2);
            int c0 = (lane & 3) * 2;
            #pragma unroll
            for (int nf = 0; nf < 8; nf++) {
                int c = c0 + nf * 8;
                if (c     > r0)     s[nf][0] = -1e30f;
                if (c + 1 > r0)     s[nf][1] = -1e30f;
                if (c     > r0 + 8) s[nf][2] = -1e30f;
                if (c + 1 > r0 + 8) s[nf][3] = -1e30f;
            }
        }

        float mr0 = -1e30f, mr1 = -1e30f;
        #pragma unroll
        for (int nf = 0; nf < 8; nf++) {
            mr0 = fmaxf(mr0, fmaxf(s[nf][0], s[nf][1]));
            mr1 = fmaxf(mr1, fmaxf(s[nf][2], s[nf][3]));
        }
        mr0 = fmaxf(mr0, __shfl_xor_sync(0xffffffffu, mr0, 1));
        mr0 = fmaxf(mr0, __shfl_xor_sync(0xffffffffu, mr0, 2));
        mr1 = fmaxf(mr1, __shfl_xor_sync(0xffffffffu, mr1, 1));
        mr1 = fmaxf(mr1, __shfl_xor_sync(0xffffffffu, mr1, 2));
        float mn0 = fmaxf(m0, mr0), mn1 = fmaxf(m1, mr1);
        float f0 = exp2p((m0 - mn0) * CEXP);
        float f1 = exp2p((m1 - mn1) * CEXP);
        l0 *= f0; l1 *= f1;
        #pragma unroll
        for (int nf = 0; nf < 8; nf++) {
            o[nf][0] *= f0; o[nf][1] *= f0; o[nf][2] *= f1; o[nf][3] *= f1;
        }
        m0 = mn0; m1 = mn1;
        #pragma unroll
        for (int nf = 0; nf < 8; nf++) {
            s[nf][0] = exp2p((s[nf][0] - m0) * CEXP);
            s[nf][1] = exp2p((s[nf][1] - m0) * CEXP);
            s[nf][2] = exp2p((s[nf][2] - m1) * CEXP);
            s[nf][3] = exp2p((s[nf][3] - m1) * CEXP);
            l0 += s[nf][0] + s[nf][1];
            l1 += s[nf][2] + s[nf][3];
        }

        #pragma unroll
        for (int kk = 0; kk < 4; kk++) {
            uint32_t ah0, ah1, ah2, ah3, al0, al1, al2, al3;
            split2(s[2*kk][0],   s[2*kk][1],   ah0, al0);
            split2(s[2*kk][2],   s[2*kk][3],   ah1, al1);
            split2(s[2*kk+1][0], s[2*kk+1][1], ah2, al2);
            split2(s[2*kk+1][2], s[2*kk+1][3], ah3, al3);
            int vrow = kk * 16 + (g >> 1) * 8 + rg;
            #pragma unroll
            for (int ep = 0; ep < 4; ep++) {
                int ecol = ep * 16 + (g & 1) * 8;
                uint32_t off = swz128(vrow * 128 + ecol * 2);
                uint32_t vh[4], vl[4];
                ldsm_x4t(sVh + off, vh);
                ldsm_x4t(sVl + off, vl);
                mma_bf16(o[2*ep],   ah0, ah1, ah2, ah3, vh[0], vh[2]);
                mma_bf16(o[2*ep+1], ah0, ah1, ah2, ah3, vh[1], vh[3]);
                mma_bf16(o[2*ep],   al0, al1, al2, al3, vh[0], vh[2]);
                mma_bf16(o[2*ep+1], al0, al1, al2, al3, vh[1], vh[3]);
                mma_bf16(o[2*ep],   ah0, ah1, ah2, ah3, vl[0], vl[2]);
                mma_bf16(o[2*ep+1], ah0, ah1, ah2, ah3, vl[1], vl[3]);
            }
        }
    }

    l0 += __shfl_xor_sync(0xffffffffu, l0, 1);
    l0 += __shfl_xor_sync(0xffffffffu, l0, 2);
    l1 += __shfl_xor_sync(0xffffffffu, l1, 1);
    l1 += __shfl_xor_sync(0xffffffffu, l1, 2);
    float rl0 = 1.0f / l0, rl1 = 1.0f / l1;
    int row0 = qstart + w * 16 + (lane >> 2);
    size_t ob0 = ((size_t)(b * SEQ + row0)) * DM + h * 64;
    size_t ob1 = ob0 + (size_t)8 * DM;
    #pragma unroll
    for (int nf = 0; nf < 8; nf++) {
        int e = nf * 8 + (lane & 3) * 2;
        uint32_t hh, ll;
        split2(o[nf][0] * rl0, o[nf][1] * rl0, hh, ll);
        *(uint32_t*)(Oh + ob0 + e) = hh;
        *(uint32_t*)(Ol + ob0 + e) = ll;
        split2(o[nf][2] * rl1, o[nf][3] * rl1, hh, ll);
        *(uint32_t*)(Oh + ob1 + e) = hh;
        *(uint32_t*)(Ol + ob1 + e) = ll;
    }
}

// ---------------- launch ----------------
extern "C" void kernel_launch(void* const* d_in, const int* in_sizes, int n_in,
                              void* d_out, int out_size) {
    const float* x      = (const float*)d_in[0];
    const float* gamma1 = (const float*)d_in[1];
    const float* beta1  = (const float*)d_in[2];
    const float* wq     = (const float*)d_in[3];
    const float* wk     = (const float*)d_in[4];
    const float* wv     = (const float*)d_in[5];
    const float* wo     = (const float*)d_in[6];
    const float* gamma2 = (const float*)d_in[7];
    const float* beta2  = (const float*)d_in[8];
    const float* fc1    = (const float*)d_in[9];
    const float* fc2    = (const float*)d_in[10];
    float* out = (float*)d_out;

    float *resid_;
    __nv_bfloat16 *nh_, *nl_, *qkvh_, *qkvl_, *ah_, *al_, *hh_, *hl_, *wh_, *wl_;
    cudaGetSymbolAddress((void**)&resid_, g_resid);
    cudaGetSymbolAddress((void**)&nh_, g_nh);     cudaGetSymbolAddress((void**)&nl_, g_nl);
    cudaGetSymbolAddress((void**)&qkvh_, g_qkvh); cudaGetSymbolAddress((void**)&qkvl_, g_qkvl);
    cudaGetSymbolAddress((void**)&ah_, g_ah);     cudaGetSymbolAddress((void**)&al_, g_al);
    cudaGetSymbolAddress((void**)&hh_, g_hh);     cudaGetSymbolAddress((void**)&hl_, g_hl);
    cudaGetSymbolAddress((void**)&wh_, g_wh);     cudaGetSymbolAddress((void**)&wl_, g_wl);

    cudaFuncSetAttribute(gemm_tc<0,2>, cudaFuncAttributeMaxDynamicSharedMemorySize, GSM);
    cudaFuncSetAttribute(gemm_tc<1,0>, cudaFuncAttributeMaxDynamicSharedMemorySize, GSM);
    cudaFuncSetAttribute(gemm_tc<2,2>, cudaFuncAttributeMaxDynamicSharedMemorySize, GSM);
    cudaFuncSetAttribute(flash_attn_tc, cudaFuncAttributeMaxDynamicSharedMemorySize, ASM);

    const int nQ = DM * DM / 4, nF = DFF * DM / 4;
    conv_hl<<<(nQ + 255) / 256, 256>>>(wq,  wh_ + WOFF_Q,  wl_ + WOFF_Q,  nQ);
    conv_hl<<<(nQ + 255) / 256, 256>>>(wk,  wh_ + WOFF_K,  wl_ + WOFF_K,  nQ);
    conv_hl<<<(nQ + 255) / 256, 256>>>(wv,  wh_ + WOFF_V,  wl_ + WOFF_V,  nQ);
    conv_hl<<<(nQ + 255) / 256, 256>>>(wo,  wh_ + WOFF_O,  wl_ + WOFF_O,  nQ);
    conv_hl<<<(nF + 255) / 256, 256>>>(fc1, wh_ + WOFF_F1, wl_ + WOFF_F1, nF);
    conv_hl<<<(nF + 255) / 256, 256>>>(fc2, wh_ + WOFF_F2, wl_ + WOFF_F2, nF);

    dim3 gQKV(QKVS / 128, BS / 128);
    dim3 gProj(DM / 128, BS / 128);
    dim3 gFF1(DFF / 128, BS / 128);
    dim3 gFF2(DM / 128, BS / 128);
    dim3 gAttn(SEQ / 64, BATCH * NH);

    layernorm_k<<<BS, 256>>>(x, gamma1, beta1, nh_, nl_);
    gemm_tc<0,2><<<gQKV, 256, GSM>>>(nh_, nl_, wh_ + WOFF_Q, wl_ + WOFF_Q,
                                     nullptr, nullptr, qkvh_, qkvl_, BS, QKVS, DM);
    flash_attn_tc<<<gAttn, 128, ASM>>>(qkvh_, qkvl_, ah_, al_);
    gemm_tc<1,0><<<gProj, 256, GSM>>>(ah_, al_, wh_ + WOFF_O, wl_ + WOFF_O,
                                      x, resid_, nullptr, nullptr, BS, DM, DM);
    layernorm_k<<<BS, 256>>>(resid_, gamma2, beta2, nh_, nl_);
    gemm_tc<2,2><<<gFF1, 256, GSM>>>(nh_, nl_, wh_ + WOFF_F1, wl_ + WOFF_F1,
                                     nullptr, nullptr, hh_, hl_, BS, DFF, DM);
    gemm_tc<1,0><<<gFF2, 256, GSM>>>(hh_, hl_, wh_ + WOFF_F2, wl_ + WOFF_F2,
                                     resid_, out, nullptr, nullptr, BS, DM, DFF);
}

// round 9
// speedup vs baseline: 9.2125x; 2.3860x over previous
#include <cuda_runtime.h>
#include <cuda_fp16.h>
#include <math.h>
#include <stdint.h>

#define BATCH 4
#define SEQ   2048
#define DM    1024
#define NH    16
#define DH    64
#define DFF   4096
#define BS    (BATCH*SEQ)
#define QKVS  3072
#define EPSLN 1e-5f
#define CEXP  0.1803368801f   // log2(e)/8

// ---------------- scratch (fp16 single precision operands) ----------------
__device__ float g_resid[(size_t)BS*DM];
__device__ __half g_n[(size_t)BS*DM];
__device__ __half g_qkv[(size_t)BS*QKVS];
__device__ __half g_a[(size_t)BS*DM];
__device__ __half g_h[(size_t)BS*DFF];
#define WOFF_Q  ((size_t)0)
#define WOFF_K  ((size_t)DM*DM)
#define WOFF_V  ((size_t)2*DM*DM)
#define WOFF_O  ((size_t)3*DM*DM)
#define WOFF_F1 ((size_t)4*DM*DM)
#define WOFF_F2 ((size_t)(4*DM*DM) + (size_t)DFF*DM)
__device__ __half g_w[(size_t)4*DM*DM + 2*(size_t)DFF*DM];

// ---------------- helpers ----------------
__device__ __forceinline__ uint32_t smem_u32(const void* p) {
    uint32_t a;
    asm("{ .reg .u64 t; cvta.to.shared.u64 t, %1; cvt.u32.u64 %0, t; }" : "=r"(a) : "l"(p));
    return a;
}
__device__ __forceinline__ uint32_t swz(uint32_t off)    { return off ^ ((off >> 3) & 0x30); }
__device__ __forceinline__ uint32_t swz128(uint32_t off) { return off ^ ((off >> 3) & 0x70); }

__device__ __forceinline__ void ldsm_x4(uint32_t addr, uint32_t& r0, uint32_t& r1,
                                        uint32_t& r2, uint32_t& r3) {
    asm volatile("ldmatrix.sync.aligned.m8n8.x4.shared.b16 {%0,%1,%2,%3}, [%4];"
                 : "=r"(r0), "=r"(r1), "=r"(r2), "=r"(r3) : "r"(addr));
}
__device__ __forceinline__ void ldsm_x4t(uint32_t addr, uint32_t* r) {
    asm volatile("ldmatrix.sync.aligned.m8n8.x4.trans.shared.b16 {%0,%1,%2,%3}, [%4];"
                 : "=r"(r[0]), "=r"(r[1]), "=r"(r[2]), "=r"(r[3]) : "r"(addr));
}
__device__ __forceinline__ void mma_f16(float* d, uint32_t a0, uint32_t a1,
                                        uint32_t a2, uint32_t a3,
                                        uint32_t b0, uint32_t b1) {
    asm volatile("mma.sync.aligned.m16n8k16.row.col.f32.f16.f16.f32 "
                 "{%0,%1,%2,%3}, {%4,%5,%6,%7}, {%8,%9}, {%0,%1,%2,%3};"
                 : "+f"(d[0]), "+f"(d[1]), "+f"(d[2]), "+f"(d[3])
                 : "r"(a0), "r"(a1), "r"(a2), "r"(a3), "r"(b0), "r"(b1));
}
#define CPA(dst, src) asm volatile("cp.async.cg.shared.global [%0], [%1], 16;" :: "r"(dst), "l"(src))

__device__ __forceinline__ float gelu_f(float x) {
    float c = x * x * x;
    float t = tanhf(0.7978845608f * (x + 0.044715f * c));
    return 0.5f * x * (1.0f + t);
}
__device__ __forceinline__ uint32_t packh2(float x, float y) {
    __half2 h = __floats2half2_rn(x, y);
    return *reinterpret_cast<uint32_t*>(&h);
}
__device__ __forceinline__ float exp2p(float x) {
    x = fmaxf(x, -60.0f);
    float y = x + 12582912.0f;
    int   n = __float_as_int(y) - 0x4B400000;
    float f = x - (y - 12582912.0f);
    float p =            1.3333558e-3f;
    p = fmaf(p, f, 9.6181291e-3f);
    p = fmaf(p, f, 5.5504109e-2f);
    p = fmaf(p, f, 2.4022651e-1f);
    p = fmaf(p, f, 6.9314718e-1f);
    p = fmaf(p, f, 1.0f);
    return __uint_as_float(__float_as_uint(p) + ((uint32_t)n << 23));
}

// ---------------- weight convert: f32 -> f16 ----------------
__global__ __launch_bounds__(256)
void conv_f16(const float* __restrict__ s, __half* __restrict__ h, int n4) {
    int i = blockIdx.x * 256 + threadIdx.x;
    if (i >= n4) return;
    float4 v = *(const float4*)(s + (size_t)i * 4);
    uint2 o;
    o.x = packh2(v.x, v.y);
    o.y = packh2(v.z, v.w);
    *(uint2*)(h + (size_t)i * 4) = o;
}

// ---------------- layernorm -> f16 ----------------
__global__ __launch_bounds__(256)
void layernorm_k(const float* __restrict__ x, const float* __restrict__ gamma,
                 const float* __restrict__ beta, __half* __restrict__ oh) {
    int row = blockIdx.x;
    const float* xr = x + (size_t)row * DM;
    int t = threadIdx.x;
    float4 v = *(const float4*)(xr + t * 4);
    float s  = v.x + v.y + v.z + v.w;
    float ss = v.x*v.x + v.y*v.y + v.z*v.z + v.w*v.w;
    #pragma unroll
    for (int o = 16; o > 0; o >>= 1) {
        s  += __shfl_xor_sync(0xffffffffu, s,  o);
        ss += __shfl_xor_sync(0xffffffffu, ss, o);
    }
    __shared__ float rs[8], rss[8];
    int w = t >> 5, l = t & 31;
    if (l == 0) { rs[w] = s; rss[w] = ss; }
    __syncthreads();
    if (w == 0) {
        float a = (l < 8) ? rs[l]  : 0.f;
        float b = (l < 8) ? rss[l] : 0.f;
        #pragma unroll
        for (int o = 4; o > 0; o >>= 1) {
            a += __shfl_xor_sync(0xffffffffu, a, o);
            b += __shfl_xor_sync(0xffffffffu, b, o);
        }
        if (l == 0) { rs[0] = a; rss[0] = b; }
    }
    __syncthreads();
    float mean = rs[0] * (1.0f / DM);
    float var  = rss[0] * (1.0f / DM) - mean * mean;
    float rstd = rsqrtf(var + EPSLN);
    float4 gv = *(const float4*)(gamma + t * 4);
    float4 bv = *(const float4*)(beta  + t * 4);
    uint2 o2;
    o2.x = packh2(gv.x * ((v.x - mean) * rstd) + bv.x,
                  gv.y * ((v.y - mean) * rstd) + bv.y);
    o2.y = packh2(gv.z * ((v.z - mean) * rstd) + bv.z,
                  gv.w * ((v.w - mean) * rstd) + bv.w);
    *(uint2*)(oh + (size_t)row * DM + t * 4) = o2;
}

// ---------------- fp16 GEMM NT (3-stage cp.async) ----------------
// C = A @ W^T, A/W fp16 [rows,K], fp32 accum. 128x128x32 tile, 8 warps.
// EPI: 0 none, 1 +R, 2 gelu.  OUT: 0 f32, 2 f16.
#define GSM (3*16384 + 1024)

template<int EPI, int OUT>
__global__ __launch_bounds__(256, 2)
void gemm_tc(const __half* __restrict__ A_, const __half* __restrict__ W_,
             const float* __restrict__ R, float* __restrict__ Cf,
             __half* __restrict__ Ch, int M, int N, int K) {
    extern __shared__ char dsm[];
    uint32_t sb = (smem_u32(dsm) + 1023) & ~1023u;

    int tid = threadIdx.x, wid = tid >> 5, lane = tid & 31;
    int wm = wid >> 2, wn = wid & 3;

    const char* Ab = (const char*)(A_ + (size_t)blockIdx.y * 128 * K);
    const char* Wb = (const char*)(W_ + (size_t)blockIdx.x * 128 * K);

    int r0 = tid >> 2, gg = tid & 3;
    uint32_t so0 = swz(r0 * 64 + gg * 16);
    uint32_t so1 = swz((r0 + 64) * 64 + gg * 16);
    size_t gb0 = (size_t)r0 * K * 2 + gg * 16;
    size_t gb1 = (size_t)(r0 + 64) * K * 2 + gg * 16;

    #define G_ISSUE(kb, st) do { \
        uint32_t s_ = sb + (st) * 16384; \
        size_t kbb = (size_t)(kb) * 2; \
        CPA(s_ + so0,        Ab + gb0 + kbb); \
        CPA(s_ + so1,        Ab + gb1 + kbb); \
        CPA(s_ + 8192 + so0, Wb + gb0 + kbb); \
        CPA(s_ + 8192 + so1, Wb + gb1 + kbb); \
    } while (0)

    float acc[4][4][4];
    #pragma unroll
    for (int i = 0; i < 4; i++)
        #pragma unroll
        for (int j = 0; j < 4; j++)
            #pragma unroll
            for (int e = 0; e < 4; e++) acc[i][j][e] = 0.f;

    int g = lane >> 3, rg = lane & 7;
    int nch = K >> 5;

    G_ISSUE(0, 0);
    asm volatile("cp.async.commit_group;");
    G_ISSUE(32, 1);
    asm volatile("cp.async.commit_group;");

    int st_c = 0, st_i = 2;
    for (int ch = 0; ch < nch; ch++) {
        if (ch + 1 < nch) asm volatile("cp.async.wait_group 1;" ::: "memory");
        else              asm volatile("cp.async.wait_group 0;" ::: "memory");
        __syncthreads();
        if (ch + 2 < nch) {
            G_ISSUE((ch + 2) << 5, st_i);
            asm volatile("cp.async.commit_group;");
            st_i = (st_i == 2) ? 0 : st_i + 1;
        }
        uint32_t ah = sb + st_c * 16384;
        st_c = (st_c == 2) ? 0 : st_c + 1;
        uint32_t bh = ah + 8192;

        #pragma unroll
        for (int ks = 0; ks < 2; ks++) {
            int kseg = ks * 2 + (g >> 1);
            uint32_t bhr[2][4];
            #pragma unroll
            for (int p = 0; p < 2; p++) {
                int nrow = wn * 32 + p * 16 + (g & 1) * 8 + rg;
                uint32_t off = swz(nrow * 64 + kseg * 16);
                ldsm_x4(bh + off, bhr[p][0], bhr[p][1], bhr[p][2], bhr[p][3]);
            }
            #pragma unroll
            for (int mf = 0; mf < 4; mf++) {
                int arow = wm * 64 + mf * 16 + (g & 1) * 8 + rg;
                uint32_t off = swz(arow * 64 + kseg * 16);
                uint32_t a0,a1,a2,a3;
                ldsm_x4(ah + off, a0, a1, a2, a3);
                #pragma unroll
                for (int nf = 0; nf < 4; nf++) {
                    int p = nf >> 1, q = nf & 1;
                    mma_f16(acc[mf][nf], a0, a1, a2, a3, bhr[p][q], bhr[p][q + 2]);
                }
            }
        }
    }

    #pragma unroll
    for (int mf = 0; mf < 4; mf++) {
        #pragma unroll
        for (int h = 0; h < 2; h++) {
            size_t row = (size_t)blockIdx.y * 128 + wm * 64 + mf * 16 + (lane >> 2) + h * 8;
            #pragma unroll
            for (int nf = 0; nf < 4; nf++) {
                size_t col = (size_t)blockIdx.x * 128 + wn * 32 + nf * 8 + (lane & 3) * 2;
                float o0 = acc[mf][nf][h * 2 + 0];
                float o1 = acc[mf][nf][h * 2 + 1];
                if (EPI == 1) {
                    float2 r2 = *(const float2*)(R + row * N + col);
                    o0 += r2.x; o1 += r2.y;
                }
                if (EPI == 2) { o0 = gelu_f(o0); o1 = gelu_f(o1); }
                if (OUT == 0) {
                    *(float2*)(Cf + row * N + col) = make_float2(o0, o1);
                } else {
                    *(uint32_t*)(Ch + row * N + col) = packh2(o0, o1);
                }
            }
        }
    }
}

// ---------------- fp16 tensor-core flash attention (3-stage KV, causal) ----------------
// QKV packed [BS, 3072]: q@0, k@1024, v@2048 (+h*64).
#define ASM (8192 + 3*16384 + 1024)

__global__ __launch_bounds__(128)
void flash_attn_tc(const __half* __restrict__ QKV, __half* __restrict__ O) {
    extern __shared__ char dsm[];
    uint32_t sb = (smem_u32(dsm) + 1023) & ~1023u;
    uint32_t sQ = sb;

    int qt = gridDim.x - 1 - blockIdx.x;
    int bh = blockIdx.y;
    int b = bh >> 4, h = bh & 15;
    int tid = threadIdx.x, w = tid >> 5, lane = tid & 31;
    int g = lane >> 3, rg = lane & 7;
    int qstart = qt * 64;

    const char* Qc = (const char*)QKV;

    size_t qg = ((size_t)(b * SEQ + qstart)) * QKVS + h * 64;
    #pragma unroll
    for (int i = 0; i < 4; i++) {
        int seg = tid + i * 128;
        int row = seg >> 3, cs = seg & 7;
        uint32_t so = swz128(row * 128 + cs * 16);
        size_t gb = (qg + (size_t)row * QKVS + cs * 8) * 2;
        CPA(sQ + so, Qc + gb);
    }

    #define AKV_ISSUE(kbase, st) do { \
        uint32_t s_ = sb + 8192 + (st) * 16384; \
        size_t g0 = ((size_t)(b * SEQ + (kbase))) * QKVS + 1024 + h * 64; \
        _Pragma("unroll") \
        for (int i_ = 0; i_ < 4; i_++) { \
            int seg_ = tid + i_ * 128; \
            int row_ = seg_ >> 3, cs_ = seg_ & 7; \
            uint32_t so_ = swz128(row_ * 128 + cs_ * 16); \
            size_t gb_ = (g0 + (size_t)row_ * QKVS + cs_ * 8) * 2; \
            CPA(s_ + so_,        Qc + gb_); \
            CPA(s_ + 8192 + so_, Qc + gb_ + 2048); \
        } \
    } while (0)

    AKV_ISSUE(0, 0);
    asm volatile("cp.async.commit_group;");
    if (qt >= 1) {
        AKV_ISSUE(64, 1);
        asm volatile("cp.async.commit_group;");
    }

    float s[8][4], o[8][4];
    uint32_t qf[4][4];
    #pragma unroll
    for (int nf = 0; nf < 8; nf++)
        #pragma unroll
        for (int e = 0; e < 4; e++) o[nf][e] = 0.f;
    float m0 = -1e30f, m1 = -1e30f, l0 = 0.f, l1 = 0.f;

    int st_c = 0, st_i = 2;
    for (int kb = 0; kb <= qt; kb++) {
        if (kb < qt) asm volatile("cp.async.wait_group 1;" ::: "memory");
        else         asm volatile("cp.async.wait_group 0;" ::: "memory");
        __syncthreads();
        if (kb + 2 <= qt) {
            AKV_ISSUE((kb + 2) * 64, st_i);
            asm volatile("cp.async.commit_group;");
            st_i = (st_i == 2) ? 0 : st_i + 1;
        }

        if (kb == 0) {
            #pragma unroll
            for (int kseg = 0; kseg < 4; kseg++) {
                int arow = w * 16 + (g & 1) * 8 + rg;
                uint32_t off = swz128(arow * 128 + kseg * 32 + (g >> 1) * 16);
                ldsm_x4(sQ + off, qf[kseg][0], qf[kseg][1], qf[kseg][2], qf[kseg][3]);
            }
        }

        uint32_t kB = sb + 8192 + st_c * 16384;
        st_c = (st_c == 2) ? 0 : st_c + 1;
        uint32_t sK = kB, sV = kB + 8192;

        // ---- S = Q K^T ----
        #pragma unroll
        for (int nf = 0; nf < 8; nf++)
            #pragma unroll
            for (int e = 0; e < 4; e++) s[nf][e] = 0.f;
        #pragma unroll
        for (int kseg = 0; kseg < 4; kseg++) {
            uint32_t kh[4][4];
            int kcol = kseg * 32 + (g >> 1) * 16;
            #pragma unroll
            for (int p = 0; p < 4; p++) {
                int nrow = p * 16 + (g & 1) * 8 + rg;
                uint32_t off = swz128(nrow * 128 + kcol);
                ldsm_x4(sK + off, kh[p][0], kh[p][1], kh[p][2], kh[p][3]);
            }
            #pragma unroll
            for (int p = 0; p < 4; p++)
                #pragma unroll
                for (int q = 0; q < 2; q++)
                    mma_f16(s[2*p+q], qf[kseg][0], qf[kseg][1], qf[kseg][2], qf[kseg][3],
                            kh[p][q], kh[p][q + 2]);
        }

        if (kb == qt) {
            int r0 = w * 16 + (lane >> 2);
            int c0 = (lane & 3) * 2;
            #pragma unroll
            for (int nf = 0; nf < 8; nf++) {
                int c = c0 + nf * 8;
                if (c     > r0)     s[nf][0] = -1e30f;
                if (c + 1 > r0)     s[nf][1] = -1e30f;
                if (c     > r0 + 8) s[nf][2] = -1e30f;
                if (c + 1 > r0 + 8) s[nf][3] = -1e30f;
            }
        }

        // ---- online softmax ----
        float mr0 = -1e30f, mr1 = -1e30f;
        #pragma unroll
        for (int nf = 0; nf < 8; nf++) {
            mr0 = fmaxf(mr0, fmaxf(s[nf][0], s[nf][1]));
            mr1 = fmaxf(mr1, fmaxf(s[nf][2], s[nf][3]));
        }
        mr0 = fmaxf(mr0, __shfl_xor_sync(0xffffffffu, mr0, 1));
        mr0 = fmaxf(mr0, __shfl_xor_sync(0xffffffffu, mr0, 2));
        mr1 = fmaxf(mr1, __shfl_xor_sync(0xffffffffu, mr1, 1));
        mr1 = fmaxf(mr1, __shfl_xor_sync(0xffffffffu, mr1, 2));
        float mn0 = fmaxf(m0, mr0), mn1 = fmaxf(m1, mr1);
        float f0 = exp2p((m0 - mn0) * CEXP);
        float f1 = exp2p((m1 - mn1) * CEXP);
        l0 *= f0; l1 *= f1;
        #pragma unroll
        for (int nf = 0; nf < 8; nf++) {
            o[nf][0] *= f0; o[nf][1] *= f0; o[nf][2] *= f1; o[nf][3] *= f1;
        }
        m0 = mn0; m1 = mn1;
        #pragma unroll
        for (int nf = 0; nf < 8; nf++) {
            s[nf][0] = exp2p((s[nf][0] - m0) * CEXP);
            s[nf][1] = exp2p((s[nf][1] - m0) * CEXP);
            s[nf][2] = exp2p((s[nf][2] - m1) * CEXP);
            s[nf][3] = exp2p((s[nf][3] - m1) * CEXP);
            l0 += s[nf][0] + s[nf][1];
            l1 += s[nf][2] + s[nf][3];
        }

        // ---- O += P V ----
        #pragma unroll
        for (int kk = 0; kk < 4; kk++) {
            uint32_t p0 = packh2(s[2*kk][0],   s[2*kk][1]);
            uint32_t p1 = packh2(s[2*kk][2],   s[2*kk][3]);
            uint32_t p2 = packh2(s[2*kk+1][0], s[2*kk+1][1]);
            uint32_t p3 = packh2(s[2*kk+1][2], s[2*kk+1][3]);
            int vrow = kk * 16 + (g >> 1) * 8 + rg;
            #pragma unroll
            for (int ep = 0; ep < 4; ep++) {
                int ecol = ep * 16 + (g & 1) * 8;
                uint32_t off = swz128(vrow * 128 + ecol * 2);
                uint32_t vh[4];
                ldsm_x4t(sV + off, vh);
                mma_f16(o[2*ep],   p0, p1, p2, p3, vh[0], vh[2]);
                mma_f16(o[2*ep+1], p0, p1, p2, p3, vh[1], vh[3]);
            }
        }
    }

    l0 += __shfl_xor_sync(0xffffffffu, l0, 1);
    l0 += __shfl_xor_sync(0xffffffffu, l0, 2);
    l1 += __shfl_xor_sync(0xffffffffu, l1, 1);
    l1 += __shfl_xor_sync(0xffffffffu, l1, 2);
    float rl0 = 1.0f / l0, rl1 = 1.0f / l1;
    int row0 = qstart + w * 16 + (lane >> 2);
    size_t ob0 = ((size_t)(b * SEQ + row0)) * DM + h * 64;
    size_t ob1 = ob0 + (size_t)8 * DM;
    #pragma unroll
    for (int nf = 0; nf < 8; nf++) {
        int e = nf * 8 + (lane & 3) * 2;
        *(uint32_t*)(O + ob0 + e) = packh2(o[nf][0] * rl0, o[nf][1] * rl0);
        *(uint32_t*)(O + ob1 + e) = packh2(o[nf][2] * rl1, o[nf][3] * rl1);
    }
}

// ---------------- launch ----------------
extern "C" void kernel_launch(void* const* d_in, const int* in_sizes, int n_in,
                              void* d_out, int out_size) {
    const float* x      = (const float*)d_in[0];
    const float* gamma1 = (const float*)d_in[1];
    const float* beta1  = (const float*)d_in[2];
    const float* wq     = (const float*)d_in[3];
    const float* wk     = (const float*)d_in[4];
    const float* wv     = (const float*)d_in[5];
    const float* wo     = (const float*)d_in[6];
    const float* gamma2 = (const float*)d_in[7];
    const float* beta2  = (const float*)d_in[8];
    const float* fc1    = (const float*)d_in[9];
    const float* fc2    = (const float*)d_in[10];
    float* out = (float*)d_out;

    float *resid_;
    __half *n_, *qkv_, *a_, *h_, *w_;
    cudaGetSymbolAddress((void**)&resid_, g_resid);
    cudaGetSymbolAddress((void**)&n_,   g_n);
    cudaGetSymbolAddress((void**)&qkv_, g_qkv);
    cudaGetSymbolAddress((void**)&a_,   g_a);
    cudaGetSymbolAddress((void**)&h_,   g_h);
    cudaGetSymbolAddress((void**)&w_,   g_w);

    cudaFuncSetAttribute(gemm_tc<0,2>, cudaFuncAttributeMaxDynamicSharedMemorySize, GSM);
    cudaFuncSetAttribute(gemm_tc<1,0>, cudaFuncAttributeMaxDynamicSharedMemorySize, GSM);
    cudaFuncSetAttribute(gemm_tc<2,2>, cudaFuncAttributeMaxDynamicSharedMemorySize, GSM);
    cudaFuncSetAttribute(flash_attn_tc, cudaFuncAttributeMaxDynamicSharedMemorySize, ASM);

    const int nQ = DM * DM / 4, nF = DFF * DM / 4;
    conv_f16<<<(nQ + 255) / 256, 256>>>(wq,  w_ + WOFF_Q,  nQ);
    conv_f16<<<(nQ + 255) / 256, 256>>>(wk,  w_ + WOFF_K,  nQ);
    conv_f16<<<(nQ + 255) / 256, 256>>>(wv,  w_ + WOFF_V,  nQ);
    conv_f16<<<(nQ + 255) / 256, 256>>>(wo,  w_ + WOFF_O,  nQ);
    conv_f16<<<(nF + 255) / 256, 256>>>(fc1, w_ + WOFF_F1, nF);
    conv_f16<<<(nF + 255) / 256, 256>>>(fc2, w_ + WOFF_F2, nF);

    dim3 gQKV(QKVS / 128, BS / 128);
    dim3 gProj(DM / 128, BS / 128);
    dim3 gFF1(DFF / 128, BS / 128);
    dim3 gFF2(DM / 128, BS / 128);
    dim3 gAttn(SEQ / 64, BATCH * NH);

    layernorm_k<<<BS, 256>>>(x, gamma1, beta1, n_);
    gemm_tc<0,2><<<gQKV, 256, GSM>>>(n_, w_ + WOFF_Q, nullptr, nullptr, qkv_, BS, QKVS, DM);
    flash_attn_tc<<<gAttn, 128, ASM>>>(qkv_, a_);
    gemm_tc<1,0><<<gProj, 256, GSM>>>(a_, w_ + WOFF_O, x, resid_, nullptr, BS, DM, DM);
    layernorm_k<<<BS, 256>>>(resid_, gamma2, beta2, n_);
    gemm_tc<2,2><<<gFF1, 256, GSM>>>(n_, w_ + WOFF_F1, nullptr, nullptr, h_, BS, DFF, DM);
    gemm_tc<1,0><<<gFF2, 256, GSM>>>(h_, w_ + WOFF_F2, resid_, out, nullptr, BS, DM, DFF);
}

// round 10
// speedup vs baseline: 9.8848x; 1.0730x over previous
#include <cuda_runtime.h>
#include <cuda_fp16.h>
#include <math.h>
#include <stdint.h>

#define BATCH 4
#define SEQ   2048
#define DM    1024
#define NH    16
#define DH    64
#define DFF   4096
#define BS    (BATCH*SEQ)
#define QKVS  3072
#define EPSLN 1e-5f
#define CEXP  0.1803368801f   // log2(e)/8

// ---------------- scratch ----------------
__device__ float g_resid[(size_t)BS*DM];
__device__ __half g_n[(size_t)BS*DM];
__device__ __half g_qkv[(size_t)BS*QKVS];
__device__ __half g_a[(size_t)BS*DM];
__device__ __half g_h[(size_t)BS*DFF];
#define WOFF_Q  ((size_t)0)
#define WOFF_K  ((size_t)DM*DM)
#define WOFF_V  ((size_t)2*DM*DM)
#define WOFF_O  ((size_t)3*DM*DM)
#define WOFF_F1 ((size_t)4*DM*DM)
#define WOFF_F2 ((size_t)(4*DM*DM) + (size_t)DFF*DM)
__device__ __half g_w[(size_t)4*DM*DM + 2*(size_t)DFF*DM];

// ---------------- helpers ----------------
__device__ __forceinline__ uint32_t smem_u32(const void* p) {
    uint32_t a;
    asm("{ .reg .u64 t; cvta.to.shared.u64 t, %1; cvt.u32.u64 %0, t; }" : "=r"(a) : "l"(p));
    return a;
}
__device__ __forceinline__ uint32_t swz128(uint32_t off) { return off ^ ((off >> 3) & 0x70); }

__device__ __forceinline__ void ldsm_x4(uint32_t addr, uint32_t& r0, uint32_t& r1,
                                        uint32_t& r2, uint32_t& r3) {
    asm volatile("ldmatrix.sync.aligned.m8n8.x4.shared.b16 {%0,%1,%2,%3}, [%4];"
                 : "=r"(r0), "=r"(r1), "=r"(r2), "=r"(r3) : "r"(addr));
}
__device__ __forceinline__ void ldsm_x4t(uint32_t addr, uint32_t* r) {
    asm volatile("ldmatrix.sync.aligned.m8n8.x4.trans.shared.b16 {%0,%1,%2,%3}, [%4];"
                 : "=r"(r[0]), "=r"(r[1]), "=r"(r[2]), "=r"(r[3]) : "r"(addr));
}
__device__ __forceinline__ void mma_f16(float* d, uint32_t a0, uint32_t a1,
                                        uint32_t a2, uint32_t a3,
                                        uint32_t b0, uint32_t b1) {
    asm volatile("mma.sync.aligned.m16n8k16.row.col.f32.f16.f16.f32 "
                 "{%0,%1,%2,%3}, {%4,%5,%6,%7}, {%8,%9}, {%0,%1,%2,%3};"
                 : "+f"(d[0]), "+f"(d[1]), "+f"(d[2]), "+f"(d[3])
                 : "r"(a0), "r"(a1), "r"(a2), "r"(a3), "r"(b0), "r"(b1));
}
#define CPA(dst, src) asm volatile("cp.async.cg.shared.global [%0], [%1], 16;" :: "r"(dst), "l"(src))

__device__ __forceinline__ float gelu_f(float x) {
    float c = x * x * x;
    float t = tanhf(0.7978845608f * (x + 0.044715f * c));
    return 0.5f * x * (1.0f + t);
}
__device__ __forceinline__ uint32_t packh2(float x, float y) {
    __half2 h = __floats2half2_rn(x, y);
    return *reinterpret_cast<uint32_t*>(&h);
}
__device__ __forceinline__ float exp2p(float x) {
    x = fmaxf(x, -60.0f);
    float y = x + 12582912.0f;
    int   n = __float_as_int(y) - 0x4B400000;
    float f = x - (y - 12582912.0f);
    float p =            1.3333558e-3f;
    p = fmaf(p, f, 9.6181291e-3f);
    p = fmaf(p, f, 5.5504109e-2f);
    p = fmaf(p, f, 2.4022651e-1f);
    p = fmaf(p, f, 6.9314718e-1f);
    p = fmaf(p, f, 1.0f);
    return __uint_as_float(__float_as_uint(p) + ((uint32_t)n << 23));
}

// ---------------- fused weight convert: all 6 matrices in one launch ----------------
// g_w layout is [wq|wk|wv|wo|fc1|fc2] contiguous; pick source by linear float4 slot.
__global__ __launch_bounds__(256)
void conv_all(const float* __restrict__ wq, const float* __restrict__ wk,
              const float* __restrict__ wv, const float* __restrict__ wo,
              const float* __restrict__ f1, const float* __restrict__ f2,
              __half* __restrict__ w) {
    int i = blockIdx.x * 256 + threadIdx.x;   // float4 slot, total 3145728
    const float* src;
    int loc;
    if (i < (1 << 20)) {                       // 4 x 2^18 slots (proj weights)
        int r = i >> 18;
        loc = i & ((1 << 18) - 1);
        src = (r == 0) ? wq : (r == 1) ? wk : (r == 2) ? wv : wo;
    } else {
        int j = i - (1 << 20);
        if (j < (1 << 20)) { src = f1; loc = j; }
        else               { src = f2; loc = j - (1 << 20); }
    }
    float4 v = *(const float4*)(src + (size_t)loc * 4);
    uint2 o;
    o.x = packh2(v.x, v.y);
    o.y = packh2(v.z, v.w);
    *(uint2*)(w + (size_t)i * 4) = o;
}

// ---------------- layernorm -> f16 ----------------
__global__ __launch_bounds__(256)
void layernorm_k(const float* __restrict__ x, const float* __restrict__ gamma,
                 const float* __restrict__ beta, __half* __restrict__ oh) {
    int row = blockIdx.x;
    const float* xr = x + (size_t)row * DM;
    int t = threadIdx.x;
    float4 v = *(const float4*)(xr + t * 4);
    float s  = v.x + v.y + v.z + v.w;
    float ss = v.x*v.x + v.y*v.y + v.z*v.z + v.w*v.w;
    #pragma unroll
    for (int o = 16; o > 0; o >>= 1) {
        s  += __shfl_xor_sync(0xffffffffu, s,  o);
        ss += __shfl_xor_sync(0xffffffffu, ss, o);
    }
    __shared__ float rs[8], rss[8];
    int w = t >> 5, l = t & 31;
    if (l == 0) { rs[w] = s; rss[w] = ss; }
    __syncthreads();
    if (w == 0) {
        float a = (l < 8) ? rs[l]  : 0.f;
        float b = (l < 8) ? rss[l] : 0.f;
        #pragma unroll
        for (int o = 4; o > 0; o >>= 1) {
            a += __shfl_xor_sync(0xffffffffu, a, o);
            b += __shfl_xor_sync(0xffffffffu, b, o);
        }
        if (l == 0) { rs[0] = a; rss[0] = b; }
    }
    __syncthreads();
    float mean = rs[0] * (1.0f / DM);
    float var  = rss[0] * (1.0f / DM) - mean * mean;
    float rstd = rsqrtf(var + EPSLN);
    float4 gv = *(const float4*)(gamma + t * 4);
    float4 bv = *(const float4*)(beta  + t * 4);
    uint2 o2;
    o2.x = packh2(gv.x * ((v.x - mean) * rstd) + bv.x,
                  gv.y * ((v.y - mean) * rstd) + bv.y);
    o2.y = packh2(gv.z * ((v.z - mean) * rstd) + bv.z,
                  gv.w * ((v.w - mean) * rstd) + bv.w);
    *(uint2*)(oh + (size_t)row * DM + t * 4) = o2;
}

// ---------------- fp16 GEMM NT: K-chunk 64, 3-stage cp.async, 2 CTAs/SM ----------------
// C = A @ W^T. 128x128 CTA tile, 8 warps (64x32 each). 128B smem rows, SW128.
// EPI: 0 none, 1 +R, 2 gelu.  OUT: 0 f32, 2 f16.
#define GSM (3*32768 + 1024)

template<int EPI, int OUT>
__global__ __launch_bounds__(256, 2)
void gemm_tc(const __half* __restrict__ A_, const __half* __restrict__ W_,
             const float* __restrict__ R, float* __restrict__ Cf,
             __half* __restrict__ Ch, int M, int N, int K) {
    extern __shared__ char dsm[];
    uint32_t sb = (smem_u32(dsm) + 1023) & ~1023u;

    int tid = threadIdx.x, wid = tid >> 5, lane = tid & 31;
    int wm = wid >> 2, wn = wid & 3;

    const char* Ab = (const char*)(A_ + (size_t)blockIdx.y * 128 * K);
    const char* Wb = (const char*)(W_ + (size_t)blockIdx.x * 128 * K);

    // copy pattern: 4 granules of 16B per matrix per thread per chunk
    int cs = tid & 7;
    int rbase = tid >> 3;                     // rows rbase + 32*i
    uint32_t soA[4];
    size_t gbA[4];
    #pragma unroll
    for (int i = 0; i < 4; i++) {
        int row = rbase + 32 * i;
        soA[i] = swz128(row * 128 + cs * 16);
        gbA[i] = (size_t)row * K * 2 + cs * 16;
    }

    #define G_ISSUE(kb, st) do { \
        uint32_t s_ = sb + (st) * 32768; \
        size_t kbb = (size_t)(kb) * 2; \
        _Pragma("unroll") \
        for (int i_ = 0; i_ < 4; i_++) { \
            CPA(s_ + soA[i_],         Ab + gbA[i_] + kbb); \
            CPA(s_ + 16384 + soA[i_], Wb + gbA[i_] + kbb); \
        } \
    } while (0)

    float acc[4][4][4];
    #pragma unroll
    for (int i = 0; i < 4; i++)
        #pragma unroll
        for (int j = 0; j < 4; j++)
            #pragma unroll
            for (int e = 0; e < 4; e++) acc[i][j][e] = 0.f;

    int g = lane >> 3, rg = lane & 7;
    int nch = K >> 6;

    G_ISSUE(0, 0);
    asm volatile("cp.async.commit_group;");
    G_ISSUE(64, 1);
    asm volatile("cp.async.commit_group;");

    int st_c = 0, st_i = 2;
    for (int ch = 0; ch < nch; ch++) {
        if (ch + 1 < nch) asm volatile("cp.async.wait_group 1;" ::: "memory");
        else              asm volatile("cp.async.wait_group 0;" ::: "memory");
        __syncthreads();
        if (ch + 2 < nch) {
            G_ISSUE((ch + 2) << 6, st_i);
            asm volatile("cp.async.commit_group;");
            st_i = (st_i == 2) ? 0 : st_i + 1;
        }
        uint32_t ah = sb + st_c * 32768;
        st_c = (st_c == 2) ? 0 : st_c + 1;
        uint32_t bh = ah + 16384;

        #pragma unroll
        for (int ks = 0; ks < 4; ks++) {
            int kcol = ks * 32 + (g >> 1) * 16;
            uint32_t bhr[2][4];
            #pragma unroll
            for (int p = 0; p < 2; p++) {
                int nrow = wn * 32 + p * 16 + (g & 1) * 8 + rg;
                uint32_t off = swz128(nrow * 128 + kcol);
                ldsm_x4(bh + off, bhr[p][0], bhr[p][1], bhr[p][2], bhr[p][3]);
            }
            #pragma unroll
            for (int mf = 0; mf < 4; mf++) {
                int arow = wm * 64 + mf * 16 + (g & 1) * 8 + rg;
                uint32_t off = swz128(arow * 128 + kcol);
                uint32_t a0,a1,a2,a3;
                ldsm_x4(ah + off, a0, a1, a2, a3);
                #pragma unroll
                for (int nf = 0; nf < 4; nf++) {
                    int p = nf >> 1, q = nf & 1;
                    mma_f16(acc[mf][nf], a0, a1, a2, a3, bhr[p][q], bhr[p][q + 2]);
                }
            }
        }
    }

    #pragma unroll
    for (int mf = 0; mf < 4; mf++) {
        #pragma unroll
        for (int h = 0; h < 2; h++) {
            size_t row = (size_t)blockIdx.y * 128 + wm * 64 + mf * 16 + (lane >> 2) + h * 8;
            #pragma unroll
            for (int nf = 0; nf < 4; nf++) {
                size_t col = (size_t)blockIdx.x * 128 + wn * 32 + nf * 8 + (lane & 3) * 2;
                float o0 = acc[mf][nf][h * 2 + 0];
                float o1 = acc[mf][nf][h * 2 + 1];
                if (EPI == 1) {
                    float2 r2 = *(const float2*)(R + row * N + col);
                    o0 += r2.x; o1 += r2.y;
                }
                if (EPI == 2) { o0 = gelu_f(o0); o1 = gelu_f(o1); }
                if (OUT == 0) {
                    *(float2*)(Cf + row * N + col) = make_float2(o0, o1);
                } else {
                    *(uint32_t*)(Ch + row * N + col) = packh2(o0, o1);
                }
            }
        }
    }
}

// ---------------- fp16 tensor-core flash attention (3-stage KV, causal) ----------------
#define ASM (8192 + 3*16384 + 1024)

__global__ __launch_bounds__(128)
void flash_attn_tc(const __half* __restrict__ QKV, __half* __restrict__ O) {
    extern __shared__ char dsm[];
    uint32_t sb = (smem_u32(dsm) + 1023) & ~1023u;
    uint32_t sQ = sb;

    int qt = gridDim.x - 1 - blockIdx.x;
    int bh = blockIdx.y;
    int b = bh >> 4, h = bh & 15;
    int tid = threadIdx.x, w = tid >> 5, lane = tid & 31;
    int g = lane >> 3, rg = lane & 7;
    int qstart = qt * 64;

    const char* Qc = (const char*)QKV;

    size_t qg = ((size_t)(b * SEQ + qstart)) * QKVS + h * 64;
    #pragma unroll
    for (int i = 0; i < 4; i++) {
        int seg = tid + i * 128;
        int row = seg >> 3, cs = seg & 7;
        uint32_t so = swz128(row * 128 + cs * 16);
        size_t gb = (qg + (size_t)row * QKVS + cs * 8) * 2;
        CPA(sQ + so, Qc + gb);
    }

    #define AKV_ISSUE(kbase, st) do { \
        uint32_t s_ = sb + 8192 + (st) * 16384; \
        size_t g0 = ((size_t)(b * SEQ + (kbase))) * QKVS + 1024 + h * 64; \
        _Pragma("unroll") \
        for (int i_ = 0; i_ < 4; i_++) { \
            int seg_ = tid + i_ * 128; \
            int row_ = seg_ >> 3, cs_ = seg_ & 7; \
            uint32_t so_ = swz128(row_ * 128 + cs_ * 16); \
            size_t gb_ = (g0 + (size_t)row_ * QKVS + cs_ * 8) * 2; \
            CPA(s_ + so_,        Qc + gb_); \
            CPA(s_ + 8192 + so_, Qc + gb_ + 2048); \
        } \
    } while (0)

    AKV_ISSUE(0, 0);
    asm volatile("cp.async.commit_group;");
    if (qt >= 1) {
        AKV_ISSUE(64, 1);
        asm volatile("cp.async.commit_group;");
    }

    float s[8][4], o[8][4];
    uint32_t qf[4][4];
    #pragma unroll
    for (int nf = 0; nf < 8; nf++)
        #pragma unroll
        for (int e = 0; e < 4; e++) o[nf][e] = 0.f;
    float m0 = -1e30f, m1 = -1e30f, l0 = 0.f, l1 = 0.f;

    int st_c = 0, st_i = 2;
    for (int kb = 0; kb <= qt; kb++) {
        if (kb < qt) asm volatile("cp.async.wait_group 1;" ::: "memory");
        else         asm volatile("cp.async.wait_group 0;" ::: "memory");
        __syncthreads();
        if (kb + 2 <= qt) {
            AKV_ISSUE((kb + 2) * 64, st_i);
            asm volatile("cp.async.commit_group;");
            st_i = (st_i == 2) ? 0 : st_i + 1;
        }

        if (kb == 0) {
            #pragma unroll
            for (int kseg = 0; kseg < 4; kseg++) {
                int arow = w * 16 + (g & 1) * 8 + rg;
                uint32_t off = swz128(arow * 128 + kseg * 32 + (g >> 1) * 16);
                ldsm_x4(sQ + off, qf[kseg][0], qf[kseg][1], qf[kseg][2], qf[kseg][3]);
            }
        }

        uint32_t kB = sb + 8192 + st_c * 16384;
        st_c = (st_c == 2) ? 0 : st_c + 1;
        uint32_t sK = kB, sV = kB + 8192;

        // ---- S = Q K^T ----
        #pragma unroll
        for (int nf = 0; nf < 8; nf++)
            #pragma unroll
            for (int e = 0; e < 4; e++) s[nf][e] = 0.f;
        #pragma unroll
        for (int kseg = 0; kseg < 4; kseg++) {
            uint32_t kh[4][4];
            int kcol = kseg * 32 + (g >> 1) * 16;
            #pragma unroll
            for (int p = 0; p < 4; p++) {
                int nrow = p * 16 + (g & 1) * 8 + rg;
                uint32_t off = swz128(nrow * 128 + kcol);
                ldsm_x4(sK + off, kh[p][0], kh[p][1], kh[p][2], kh[p][3]);
            }
            #pragma unroll
            for (int p = 0; p < 4; p++)
                #pragma unroll
                for (int q = 0; q < 2; q++)
                    mma_f16(s[2*p+q], qf[kseg][0], qf[kseg][1], qf[kseg][2], qf[kseg][3],
                            kh[p][q], kh[p][q + 2]);
        }

        if (kb == qt) {
            int r0 = w * 16 + (lane >> 2);
            int c0 = (lane & 3) * 2;
            #pragma unroll
            for (int nf = 0; nf < 8; nf++) {
                int c = c0 + nf * 8;
                if (c     > r0)     s[nf][0] = -1e30f;
                if (c + 1 > r0)     s[nf][1] = -1e30f;
                if (c     > r0 + 8) s[nf][2] = -1e30f;
                if (c + 1 > r0 + 8) s[nf][3] = -1e30f;
            }
        }

        // ---- online softmax ----
        float mr0 = -1e30f, mr1 = -1e30f;
        #pragma unroll
        for (int nf = 0; nf < 8; nf++) {
            mr0 = fmaxf(mr0, fmaxf(s[nf][0], s[nf][1]));
            mr1 = fmaxf(mr1, fmaxf(s[nf][2], s[nf][3]));
        }
        mr0 = fmaxf(mr0, __shfl_xor_sync(0xffffffffu, mr0, 1));
        mr0 = fmaxf(mr0, __shfl_xor_sync(0xffffffffu, mr0, 2));
        mr1 = fmaxf(mr1, __shfl_xor_sync(0xffffffffu, mr1, 1));
        mr1 = fmaxf(mr1, __shfl_xor_sync(0xffffffffu, mr1, 2));
        float mn0 = fmaxf(m0, mr0), mn1 = fmaxf(m1, mr1);
        float f0 = exp2p((m0 - mn0) * CEXP);
        float f1 = exp2p((m1 - mn1) * CEXP);
        l0 *= f0; l1 *= f1;
        #pragma unroll
        for (int nf = 0; nf < 8; nf++) {
            o[nf][0] *= f0; o[nf][1] *= f0; o[nf][2] *= f1; o[nf][3] *= f1;
        }
        m0 = mn0; m1 = mn1;
        #pragma unroll
        for (int nf = 0; nf < 8; nf++) {
            s[nf][0] = exp2p((s[nf][0] - m0) * CEXP);
            s[nf][1] = exp2p((s[nf][1] - m0) * CEXP);
            s[nf][2] = exp2p((s[nf][2] - m1) * CEXP);
            s[nf][3] = exp2p((s[nf][3] - m1) * CEXP);
            l0 += s[nf][0] + s[nf][1];
            l1 += s[nf][2] + s[nf][3];
        }

        // ---- O += P V ----
        #pragma unroll
        for (int kk = 0; kk < 4; kk++) {
            uint32_t p0 = packh2(s[2*kk][0],   s[2*kk][1]);
            uint32_t p1 = packh2(s[2*kk][2],   s[2*kk][3]);
            uint32_t p2 = packh2(s[2*kk+1][0], s[2*kk+1][1]);
            uint32_t p3 = packh2(s[2*kk+1][2], s[2*kk+1][3]);
            int vrow = kk * 16 + (g >> 1) * 8 + rg;
            #pragma unroll
            for (int ep = 0; ep < 4; ep++) {
                int ecol = ep * 16 + (g & 1) * 8;
                uint32_t off = swz128(vrow * 128 + ecol * 2);
                uint32_t vh[4];
                ldsm_x4t(sV + off, vh);
                mma_f16(o[2*ep],   p0, p1, p2, p3, vh[0], vh[2]);
                mma_f16(o[2*ep+1], p0, p1, p2, p3, vh[1], vh[3]);
            }
        }
    }

    l0 += __shfl_xor_sync(0xffffffffu, l0, 1);
    l0 += __shfl_xor_sync(0xffffffffu, l0, 2);
    l1 += __shfl_xor_sync(0xffffffffu, l1, 1);
    l1 += __shfl_xor_sync(0xffffffffu, l1, 2);
    float rl0 = 1.0f / l0, rl1 = 1.0f / l1;
    int row0 = qstart + w * 16 + (lane >> 2);
    size_t ob0 = ((size_t)(b * SEQ + row0)) * DM + h * 64;
    size_t ob1 = ob0 + (size_t)8 * DM;
    #pragma unroll
    for (int nf = 0; nf < 8; nf++) {
        int e = nf * 8 + (lane & 3) * 2;
        *(uint32_t*)(O + ob0 + e) = packh2(o[nf][0] * rl0, o[nf][1] * rl0);
        *(uint32_t*)(O + ob1 + e) = packh2(o[nf][2] * rl1, o[nf][3] * rl1);
    }
}

// ---------------- launch ----------------
extern "C" void kernel_launch(void* const* d_in, const int* in_sizes, int n_in,
                              void* d_out, int out_size) {
    const float* x      = (const float*)d_in[0];
    const float* gamma1 = (const float*)d_in[1];
    const float* beta1  = (const float*)d_in[2];
    const float* wq     = (const float*)d_in[3];
    const float* wk     = (const float*)d_in[4];
    const float* wv     = (const float*)d_in[5];
    const float* wo     = (const float*)d_in[6];
    const float* gamma2 = (const float*)d_in[7];
    const float* beta2  = (const float*)d_in[8];
    const float* fc1    = (const float*)d_in[9];
    const float* fc2    = (const float*)d_in[10];
    float* out = (float*)d_out;

    float *resid_;
    __half *n_, *qkv_, *a_, *h_, *w_;
    cudaGetSymbolAddress((void**)&resid_, g_resid);
    cudaGetSymbolAddress((void**)&n_,   g_n);
    cudaGetSymbolAddress((void**)&qkv_, g_qkv);
    cudaGetSymbolAddress((void**)&a_,   g_a);
    cudaGetSymbolAddress((void**)&h_,   g_h);
    cudaGetSymbolAddress((void**)&w_,   g_w);

    cudaFuncSetAttribute(gemm_tc<0,2>, cudaFuncAttributeMaxDynamicSharedMemorySize, GSM);
    cudaFuncSetAttribute(gemm_tc<1,0>, cudaFuncAttributeMaxDynamicSharedMemorySize, GSM);
    cudaFuncSetAttribute(gemm_tc<2,2>, cudaFuncAttributeMaxDynamicSharedMemorySize, GSM);
    cudaFuncSetAttribute(flash_attn_tc, cudaFuncAttributeMaxDynamicSharedMemorySize, ASM);

    // one fused weight-convert launch (12582912 halves = 3145728 float4 slots)
    conv_all<<<3145728 / 256, 256>>>(wq, wk, wv, wo, fc1, fc2, w_);

    dim3 gQKV(QKVS / 128, BS / 128);
    dim3 gProj(DM / 128, BS / 128);
    dim3 gFF1(DFF / 128, BS / 128);
    dim3 gFF2(DM / 128, BS / 128);
    dim3 gAttn(SEQ / 64, BATCH * NH);

    layernorm_k<<<BS, 256>>>(x, gamma1, beta1, n_);
    gemm_tc<0,2><<<gQKV, 256, GSM>>>(n_, w_ + WOFF_Q, nullptr, nullptr, qkv_, BS, QKVS, DM);
    flash_attn_tc<<<gAttn, 128, ASM>>>(qkv_, a_);
    gemm_tc<1,0><<<gProj, 256, GSM>>>(a_, w_ + WOFF_O, x, resid_, nullptr, BS, DM, DM);
    layernorm_k<<<BS, 256>>>(resid_, gamma2, beta2, n_);
    gemm_tc<2,2><<<gFF1, 256, GSM>>>(n_, w_ + WOFF_F1, nullptr, nullptr, h_, BS, DFF, DM);
    gemm_tc<1,0><<<gFF2, 256, GSM>>>(h_, w_ + WOFF_F2, resid_, out, nullptr, BS, DM, DFF);
}